// round 7
// baseline (speedup 1.0000x reference)
#include <cuda_runtime.h>
#include <cuda_bf16.h>
#include <cstdint>
#include <math.h>

typedef __nv_bfloat16 bf16;

// ---------------- problem constants ----------------
#define BB   8
#define TT   1024
#define DD   256
#define HH   512
#define NN   16
#define RR   8
#define LL   4
#define BT   (BB*TT)        // 8192
#define BTH  (BB*TT*HH)     // 4194304
#define BTD  (BB*TT*DD)     // 2097152
#define NW   (LL*HH*DD)     // 524288

#define GRID_PERSIST 296    // 148 SMs x 2 blocks, all resident in one wave

// ---------------- scratch (static device globals; no allocation) ----------------
__device__ float g_h  [BTD];
__device__ float g_v  [BTH];        // [bt][h]
__device__ float g_vcT[BTH];        // [h][bt]
__device__ float g_dtT[BTH];        // [h][bt]
__device__ bf16 g_lnh[BTD], g_lnl[BTD];
__device__ bf16 g_yh [BTH], g_yl [BTH];   // [bt][h]
__device__ bf16 g_iwh[NW],  g_iwl[NW];
__device__ bf16 g_owh[NW],  g_owl[NW];

// ---------------- grid-wide spin barrier ----------------
__device__ unsigned int g_bar_cnt;
__device__ unsigned int g_bar_gen;

__device__ __forceinline__ void grid_barrier() {
    __syncthreads();
    if (threadIdx.x == 0) {
        __threadfence();
        unsigned int gen = atomicAdd(&g_bar_gen, 0u);
        unsigned int arrived = atomicAdd(&g_bar_cnt, 1u);
        if (arrived == gridDim.x - 1) {
            g_bar_cnt = 0;
            __threadfence();
            atomicAdd(&g_bar_gen, 1u);
        } else {
            while (atomicAdd(&g_bar_gen, 0u) == gen) __nanosleep(128);
        }
        __threadfence();
    }
    __syncthreads();
}

// ---------------- helpers ----------------
__device__ __forceinline__ float silu_f(float x) {
    return x / (1.f + __expf(-x));
}

__device__ __forceinline__ void split_bf16(float v, bf16& h, bf16& l) {
    h = __float2bfloat16(v);
    l = __float2bfloat16(v - __bfloat162float(h));
}

__device__ __forceinline__ unsigned int pk2(bf16 a, bf16 b) {
    return (unsigned int)__bfloat16_as_ushort(a) |
           ((unsigned int)__bfloat16_as_ushort(b) << 16);
}

__device__ __forceinline__ void ldsm4(unsigned int r[4], const void* p) {
    unsigned int a = (unsigned int)__cvta_generic_to_shared(p);
    asm volatile("ldmatrix.sync.aligned.m8n8.x4.shared.b16 {%0,%1,%2,%3}, [%4];"
                 : "=r"(r[0]), "=r"(r[1]), "=r"(r[2]), "=r"(r[3]) : "r"(a));
}

__device__ __forceinline__ void mma_bf16(float c[4], const unsigned int a[4],
                                         unsigned int b0, unsigned int b1) {
    asm volatile(
        "mma.sync.aligned.m16n8k16.row.col.f32.bf16.bf16.f32 "
        "{%0,%1,%2,%3},{%4,%5,%6,%7},{%8,%9},{%0,%1,%2,%3};"
        : "+f"(c[0]), "+f"(c[1]), "+f"(c[2]), "+f"(c[3])
        : "r"(a[0]), "r"(a[1]), "r"(a[2]), "r"(a[3]), "r"(b0), "r"(b1));
}

// ---------------- smem union layout (31 KB) ----------------
#define PADK 40
#define SMEM_BYTES 30976
// gemm:  sAh @0 (10240), sAl @10240 (10240), sWh @20480 (5120), sWl @25600 (5120)
// conv:  float tile[34][33] @0 (4488)
// dt:    float red[128][9] @0 (4608), float dtr[128][9] @4608 (4608)
// scan:  float sx[2][16][33] @0 (8448), sd[2][16][33] @8448 (8448),
//        bf16 yh[32][16] @16896 (1024), bf16 yl[32][16] @17920 (1024)

// ---------------- gemm tile with register double-buffering ----------------
__device__ void gemm_tile(char* s_raw,
    const bf16* __restrict__ Ah, const bf16* __restrict__ Al,
    const bf16* __restrict__ Wh, const bf16* __restrict__ Wl,
    float* __restrict__ C, int N, int K, int accumulate, int bm, int bn)
{
    bf16 (*sAh)[PADK] = (bf16(*)[PADK])(s_raw);
    bf16 (*sAl)[PADK] = (bf16(*)[PADK])(s_raw + 10240);
    bf16 (*sWh)[PADK] = (bf16(*)[PADK])(s_raw + 20480);
    bf16 (*sWl)[PADK] = (bf16(*)[PADK])(s_raw + 25600);

    const int tid  = threadIdx.x;
    const int lane = tid & 31;
    const int wid  = tid >> 5;
    const int wm   = (wid & 3) * 32;
    const int wn   = (wid >> 2) * 32;

    float acc[2][4][4];
    #pragma unroll
    for (int a = 0; a < 2; a++)
        #pragma unroll
        for (int b = 0; b < 4; b++)
            #pragma unroll
            for (int c = 0; c < 4; c++) acc[a][b][c] = 0.f;

    const int lrow = tid >> 2;
    const int lcol = (tid & 3) * 8;

    const int a_row = lane & 15;
    const int a_col = (lane >> 4) << 3;
    const int bq    = lane >> 3;
    const int b_row = (lane & 7) + ((bq >> 1) << 3);
    const int b_col = (bq & 1) << 3;

    const bf16* pAh0 = Ah + (size_t)(bm + lrow) * K + lcol;
    const bf16* pAh1 = pAh0 + (size_t)64 * K;
    const bf16* pAl0 = Al + (size_t)(bm + lrow) * K + lcol;
    const bf16* pAl1 = pAl0 + (size_t)64 * K;
    const bf16* pWh  = Wh + (size_t)(bn + lrow) * K + lcol;
    const bf16* pWl  = Wl + (size_t)(bn + lrow) * K + lcol;

    // prologue: load first K-tile into registers
    uint4 rAh0 = *(const uint4*)pAh0;
    uint4 rAh1 = *(const uint4*)pAh1;
    uint4 rAl0 = *(const uint4*)pAl0;
    uint4 rAl1 = *(const uint4*)pAl1;
    uint4 rWh  = *(const uint4*)pWh;
    uint4 rWl  = *(const uint4*)pWl;

    for (int kt = 0; kt < K; kt += 32) {
        // commit current registers to smem
        *(uint4*)&sAh[lrow     ][lcol] = rAh0;
        *(uint4*)&sAh[lrow + 64][lcol] = rAh1;
        *(uint4*)&sAl[lrow     ][lcol] = rAl0;
        *(uint4*)&sAl[lrow + 64][lcol] = rAl1;
        *(uint4*)&sWh[lrow][lcol] = rWh;
        *(uint4*)&sWl[lrow][lcol] = rWl;
        __syncthreads();

        // prefetch next K-tile (latency hidden behind MMAs below)
        if (kt + 32 < K) {
            int o = kt + 32;
            rAh0 = *(const uint4*)(pAh0 + o);
            rAh1 = *(const uint4*)(pAh1 + o);
            rAl0 = *(const uint4*)(pAl0 + o);
            rAl1 = *(const uint4*)(pAl1 + o);
            rWh  = *(const uint4*)(pWh + o);
            rWl  = *(const uint4*)(pWl + o);
        }

        #pragma unroll
        for (int ks = 0; ks < 2; ks++) {
            const int k0 = ks * 16;
            unsigned int ah[2][4], al[2][4];
            #pragma unroll
            for (int mt = 0; mt < 2; mt++) {
                ldsm4(ah[mt], &sAh[wm + mt * 16 + a_row][k0 + a_col]);
                ldsm4(al[mt], &sAl[wm + mt * 16 + a_row][k0 + a_col]);
            }
            unsigned int bh[2][4], bl[2][4];
            #pragma unroll
            for (int nb = 0; nb < 2; nb++) {
                ldsm4(bh[nb], &sWh[wn + nb * 16 + b_row][k0 + b_col]);
                ldsm4(bl[nb], &sWl[wn + nb * 16 + b_row][k0 + b_col]);
            }
            #pragma unroll
            for (int mt = 0; mt < 2; mt++) {
                #pragma unroll
                for (int nt = 0; nt < 4; nt++) {
                    const int nb = nt >> 1, hf = (nt & 1) * 2;
                    mma_bf16(acc[mt][nt], ah[mt], bh[nb][hf], bh[nb][hf + 1]);
                    mma_bf16(acc[mt][nt], ah[mt], bl[nb][hf], bl[nb][hf + 1]);
                    mma_bf16(acc[mt][nt], al[mt], bh[nb][hf], bh[nb][hf + 1]);
                }
            }
        }
        __syncthreads();
    }

    const int cg = lane >> 2;
    const int ct = (lane & 3) * 2;
    #pragma unroll
    for (int mt = 0; mt < 2; mt++) {
        #pragma unroll
        for (int nt = 0; nt < 4; nt++) {
            int r0 = bm + wm + mt * 16 + cg;
            int c0 = bn + wn + nt * 8 + ct;
            float2* p0 = (float2*)(C + (size_t)r0 * N + c0);
            float2* p1 = (float2*)(C + (size_t)(r0 + 8) * N + c0);
            float2 v0 = make_float2(acc[mt][nt][0], acc[mt][nt][1]);
            float2 v1 = make_float2(acc[mt][nt][2], acc[mt][nt][3]);
            if (accumulate) {
                float2 o0 = *p0, o1 = *p1;
                v0.x += o0.x; v0.y += o0.y;
                v1.x += o1.x; v1.y += o1.y;
            }
            *p0 = v0; *p1 = v1;
        }
    }
}

// ---------------- merged embed + pos-encoding + weight split (1 node) ----------------
__global__ void emb_split_kernel(const float* __restrict__ x,
                                 const float* __restrict__ emb_w,
                                 const float* __restrict__ emb_b,
                                 const float* __restrict__ in_w,
                                 const float* __restrict__ out_w) {
    if (blockIdx.x < BT) {
        int bt = blockIdx.x;
        int d  = threadIdx.x;
        __shared__ float sx[32];
        if (d < 32) sx[d] = x[bt * 32 + d];
        __syncthreads();
        float acc = emb_b[d];
        const float* w = emb_w + d * 32;
        #pragma unroll
        for (int i = 0; i < 32; i++) acc = fmaf(sx[i], w[i], acc);
        int t = bt & (TT - 1);
        int k2 = d & ~1;
        float div = __expf((float)k2 * (-9.210340371976184f / 256.0f));
        float ang = (float)t * div;
        acc += (d & 1) ? cosf(ang) : sinf(ang);
        g_h[bt * DD + d] = acc;
    } else {
        int i = (blockIdx.x - BT) * 256 + threadIdx.x;
        if (i < NW) {
            split_bf16(in_w[i], g_iwh[i], g_iwl[i]);
        } else {
            int j = i - NW;
            split_bf16(out_w[j], g_owh[j], g_owl[j]);
        }
    }
}

// ---------------- persistent per-layer kernel (6 phases, 5 grid barriers) ----------------
__global__ __launch_bounds__(256, 2) void layer_kernel(
    const float* __restrict__ ng,  const float* __restrict__ nb_,
    const float* __restrict__ cw,
    const float* __restrict__ Apw, const float* __restrict__ Dpw,
    const float* __restrict__ w1,  const float* __restrict__ b1,
    const float* __restrict__ w2,  const float* __restrict__ b2,
    const bf16* __restrict__ iwh,  const bf16* __restrict__ iwl,
    const bf16* __restrict__ owh,  const bf16* __restrict__ owl)
{
    __shared__ __align__(16) char s_raw[SMEM_BYTES];
    const int bid = blockIdx.x;
    const int nbk = gridDim.x;
    const int tid = threadIdx.x;
    const int lane = tid & 31;
    const int warp = tid >> 5;

    // ---- phase 0: layernorm (warp per row) -> g_lnh/g_lnl ----
    for (int row = bid * 8 + warp; row < BT; row += nbk * 8) {
        const float* p = g_h + (size_t)row * DD + lane * 8;
        float4 a = *(const float4*)p;
        float4 c = *(const float4*)(p + 4);
        float v[8] = {a.x, a.y, a.z, a.w, c.x, c.y, c.z, c.w};
        float s = 0.f;
        #pragma unroll
        for (int j = 0; j < 8; j++) s += v[j];
        #pragma unroll
        for (int o = 16; o; o >>= 1) s += __shfl_xor_sync(0xffffffffu, s, o);
        float mean = s * (1.f / 256.f);
        float vv = 0.f;
        #pragma unroll
        for (int j = 0; j < 8; j++) { float d0 = v[j] - mean; vv += d0 * d0; }
        #pragma unroll
        for (int o = 16; o; o >>= 1) vv += __shfl_xor_sync(0xffffffffu, vv, o);
        float rstd = rsqrtf(vv * (1.f / 256.f) + 1e-5f);
        float4 gg0 = *(const float4*)(ng + lane * 8);
        float4 gg1 = *(const float4*)(ng + lane * 8 + 4);
        float4 bb0 = *(const float4*)(nb_ + lane * 8);
        float4 bb1 = *(const float4*)(nb_ + lane * 8 + 4);
        float gv[8] = {gg0.x, gg0.y, gg0.z, gg0.w, gg1.x, gg1.y, gg1.z, gg1.w};
        float bv[8] = {bb0.x, bb0.y, bb0.z, bb0.w, bb1.x, bb1.y, bb1.z, bb1.w};
        bf16 oh[8], ol[8];
        #pragma unroll
        for (int j = 0; j < 8; j++) {
            float o = (v[j] - mean) * rstd * gv[j] + bv[j];
            split_bf16(o, oh[j], ol[j]);
        }
        uint4 uh, ul;
        uh.x = pk2(oh[0], oh[1]); uh.y = pk2(oh[2], oh[3]);
        uh.z = pk2(oh[4], oh[5]); uh.w = pk2(oh[6], oh[7]);
        ul.x = pk2(ol[0], ol[1]); ul.y = pk2(ol[2], ol[3]);
        ul.z = pk2(ol[4], ol[5]); ul.w = pk2(ol[6], ol[7]);
        *(uint4*)(g_lnh + (size_t)row * DD + lane * 8) = uh;
        *(uint4*)(g_lnl + (size_t)row * DD + lane * 8) = ul;
    }
    grid_barrier();

    // ---- phase 1: gemm1  v[bt][h] = ln @ in_w^T  (512 tiles) ----
    for (int t = bid; t < 512; t += nbk)
        gemm_tile(s_raw, g_lnh, g_lnl, iwh, iwl, g_v, HH, DD, 0,
                  (t >> 3) * 128, (t & 7) * 64);
    grid_barrier();

    // ---- phase 2: conv(k=3) + silu + transpose -> g_vcT[h][bt] ----
    {
        float (*tile)[33] = (float(*)[33])(s_raw);
        for (int task = bid; task < BB * 16 * 32; task += nbk) {
            const int b  = task >> 9;
            const int h0 = ((task >> 5) & 15) * 32;
            const int t0 = (task & 31) * 32;
            #pragma unroll
            for (int i = tid; i < 34 * 32; i += 256) {
                int tt = i >> 5;
                int hh = i & 31;
                int t  = t0 + tt - 1;
                float v = 0.f;
                if (t >= 0 && t < TT)
                    v = g_v[((size_t)b * TT + t) * HH + h0 + hh];
                tile[tt][hh] = v;
            }
            __syncthreads();
            const int tl = tid & 31;
            const int hq = tid >> 5;
            #pragma unroll
            for (int j = 0; j < 4; j++) {
                int hh = hq * 4 + j;
                int h  = h0 + hh;
                float w0 = cw[h * 3 + 0], w1v = cw[h * 3 + 1], w2v = cw[h * 3 + 2];
                float acc = tile[tl][hh] * w0;
                acc = fmaf(tile[tl + 1][hh], w1v, acc);
                acc = fmaf(tile[tl + 2][hh], w2v, acc);
                g_vcT[(size_t)h * BT + b * TT + t0 + tl] = silu_f(acc);
            }
            __syncthreads();
        }
    }
    grid_barrier();

    // ---- phase 3: dt1 + dt2 fused -> g_dtT[h][bt] ----
    {
        float (*red)[9]  = (float(*)[9])(s_raw);
        float (*dtrs)[9] = (float(*)[9])(s_raw + 4608);
        const int btl = tid & 127;
        const int q   = tid >> 7;
        for (int task = bid; task < BT / 128; task += nbk) {
            const int bt0 = task * 128;
            float acc[RR];
            #pragma unroll
            for (int r = 0; r < RR; r++) acc[r] = 0.f;
            const int hbase = q * 256;
            #pragma unroll 4
            for (int hh = 0; hh < 256; hh++) {
                int h = hbase + hh;
                float v = g_vcT[(size_t)h * BT + bt0 + btl];
                #pragma unroll
                for (int r = 0; r < RR; r++) acc[r] = fmaf(v, w1[r * HH + h], acc[r]);
            }
            if (q == 1) {
                #pragma unroll
                for (int r = 0; r < RR; r++) red[btl][r] = acc[r];
            }
            __syncthreads();
            if (q == 0) {
                #pragma unroll
                for (int r = 0; r < RR; r++)
                    dtrs[btl][r] = fmaxf(acc[r] + red[btl][r] + b1[r], 0.f);
            }
            __syncthreads();
            for (int hh = q; hh < HH; hh += 2) {
                float wreg[RR];
                #pragma unroll
                for (int r = 0; r < RR; r++) wreg[r] = w2[hh * RR + r];
                float a2 = b2[hh];
                #pragma unroll
                for (int r = 0; r < RR; r++) a2 = fmaf(dtrs[btl][r], wreg[r], a2);
                float sp = (a2 > 15.f) ? a2 : log1pf(__expf(a2));
                g_dtT[(size_t)hh * BT + bt0 + btl] = sp;
            }
            __syncthreads();
        }
    }
    grid_barrier();

    // ---- phase 4: selective scan with double-buffered smem staging ----
    {
        float (*sxb)[16][33] = (float(*)[16][33])(s_raw);            // [2][16][33]
        float (*sdb)[16][33] = (float(*)[16][33])(s_raw + 8448);     // [2][16][33]
        bf16 (*s_yh)[16] = (bf16(*)[16])(s_raw + 16896);
        bf16 (*s_yl)[16] = (bf16(*)[16])(s_raw + 17920);
        const int cid = tid >> 4;       // 0..15
        const int n   = tid & 15;
        const int fl_t = tid >> 3;      // 0..31
        const int fl_h = (tid & 7) * 2; // 0..14
        // loader mapping: tid<128 loads x, tid>=128 loads dt
        const int lc = (tid & 127) >> 3;     // channel 0..15
        const int lsg = (tid & 7) * 4;       // 0,4,..,28

        for (int task = bid; task < (BB * HH) / 16; task += nbk) {
            const int b    = task >> 5;
            const int hblk = (task & 31) * 16;
            const int h    = hblk + cid;
            float Ap = Apw[h * NN + n];
            float A  = -__expf(Ap);
            float invA = (fabsf(A) < 1e-5f) ? 1.f : (1.f / A);
            float Dp = Dpw[h];
            const size_t rowoff = (size_t)(hblk + lc) * BT + b * TT + lsg;

            // preload tile 0
            {
                float4 v = (tid < 128) ? *(const float4*)(g_vcT + rowoff)
                                       : *(const float4*)(g_dtT + rowoff);
                float* dst = (tid < 128) ? &sxb[0][lc][lsg] : &sdb[0][lc][lsg];
                dst[0] = v.x; dst[1] = v.y; dst[2] = v.z; dst[3] = v.w;
            }

            float state = 0.f;
            int buf = 0;
            for (int tb = 0; tb < TT; tb += 32) {
                __syncthreads();   // tile[buf] ready, y staging free
                if (tb + 32 < TT) {
                    float4 v = (tid < 128) ? *(const float4*)(g_vcT + rowoff + tb + 32)
                                           : *(const float4*)(g_dtT + rowoff + tb + 32);
                    float* dst = (tid < 128) ? &sxb[buf ^ 1][lc][lsg] : &sdb[buf ^ 1][lc][lsg];
                    dst[0] = v.x; dst[1] = v.y; dst[2] = v.z; dst[3] = v.w;
                }
                #pragma unroll 8
                for (int tt = 0; tt < 32; tt++) {
                    float dtv = sdb[buf][cid][tt];
                    float x   = sxb[buf][cid][tt];
                    float discA = __expf(A * dtv);
                    float discB = (discA - 1.f) * invA * dtv;
                    state = fmaf(discA, state, discB * x);
                    float part = state * Ap;
                    part += __shfl_xor_sync(0xffffffffu, part, 8);
                    part += __shfl_xor_sync(0xffffffffu, part, 4);
                    part += __shfl_xor_sync(0xffffffffu, part, 2);
                    part += __shfl_xor_sync(0xffffffffu, part, 1);
                    if (n == 0) {
                        float y = fmaf(Dp, x, part);
                        bf16 hh_, ll_;
                        split_bf16(y, hh_, ll_);
                        s_yh[tt][cid] = hh_;
                        s_yl[tt][cid] = ll_;
                    }
                }
                __syncthreads();
                size_t base = (size_t)(b * TT + tb + fl_t) * HH + hblk + fl_h;
                *(unsigned int*)(g_yh + base) = *(unsigned int*)&s_yh[fl_t][fl_h];
                *(unsigned int*)(g_yl + base) = *(unsigned int*)&s_yl[fl_t][fl_h];
                buf ^= 1;
            }
            __syncthreads();
        }
    }
    grid_barrier();

    // ---- phase 5: gemm2  h[bt][d] += y @ out_w^T (256 tiles) ----
    for (int t = bid; t < 256; t += nbk)
        gemm_tile(s_raw, g_yh, g_yl, owh, owl, g_h, DD, HH, 1,
                  (t >> 2) * 128, (t & 3) * 64);
}

// ---------------- final LN (last token) + head1(silu) + head2 ----------------
__global__ void final_kernel(const float* __restrict__ fg,
                             const float* __restrict__ fb,
                             const float* __restrict__ w1,
                             const float* __restrict__ b1,
                             const float* __restrict__ w2,
                             const float* __restrict__ b2,
                             float* __restrict__ out) {
    int b = blockIdx.x;
    int tid = threadIdx.x;
    __shared__ float red1[8], red2[8];
    __shared__ float s_ln[DD];
    __shared__ float s_h1[DD];
    const float* row = g_h + (size_t)(b * TT + (TT - 1)) * DD;
    float v = row[tid];
    float s = v;
    #pragma unroll
    for (int o = 16; o; o >>= 1) s += __shfl_xor_sync(0xffffffffu, s, o);
    if ((tid & 31) == 0) red1[tid >> 5] = s;
    __syncthreads();
    float mean = 0.f;
    #pragma unroll
    for (int i = 0; i < 8; i++) mean += red1[i];
    mean *= (1.f / 256.f);
    float c = v - mean;
    float cc = c * c;
    #pragma unroll
    for (int o = 16; o; o >>= 1) cc += __shfl_xor_sync(0xffffffffu, cc, o);
    if ((tid & 31) == 0) red2[tid >> 5] = cc;
    __syncthreads();
    float var = 0.f;
    #pragma unroll
    for (int i = 0; i < 8; i++) var += red2[i];
    var *= (1.f / 256.f);
    s_ln[tid] = c * rsqrtf(var + 1e-5f) * fg[tid] + fb[tid];
    __syncthreads();
    float acc = b1[tid];
    const float* w1r = w1 + tid * DD;
    #pragma unroll 8
    for (int k = 0; k < DD; k++) acc = fmaf(s_ln[k], w1r[k], acc);
    s_h1[tid] = silu_f(acc);
    __syncthreads();
    if (tid < 96) {
        float a2 = b2[tid];
        const float* w2r = w2 + tid * DD;
        #pragma unroll 8
        for (int k = 0; k < DD; k++) a2 = fmaf(s_h1[k], w2r[k], a2);
        out[b * 96 + tid] = a2;
    }
}

// ---------------- launcher: 6 graph nodes total ----------------
extern "C" void kernel_launch(void* const* d_in, const int* in_sizes, int n_in,
                              void* d_out, int out_size) {
    const float* x      = (const float*)d_in[0];
    const float* emb_w  = (const float*)d_in[1];
    const float* emb_b  = (const float*)d_in[2];
    const float* norm_g = (const float*)d_in[3];
    const float* norm_b = (const float*)d_in[4];
    const float* in_w   = (const float*)d_in[5];
    const float* conv_w = (const float*)d_in[6];
    const float* A_p    = (const float*)d_in[7];
    const float* D_p    = (const float*)d_in[8];
    const float* dt1_w  = (const float*)d_in[9];
    const float* dt1_b  = (const float*)d_in[10];
    const float* dt2_w  = (const float*)d_in[11];
    const float* dt2_b  = (const float*)d_in[12];
    const float* out_w  = (const float*)d_in[13];
    const float* fin_g  = (const float*)d_in[14];
    const float* fin_b  = (const float*)d_in[15];
    const float* h1_w   = (const float*)d_in[16];
    const float* h1_b   = (const float*)d_in[17];
    const float* h2_w   = (const float*)d_in[18];
    const float* h2_b   = (const float*)d_in[19];
    float* out = (float*)d_out;

    bf16 *piwh, *piwl, *powh, *powl;
    cudaGetSymbolAddress((void**)&piwh, g_iwh);
    cudaGetSymbolAddress((void**)&piwl, g_iwl);
    cudaGetSymbolAddress((void**)&powh, g_owh);
    cudaGetSymbolAddress((void**)&powl, g_owl);

    emb_split_kernel<<<BT + (2 * NW) / 256, 256>>>(x, emb_w, emb_b, in_w, out_w);

    for (int l = 0; l < LL; l++) {
        layer_kernel<<<GRID_PERSIST, 256>>>(
            norm_g + l * DD, norm_b + l * DD,
            conv_w + (size_t)l * HH * 3,
            A_p + (size_t)l * HH * NN, D_p + l * HH,
            dt1_w + (size_t)l * RR * HH, dt1_b + l * RR,
            dt2_w + (size_t)l * HH * RR, dt2_b + l * HH,
            piwh + (size_t)l * HH * DD, piwl + (size_t)l * HH * DD,
            powh + (size_t)l * DD * HH, powl + (size_t)l * DD * HH);
    }

    final_kernel<<<BB, 256>>>(fin_g, fin_b, h1_w, h1_b, h2_w, h2_b, out);
}

// round 8
// speedup vs baseline: 1.0702x; 1.0702x over previous
#include <cuda_runtime.h>
#include <cuda_bf16.h>
#include <cstdint>
#include <math.h>

typedef __nv_bfloat16 bf16;

// ---------------- problem constants ----------------
#define BB   8
#define TT   1024
#define DD   256
#define HH   512
#define NN   16
#define RR   8
#define LL   4
#define BT   (BB*TT)        // 8192
#define BTH  (BB*TT*HH)     // 4194304
#define BTD  (BB*TT*DD)     // 2097152
#define NW   (LL*HH*DD)     // 524288
#define CH   (BB*HH)        // 4096 channels

#define GRID_PERSIST 296    // 148 SMs x 2 blocks, all resident in one wave

// ---------------- scratch (static device globals; no allocation) ----------------
__device__ float g_h  [BTD];
__device__ float g_v  [BTH];        // [bt][h] gemm1 out; reused as scan scratch (float2 summaries)
__device__ float g_vcT[BTH];        // [h][bt]
__device__ float g_dtT[BTH];        // [h][bt]
__device__ bf16 g_lnh[BTD], g_lnl[BTD];
__device__ bf16 g_yh [BTH], g_yl [BTH];   // [bt][h]
__device__ bf16 g_iwh[NW],  g_iwl[NW];
__device__ bf16 g_owh[NW],  g_owl[NW];

// ---------------- grid-wide spin barrier ----------------
__device__ unsigned int g_bar_cnt;
__device__ unsigned int g_bar_gen;

__device__ __forceinline__ void grid_barrier() {
    __syncthreads();
    if (threadIdx.x == 0) {
        __threadfence();
        unsigned int gen = atomicAdd(&g_bar_gen, 0u);
        unsigned int arrived = atomicAdd(&g_bar_cnt, 1u);
        if (arrived == gridDim.x - 1) {
            g_bar_cnt = 0;
            __threadfence();
            atomicAdd(&g_bar_gen, 1u);
        } else {
            while (atomicAdd(&g_bar_gen, 0u) == gen) __nanosleep(128);
        }
        __threadfence();
    }
    __syncthreads();
}

// ---------------- helpers ----------------
__device__ __forceinline__ float silu_f(float x) {
    return x / (1.f + __expf(-x));
}

__device__ __forceinline__ void split_bf16(float v, bf16& h, bf16& l) {
    h = __float2bfloat16(v);
    l = __float2bfloat16(v - __bfloat162float(h));
}

__device__ __forceinline__ unsigned int pk2(bf16 a, bf16 b) {
    return (unsigned int)__bfloat16_as_ushort(a) |
           ((unsigned int)__bfloat16_as_ushort(b) << 16);
}

__device__ __forceinline__ void ldsm4(unsigned int r[4], const void* p) {
    unsigned int a = (unsigned int)__cvta_generic_to_shared(p);
    asm volatile("ldmatrix.sync.aligned.m8n8.x4.shared.b16 {%0,%1,%2,%3}, [%4];"
                 : "=r"(r[0]), "=r"(r[1]), "=r"(r[2]), "=r"(r[3]) : "r"(a));
}

__device__ __forceinline__ void mma_bf16(float c[4], const unsigned int a[4],
                                         unsigned int b0, unsigned int b1) {
    asm volatile(
        "mma.sync.aligned.m16n8k16.row.col.f32.bf16.bf16.f32 "
        "{%0,%1,%2,%3},{%4,%5,%6,%7},{%8,%9},{%0,%1,%2,%3};"
        : "+f"(c[0]), "+f"(c[1]), "+f"(c[2]), "+f"(c[3])
        : "r"(a[0]), "r"(a[1]), "r"(a[2]), "r"(a[3]), "r"(b0), "r"(b1));
}

// ---------------- smem union layout (31 KB) ----------------
#define PADK 40
#define SMEM_BYTES 30976

// ---------------- gemm tile (R6 version — no reg prefetch) ----------------
__device__ void gemm_tile(char* s_raw,
    const bf16* __restrict__ Ah, const bf16* __restrict__ Al,
    const bf16* __restrict__ Wh, const bf16* __restrict__ Wl,
    float* __restrict__ C, int N, int K, int accumulate, int bm, int bn)
{
    bf16 (*sAh)[PADK] = (bf16(*)[PADK])(s_raw);
    bf16 (*sAl)[PADK] = (bf16(*)[PADK])(s_raw + 10240);
    bf16 (*sWh)[PADK] = (bf16(*)[PADK])(s_raw + 20480);
    bf16 (*sWl)[PADK] = (bf16(*)[PADK])(s_raw + 25600);

    const int tid  = threadIdx.x;
    const int lane = tid & 31;
    const int wid  = tid >> 5;
    const int wm   = (wid & 3) * 32;
    const int wn   = (wid >> 2) * 32;

    float acc[2][4][4];
    #pragma unroll
    for (int a = 0; a < 2; a++)
        #pragma unroll
        for (int b = 0; b < 4; b++)
            #pragma unroll
            for (int c = 0; c < 4; c++) acc[a][b][c] = 0.f;

    const int lrow = tid >> 2;
    const int lcol = (tid & 3) * 8;

    const int a_row = lane & 15;
    const int a_col = (lane >> 4) << 3;
    const int bq    = lane >> 3;
    const int b_row = (lane & 7) + ((bq >> 1) << 3);
    const int b_col = (bq & 1) << 3;

    for (int kt = 0; kt < K; kt += 32) {
        const bf16* pA = Ah + (size_t)(bm + lrow) * K + kt + lcol;
        const bf16* pa = Al + (size_t)(bm + lrow) * K + kt + lcol;
        *(uint4*)&sAh[lrow     ][lcol] = *(const uint4*)pA;
        *(uint4*)&sAh[lrow + 64][lcol] = *(const uint4*)(pA + (size_t)64 * K);
        *(uint4*)&sAl[lrow     ][lcol] = *(const uint4*)pa;
        *(uint4*)&sAl[lrow + 64][lcol] = *(const uint4*)(pa + (size_t)64 * K);
        const bf16* pW = Wh + (size_t)(bn + lrow) * K + kt + lcol;
        const bf16* pw = Wl + (size_t)(bn + lrow) * K + kt + lcol;
        *(uint4*)&sWh[lrow][lcol] = *(const uint4*)pW;
        *(uint4*)&sWl[lrow][lcol] = *(const uint4*)pw;
        __syncthreads();

        #pragma unroll
        for (int ks = 0; ks < 2; ks++) {
            const int k0 = ks * 16;
            unsigned int ah[2][4], al[2][4];
            #pragma unroll
            for (int mt = 0; mt < 2; mt++) {
                ldsm4(ah[mt], &sAh[wm + mt * 16 + a_row][k0 + a_col]);
                ldsm4(al[mt], &sAl[wm + mt * 16 + a_row][k0 + a_col]);
            }
            unsigned int bh[2][4], bl[2][4];
            #pragma unroll
            for (int nb = 0; nb < 2; nb++) {
                ldsm4(bh[nb], &sWh[wn + nb * 16 + b_row][k0 + b_col]);
                ldsm4(bl[nb], &sWl[wn + nb * 16 + b_row][k0 + b_col]);
            }
            #pragma unroll
            for (int mt = 0; mt < 2; mt++) {
                #pragma unroll
                for (int nt = 0; nt < 4; nt++) {
                    const int nb = nt >> 1, hf = (nt & 1) * 2;
                    mma_bf16(acc[mt][nt], ah[mt], bh[nb][hf], bh[nb][hf + 1]);
                    mma_bf16(acc[mt][nt], ah[mt], bl[nb][hf], bl[nb][hf + 1]);
                    mma_bf16(acc[mt][nt], al[mt], bh[nb][hf], bh[nb][hf + 1]);
                }
            }
        }
        __syncthreads();
    }

    const int cg = lane >> 2;
    const int ct = (lane & 3) * 2;
    #pragma unroll
    for (int mt = 0; mt < 2; mt++) {
        #pragma unroll
        for (int nt = 0; nt < 4; nt++) {
            int r0 = bm + wm + mt * 16 + cg;
            int c0 = bn + wn + nt * 8 + ct;
            float2* p0 = (float2*)(C + (size_t)r0 * N + c0);
            float2* p1 = (float2*)(C + (size_t)(r0 + 8) * N + c0);
            float2 v0 = make_float2(acc[mt][nt][0], acc[mt][nt][1]);
            float2 v1 = make_float2(acc[mt][nt][2], acc[mt][nt][3]);
            if (accumulate) {
                float2 o0 = *p0, o1 = *p1;
                v0.x += o0.x; v0.y += o0.y;
                v1.x += o1.x; v1.y += o1.y;
            }
            *p0 = v0; *p1 = v1;
        }
    }
}

// ---------------- merged embed + pos-encoding + weight split ----------------
__global__ void emb_split_kernel(const float* __restrict__ x,
                                 const float* __restrict__ emb_w,
                                 const float* __restrict__ emb_b,
                                 const float* __restrict__ in_w,
                                 const float* __restrict__ out_w) {
    if (blockIdx.x < BT) {
        int bt = blockIdx.x;
        int d  = threadIdx.x;
        __shared__ float sx[32];
        if (d < 32) sx[d] = x[bt * 32 + d];
        __syncthreads();
        float acc = emb_b[d];
        const float* w = emb_w + d * 32;
        #pragma unroll
        for (int i = 0; i < 32; i++) acc = fmaf(sx[i], w[i], acc);
        int t = bt & (TT - 1);
        int k2 = d & ~1;
        float div = __expf((float)k2 * (-9.210340371976184f / 256.0f));
        float ang = (float)t * div;
        acc += (d & 1) ? cosf(ang) : sinf(ang);
        g_h[bt * DD + d] = acc;
    } else {
        int i = (blockIdx.x - BT) * 256 + threadIdx.x;
        if (i < NW) {
            split_bf16(in_w[i], g_iwh[i], g_iwl[i]);
        } else {
            int j = i - NW;
            split_bf16(out_w[j], g_owh[j], g_owl[j]);
        }
    }
}

// ---------------- persistent per-layer kernel ----------------
__global__ __launch_bounds__(256, 2) void layer_kernel(
    const float* __restrict__ ng,  const float* __restrict__ nb_,
    const float* __restrict__ cw,
    const float* __restrict__ Apw, const float* __restrict__ Dpw,
    const float* __restrict__ w1,  const float* __restrict__ b1,
    const float* __restrict__ w2,  const float* __restrict__ b2,
    const bf16* __restrict__ iwh,  const bf16* __restrict__ iwl,
    const bf16* __restrict__ owh,  const bf16* __restrict__ owl)
{
    __shared__ __align__(16) char s_raw[SMEM_BYTES];
    const int bid = blockIdx.x;
    const int nbk = gridDim.x;
    const int tid = threadIdx.x;
    const int lane = tid & 31;
    const int warp = tid >> 5;

    // ---- phase 0: layernorm (warp per row) -> g_lnh/g_lnl ----
    for (int row = bid * 8 + warp; row < BT; row += nbk * 8) {
        const float* p = g_h + (size_t)row * DD + lane * 8;
        float4 a = *(const float4*)p;
        float4 c = *(const float4*)(p + 4);
        float v[8] = {a.x, a.y, a.z, a.w, c.x, c.y, c.z, c.w};
        float s = 0.f;
        #pragma unroll
        for (int j = 0; j < 8; j++) s += v[j];
        #pragma unroll
        for (int o = 16; o; o >>= 1) s += __shfl_xor_sync(0xffffffffu, s, o);
        float mean = s * (1.f / 256.f);
        float vv = 0.f;
        #pragma unroll
        for (int j = 0; j < 8; j++) { float d0 = v[j] - mean; vv += d0 * d0; }
        #pragma unroll
        for (int o = 16; o; o >>= 1) vv += __shfl_xor_sync(0xffffffffu, vv, o);
        float rstd = rsqrtf(vv * (1.f / 256.f) + 1e-5f);
        float4 gg0 = *(const float4*)(ng + lane * 8);
        float4 gg1 = *(const float4*)(ng + lane * 8 + 4);
        float4 bb0 = *(const float4*)(nb_ + lane * 8);
        float4 bb1 = *(const float4*)(nb_ + lane * 8 + 4);
        float gv[8] = {gg0.x, gg0.y, gg0.z, gg0.w, gg1.x, gg1.y, gg1.z, gg1.w};
        float bv[8] = {bb0.x, bb0.y, bb0.z, bb0.w, bb1.x, bb1.y, bb1.z, bb1.w};
        bf16 oh[8], ol[8];
        #pragma unroll
        for (int j = 0; j < 8; j++) {
            float o = (v[j] - mean) * rstd * gv[j] + bv[j];
            split_bf16(o, oh[j], ol[j]);
        }
        uint4 uh, ul;
        uh.x = pk2(oh[0], oh[1]); uh.y = pk2(oh[2], oh[3]);
        uh.z = pk2(oh[4], oh[5]); uh.w = pk2(oh[6], oh[7]);
        ul.x = pk2(ol[0], ol[1]); ul.y = pk2(ol[2], ol[3]);
        ul.z = pk2(ol[4], ol[5]); ul.w = pk2(ol[6], ol[7]);
        *(uint4*)(g_lnh + (size_t)row * DD + lane * 8) = uh;
        *(uint4*)(g_lnl + (size_t)row * DD + lane * 8) = ul;
    }
    grid_barrier();

    // ---- phase 1: gemm1  v[bt][h] = ln @ in_w^T  (512 tiles) ----
    for (int t = bid; t < 512; t += nbk)
        gemm_tile(s_raw, g_lnh, g_lnl, iwh, iwl, g_v, HH, DD, 0,
                  (t >> 3) * 128, (t & 7) * 64);
    grid_barrier();

    // ---- phase 2: conv(k=3) + silu + transpose -> g_vcT[h][bt] ----
    {
        float (*tile)[33] = (float(*)[33])(s_raw);
        for (int task = bid; task < BB * 16 * 32; task += nbk) {
            const int b  = task >> 9;
            const int h0 = ((task >> 5) & 15) * 32;
            const int t0 = (task & 31) * 32;
            #pragma unroll
            for (int i = tid; i < 34 * 32; i += 256) {
                int tt = i >> 5;
                int hh = i & 31;
                int t  = t0 + tt - 1;
                float v = 0.f;
                if (t >= 0 && t < TT)
                    v = g_v[((size_t)b * TT + t) * HH + h0 + hh];
                tile[tt][hh] = v;
            }
            __syncthreads();
            const int tl = tid & 31;
            const int hq = tid >> 5;
            #pragma unroll
            for (int j = 0; j < 4; j++) {
                int hh = hq * 4 + j;
                int h  = h0 + hh;
                float w0 = cw[h * 3 + 0], w1v = cw[h * 3 + 1], w2v = cw[h * 3 + 2];
                float acc = tile[tl][hh] * w0;
                acc = fmaf(tile[tl + 1][hh], w1v, acc);
                acc = fmaf(tile[tl + 2][hh], w2v, acc);
                g_vcT[(size_t)h * BT + b * TT + t0 + tl] = silu_f(acc);
            }
            __syncthreads();
        }
    }
    grid_barrier();

    // ---- phase 3: dt1 + dt2 fused -> g_dtT[h][bt] (128 tasks of 64 bt) ----
    {
        float (*red)[64][9] = (float(*)[64][9])(s_raw);           // [3][64][9]
        float (*dtrs)[9]    = (float(*)[9])(s_raw + 6912);
        const int btl = tid & 63;
        const int q   = tid >> 6;       // 0..3
        for (int task = bid; task < BT / 64; task += nbk) {
            const int bt0 = task * 64;
            float acc[RR];
            #pragma unroll
            for (int r = 0; r < RR; r++) acc[r] = 0.f;
            const int hbase = q * 128;
            #pragma unroll 4
            for (int hh = 0; hh < 128; hh++) {
                int h = hbase + hh;
                float v = g_vcT[(size_t)h * BT + bt0 + btl];
                #pragma unroll
                for (int r = 0; r < RR; r++) acc[r] = fmaf(v, w1[r * HH + h], acc[r]);
            }
            if (q > 0) {
                #pragma unroll
                for (int r = 0; r < RR; r++) red[q - 1][btl][r] = acc[r];
            }
            __syncthreads();
            if (q == 0) {
                #pragma unroll
                for (int r = 0; r < RR; r++)
                    dtrs[btl][r] = fmaxf(acc[r] + red[0][btl][r] + red[1][btl][r]
                                         + red[2][btl][r] + b1[r], 0.f);
            }
            __syncthreads();
            for (int hh = q; hh < HH; hh += 4) {
                float wreg[RR];
                #pragma unroll
                for (int r = 0; r < RR; r++) wreg[r] = w2[hh * RR + r];
                float a2 = b2[hh];
                #pragma unroll
                for (int r = 0; r < RR; r++) a2 = fmaf(dtrs[btl][r], wreg[r], a2);
                float sp = (a2 > 15.f) ? a2 : log1pf(__expf(a2));
                g_dtT[(size_t)hh * BT + bt0 + btl] = sp;
            }
            __syncthreads();
        }
    }
    grid_barrier();

    // ---- phase 4a: scan pass 1 — chunk summaries (P, e) into g_v scratch ----
    // task = (b, hblk, chunk); block = 16 channels x 16 n-lanes
    {
        float2* scr = (float2*)g_v;
        const int u = tid >> 4;
        const int n = tid & 15;
        for (int task = bid; task < BB * 32 * 32; task += nbk) {
            const int b  = task >> 10;
            const int hb = (task >> 5) & 31;
            const int ck = task & 31;
            const int h  = hb * 16 + u;
            const int ch = b * HH + h;
            float Ap = Apw[h * NN + n];
            float A  = -__expf(Ap);
            float invA = (fabsf(A) < 1e-5f) ? 1.f : (1.f / A);
            const float* xr = g_vcT + (size_t)h * BT + b * TT + ck * 32;
            const float* dr = g_dtT + (size_t)h * BT + b * TT + ck * 32;
            float state = 0.f, P = 1.f;
            #pragma unroll 8
            for (int t = 0; t < 32; t++) {
                float dtv = dr[t];
                float x   = xr[t];
                float dA = __expf(A * dtv);
                float dB = (dA - 1.f) * invA * dtv;
                state = fmaf(dA, state, dB * x);
                P *= dA;
            }
            scr[((size_t)ch * 32 + ck) * 16 + n] = make_float2(P, state);
        }
    }
    grid_barrier();

    // ---- phase 4b: serial carry per (ch, n); carry_j stored in-place (.x) ----
    {
        float2* scr = (float2*)g_v;
        for (int i = bid * 256 + tid; i < CH * NN; i += nbk * 256) {
            float2* base = scr + ((size_t)(i >> 4) * 32) * 16 + (i & 15);
            float c = 0.f;
            #pragma unroll 8
            for (int j = 0; j < 32; j++) {
                float2 s = base[(size_t)j * 16];
                base[(size_t)j * 16].x = c;        // carry = state at chunk start
                c = fmaf(s.x, c, s.y);
            }
        }
    }
    grid_barrier();

    // ---- phase 4c: scan pass 2 — re-scan with carry init, emit y ----
    {
        float2* scr = (float2*)g_v;
        bf16 (*s_yh)[16] = (bf16(*)[16])(s_raw);
        bf16 (*s_yl)[16] = (bf16(*)[16])(s_raw + 1024);
        const int u = tid >> 4;
        const int n = tid & 15;
        const int fl_t = tid >> 3;      // 0..31
        const int fl_h = (tid & 7) * 2; // 0..14
        for (int task = bid; task < BB * 32 * 32; task += nbk) {
            const int b  = task >> 10;
            const int hb = (task >> 5) & 31;
            const int ck = task & 31;
            const int h  = hb * 16 + u;
            const int ch = b * HH + h;
            float Ap = Apw[h * NN + n];
            float A  = -__expf(Ap);
            float invA = (fabsf(A) < 1e-5f) ? 1.f : (1.f / A);
            float Dp = Dpw[h];
            const float* xr = g_vcT + (size_t)h * BT + b * TT + ck * 32;
            const float* dr = g_dtT + (size_t)h * BT + b * TT + ck * 32;
            float state = scr[((size_t)ch * 32 + ck) * 16 + n].x;
            #pragma unroll 8
            for (int t = 0; t < 32; t++) {
                float dtv = dr[t];
                float x   = xr[t];
                float dA = __expf(A * dtv);
                float dB = (dA - 1.f) * invA * dtv;
                state = fmaf(dA, state, dB * x);
                float part = state * Ap;
                part += __shfl_xor_sync(0xffffffffu, part, 8);
                part += __shfl_xor_sync(0xffffffffu, part, 4);
                part += __shfl_xor_sync(0xffffffffu, part, 2);
                part += __shfl_xor_sync(0xffffffffu, part, 1);
                if (n == 0) {
                    float y = fmaf(Dp, x, part);
                    bf16 hh_, ll_;
                    split_bf16(y, hh_, ll_);
                    s_yh[t][u] = hh_;
                    s_yl[t][u] = ll_;
                }
            }
            __syncthreads();
            size_t base = (size_t)(b * TT + ck * 32 + fl_t) * HH + hb * 16 + fl_h;
            *(unsigned int*)(g_yh + base) = *(unsigned int*)&s_yh[fl_t][fl_h];
            *(unsigned int*)(g_yl + base) = *(unsigned int*)&s_yl[fl_t][fl_h];
            __syncthreads();
        }
    }
    grid_barrier();

    // ---- phase 5: gemm2  h[bt][d] += y @ out_w^T (256 tiles) ----
    for (int t = bid; t < 256; t += nbk)
        gemm_tile(s_raw, g_yh, g_yl, owh, owl, g_h, DD, HH, 1,
                  (t >> 2) * 128, (t & 3) * 64);
}

// ---------------- final LN (last token) + head1(silu) + head2 ----------------
__global__ void final_kernel(const float* __restrict__ fg,
                             const float* __restrict__ fb,
                             const float* __restrict__ w1,
                             const float* __restrict__ b1,
                             const float* __restrict__ w2,
                             const float* __restrict__ b2,
                             float* __restrict__ out) {
    int b = blockIdx.x;
    int tid = threadIdx.x;
    __shared__ float red1[8], red2[8];
    __shared__ float s_ln[DD];
    __shared__ float s_h1[DD];
    const float* row = g_h + (size_t)(b * TT + (TT - 1)) * DD;
    float v = row[tid];
    float s = v;
    #pragma unroll
    for (int o = 16; o; o >>= 1) s += __shfl_xor_sync(0xffffffffu, s, o);
    if ((tid & 31) == 0) red1[tid >> 5] = s;
    __syncthreads();
    float mean = 0.f;
    #pragma unroll
    for (int i = 0; i < 8; i++) mean += red1[i];
    mean *= (1.f / 256.f);
    float c = v - mean;
    float cc = c * c;
    #pragma unroll
    for (int o = 16; o; o >>= 1) cc += __shfl_xor_sync(0xffffffffu, cc, o);
    if ((tid & 31) == 0) red2[tid >> 5] = cc;
    __syncthreads();
    float var = 0.f;
    #pragma unroll
    for (int i = 0; i < 8; i++) var += red2[i];
    var *= (1.f / 256.f);
    s_ln[tid] = c * rsqrtf(var + 1e-5f) * fg[tid] + fb[tid];
    __syncthreads();
    float acc = b1[tid];
    const float* w1r = w1 + tid * DD;
    #pragma unroll 8
    for (int k = 0; k < DD; k++) acc = fmaf(s_ln[k], w1r[k], acc);
    s_h1[tid] = silu_f(acc);
    __syncthreads();
    if (tid < 96) {
        float a2 = b2[tid];
        const float* w2r = w2 + tid * DD;
        #pragma unroll 8
        for (int k = 0; k < DD; k++) a2 = fmaf(s_h1[k], w2r[k], a2);
        out[b * 96 + tid] = a2;
    }
}

// ---------------- launcher: 6 graph nodes total ----------------
extern "C" void kernel_launch(void* const* d_in, const int* in_sizes, int n_in,
                              void* d_out, int out_size) {
    const float* x      = (const float*)d_in[0];
    const float* emb_w  = (const float*)d_in[1];
    const float* emb_b  = (const float*)d_in[2];
    const float* norm_g = (const float*)d_in[3];
    const float* norm_b = (const float*)d_in[4];
    const float* in_w   = (const float*)d_in[5];
    const float* conv_w = (const float*)d_in[6];
    const float* A_p    = (const float*)d_in[7];
    const float* D_p    = (const float*)d_in[8];
    const float* dt1_w  = (const float*)d_in[9];
    const float* dt1_b  = (const float*)d_in[10];
    const float* dt2_w  = (const float*)d_in[11];
    const float* dt2_b  = (const float*)d_in[12];
    const float* out_w  = (const float*)d_in[13];
    const float* fin_g  = (const float*)d_in[14];
    const float* fin_b  = (const float*)d_in[15];
    const float* h1_w   = (const float*)d_in[16];
    const float* h1_b   = (const float*)d_in[17];
    const float* h2_w   = (const float*)d_in[18];
    const float* h2_b   = (const float*)d_in[19];
    float* out = (float*)d_out;

    bf16 *piwh, *piwl, *powh, *powl;
    cudaGetSymbolAddress((void**)&piwh, g_iwh);
    cudaGetSymbolAddress((void**)&piwl, g_iwl);
    cudaGetSymbolAddress((void**)&powh, g_owh);
    cudaGetSymbolAddress((void**)&powl, g_owl);

    emb_split_kernel<<<BT + (2 * NW) / 256, 256>>>(x, emb_w, emb_b, in_w, out_w);

    for (int l = 0; l < LL; l++) {
        layer_kernel<<<GRID_PERSIST, 256>>>(
            norm_g + l * DD, norm_b + l * DD,
            conv_w + (size_t)l * HH * 3,
            A_p + (size_t)l * HH * NN, D_p + l * HH,
            dt1_w + (size_t)l * RR * HH, dt1_b + l * RR,
            dt2_w + (size_t)l * HH * RR, dt2_b + l * HH,
            piwh + (size_t)l * HH * DD, piwl + (size_t)l * HH * DD,
            powh + (size_t)l * DD * HH, powl + (size_t)l * DD * HH);
    }

    final_kernel<<<BB, 256>>>(fin_g, fin_b, h1_w, h1_b, h2_w, h2_b, out);
}

// round 9
// speedup vs baseline: 1.1593x; 1.0833x over previous
#include <cuda_runtime.h>
#include <cuda_bf16.h>
#include <cstdint>
#include <math.h>

typedef __nv_bfloat16 bf16;

// ---------------- problem constants ----------------
#define BB   8
#define TT   1024
#define DD   256
#define HH   512
#define NN   16
#define RR   8
#define LL   4
#define BT   (BB*TT)        // 8192
#define BTH  (BB*TT*HH)     // 4194304
#define BTD  (BB*TT*DD)     // 2097152
#define NW   (LL*HH*DD)     // 524288
#define CH   (BB*HH)        // 4096 channels

#define GRID_A   296        // 148 SMs x 2 blocks (128-reg class)
#define GRID_MID 592        // 148 SMs x 4 blocks (64-reg class)

// ---------------- scratch (static device globals; no allocation) ----------------
__device__ float g_h  [BTD];
__device__ float g_v  [BTH];        // gemm1 out; reused as scan scratch (float2 summaries)
__device__ float g_vcT[BTH];        // [h][bt]
__device__ float g_dtT[BTH];        // [h][bt]
__device__ bf16 g_lnh[BTD], g_lnl[BTD];
__device__ bf16 g_yh [BTH], g_yl [BTH];   // [bt][h]
__device__ bf16 g_iwh[NW],  g_iwl[NW];
__device__ bf16 g_owh[NW],  g_owl[NW];

// ---------------- grid-wide spin barrier ----------------
__device__ unsigned int g_bar_cnt;
__device__ unsigned int g_bar_gen;

__device__ __forceinline__ void grid_barrier() {
    __syncthreads();
    if (threadIdx.x == 0) {
        __threadfence();
        unsigned int gen = atomicAdd(&g_bar_gen, 0u);
        unsigned int arrived = atomicAdd(&g_bar_cnt, 1u);
        if (arrived == gridDim.x - 1) {
            g_bar_cnt = 0;
            __threadfence();
            atomicAdd(&g_bar_gen, 1u);
        } else {
            while (atomicAdd(&g_bar_gen, 0u) == gen) __nanosleep(128);
        }
        __threadfence();
    }
    __syncthreads();
}

// ---------------- helpers ----------------
__device__ __forceinline__ float silu_f(float x) {
    return x / (1.f + __expf(-x));
}

__device__ __forceinline__ void split_bf16(float v, bf16& h, bf16& l) {
    h = __float2bfloat16(v);
    l = __float2bfloat16(v - __bfloat162float(h));
}

__device__ __forceinline__ unsigned int pk2(bf16 a, bf16 b) {
    return (unsigned int)__bfloat16_as_ushort(a) |
           ((unsigned int)__bfloat16_as_ushort(b) << 16);
}

__device__ __forceinline__ void ldsm4(unsigned int r[4], const void* p) {
    unsigned int a = (unsigned int)__cvta_generic_to_shared(p);
    asm volatile("ldmatrix.sync.aligned.m8n8.x4.shared.b16 {%0,%1,%2,%3}, [%4];"
                 : "=r"(r[0]), "=r"(r[1]), "=r"(r[2]), "=r"(r[3]) : "r"(a));
}

__device__ __forceinline__ void mma_bf16(float c[4], const unsigned int a[4],
                                         unsigned int b0, unsigned int b1) {
    asm volatile(
        "mma.sync.aligned.m16n8k16.row.col.f32.bf16.bf16.f32 "
        "{%0,%1,%2,%3},{%4,%5,%6,%7},{%8,%9},{%0,%1,%2,%3};"
        : "+f"(c[0]), "+f"(c[1]), "+f"(c[2]), "+f"(c[3])
        : "r"(a[0]), "r"(a[1]), "r"(a[2]), "r"(a[3]), "r"(b0), "r"(b1));
}

// ---------------- gemm tile ----------------
#define PADK 40
#define GEMM_SMEM 30720
__device__ void gemm_tile(char* s_raw,
    const bf16* __restrict__ Ah, const bf16* __restrict__ Al,
    const bf16* __restrict__ Wh, const bf16* __restrict__ Wl,
    float* __restrict__ C, int N, int K, int accumulate, int bm, int bn)
{
    bf16 (*sAh)[PADK] = (bf16(*)[PADK])(s_raw);
    bf16 (*sAl)[PADK] = (bf16(*)[PADK])(s_raw + 10240);
    bf16 (*sWh)[PADK] = (bf16(*)[PADK])(s_raw + 20480);
    bf16 (*sWl)[PADK] = (bf16(*)[PADK])(s_raw + 25600);

    const int tid  = threadIdx.x;
    const int lane = tid & 31;
    const int wid  = tid >> 5;
    const int wm   = (wid & 3) * 32;
    const int wn   = (wid >> 2) * 32;

    float acc[2][4][4];
    #pragma unroll
    for (int a = 0; a < 2; a++)
        #pragma unroll
        for (int b = 0; b < 4; b++)
            #pragma unroll
            for (int c = 0; c < 4; c++) acc[a][b][c] = 0.f;

    const int lrow = tid >> 2;
    const int lcol = (tid & 3) * 8;

    const int a_row = lane & 15;
    const int a_col = (lane >> 4) << 3;
    const int bq    = lane >> 3;
    const int b_row = (lane & 7) + ((bq >> 1) << 3);
    const int b_col = (bq & 1) << 3;

    for (int kt = 0; kt < K; kt += 32) {
        const bf16* pA = Ah + (size_t)(bm + lrow) * K + kt + lcol;
        const bf16* pa = Al + (size_t)(bm + lrow) * K + kt + lcol;
        *(uint4*)&sAh[lrow     ][lcol] = *(const uint4*)pA;
        *(uint4*)&sAh[lrow + 64][lcol] = *(const uint4*)(pA + (size_t)64 * K);
        *(uint4*)&sAl[lrow     ][lcol] = *(const uint4*)pa;
        *(uint4*)&sAl[lrow + 64][lcol] = *(const uint4*)(pa + (size_t)64 * K);
        const bf16* pW = Wh + (size_t)(bn + lrow) * K + kt + lcol;
        const bf16* pw = Wl + (size_t)(bn + lrow) * K + kt + lcol;
        *(uint4*)&sWh[lrow][lcol] = *(const uint4*)pW;
        *(uint4*)&sWl[lrow][lcol] = *(const uint4*)pw;
        __syncthreads();

        #pragma unroll
        for (int ks = 0; ks < 2; ks++) {
            const int k0 = ks * 16;
            unsigned int ah[2][4], al[2][4];
            #pragma unroll
            for (int mt = 0; mt < 2; mt++) {
                ldsm4(ah[mt], &sAh[wm + mt * 16 + a_row][k0 + a_col]);
                ldsm4(al[mt], &sAl[wm + mt * 16 + a_row][k0 + a_col]);
            }
            unsigned int bh[2][4], bl[2][4];
            #pragma unroll
            for (int nb = 0; nb < 2; nb++) {
                ldsm4(bh[nb], &sWh[wn + nb * 16 + b_row][k0 + b_col]);
                ldsm4(bl[nb], &sWl[wn + nb * 16 + b_row][k0 + b_col]);
            }
            #pragma unroll
            for (int mt = 0; mt < 2; mt++) {
                #pragma unroll
                for (int nt = 0; nt < 4; nt++) {
                    const int nb = nt >> 1, hf = (nt & 1) * 2;
                    mma_bf16(acc[mt][nt], ah[mt], bh[nb][hf], bh[nb][hf + 1]);
                    mma_bf16(acc[mt][nt], ah[mt], bl[nb][hf], bl[nb][hf + 1]);
                    mma_bf16(acc[mt][nt], al[mt], bh[nb][hf], bh[nb][hf + 1]);
                }
            }
        }
        __syncthreads();
    }

    const int cg = lane >> 2;
    const int ct = (lane & 3) * 2;
    #pragma unroll
    for (int mt = 0; mt < 2; mt++) {
        #pragma unroll
        for (int nt = 0; nt < 4; nt++) {
            int r0 = bm + wm + mt * 16 + cg;
            int c0 = bn + wn + nt * 8 + ct;
            float2* p0 = (float2*)(C + (size_t)r0 * N + c0);
            float2* p1 = (float2*)(C + (size_t)(r0 + 8) * N + c0);
            float2 v0 = make_float2(acc[mt][nt][0], acc[mt][nt][1]);
            float2 v1 = make_float2(acc[mt][nt][2], acc[mt][nt][3]);
            if (accumulate) {
                float2 o0 = *p0, o1 = *p1;
                v0.x += o0.x; v0.y += o0.y;
                v1.x += o1.x; v1.y += o1.y;
            }
            *p0 = v0; *p1 = v1;
        }
    }
}

// ---------------- merged embed + pos-encoding + weight split ----------------
__global__ void emb_split_kernel(const float* __restrict__ x,
                                 const float* __restrict__ emb_w,
                                 const float* __restrict__ emb_b,
                                 const float* __restrict__ in_w,
                                 const float* __restrict__ out_w) {
    if (blockIdx.x < BT) {
        int bt = blockIdx.x;
        int d  = threadIdx.x;
        __shared__ float sx[32];
        if (d < 32) sx[d] = x[bt * 32 + d];
        __syncthreads();
        float acc = emb_b[d];
        const float* w = emb_w + d * 32;
        #pragma unroll
        for (int i = 0; i < 32; i++) acc = fmaf(sx[i], w[i], acc);
        int t = bt & (TT - 1);
        int k2 = d & ~1;
        float div = __expf((float)k2 * (-9.210340371976184f / 256.0f));
        float ang = (float)t * div;
        acc += (d & 1) ? cosf(ang) : sinf(ang);
        g_h[bt * DD + d] = acc;
    } else {
        int i = (blockIdx.x - BT) * 256 + threadIdx.x;
        if (i < NW) {
            split_bf16(in_w[i], g_iwh[i], g_iwl[i]);
        } else {
            int j = i - NW;
            split_bf16(out_w[j], g_owh[j], g_owl[j]);
        }
    }
}

// ---------------- kernel A: LN + gemm1 (128-reg class) ----------------
__global__ __launch_bounds__(256, 2) void kernel_a(
    const float* __restrict__ ng,  const float* __restrict__ nb_,
    const bf16* __restrict__ iwh,  const bf16* __restrict__ iwl)
{
    __shared__ __align__(16) char s_raw[GEMM_SMEM];
    const int bid = blockIdx.x;
    const int nbk = gridDim.x;
    const int tid = threadIdx.x;
    const int lane = tid & 31;
    const int warp = tid >> 5;

    // ---- LN (warp per row) -> g_lnh/g_lnl ----
    for (int row = bid * 8 + warp; row < BT; row += nbk * 8) {
        const float* p = g_h + (size_t)row * DD + lane * 8;
        float4 a = *(const float4*)p;
        float4 c = *(const float4*)(p + 4);
        float v[8] = {a.x, a.y, a.z, a.w, c.x, c.y, c.z, c.w};
        float s = 0.f;
        #pragma unroll
        for (int j = 0; j < 8; j++) s += v[j];
        #pragma unroll
        for (int o = 16; o; o >>= 1) s += __shfl_xor_sync(0xffffffffu, s, o);
        float mean = s * (1.f / 256.f);
        float vv = 0.f;
        #pragma unroll
        for (int j = 0; j < 8; j++) { float d0 = v[j] - mean; vv += d0 * d0; }
        #pragma unroll
        for (int o = 16; o; o >>= 1) vv += __shfl_xor_sync(0xffffffffu, vv, o);
        float rstd = rsqrtf(vv * (1.f / 256.f) + 1e-5f);
        float4 gg0 = *(const float4*)(ng + lane * 8);
        float4 gg1 = *(const float4*)(ng + lane * 8 + 4);
        float4 bb0 = *(const float4*)(nb_ + lane * 8);
        float4 bb1 = *(const float4*)(nb_ + lane * 8 + 4);
        float gv[8] = {gg0.x, gg0.y, gg0.z, gg0.w, gg1.x, gg1.y, gg1.z, gg1.w};
        float bv[8] = {bb0.x, bb0.y, bb0.z, bb0.w, bb1.x, bb1.y, bb1.z, bb1.w};
        bf16 oh[8], ol[8];
        #pragma unroll
        for (int j = 0; j < 8; j++) {
            float o = (v[j] - mean) * rstd * gv[j] + bv[j];
            split_bf16(o, oh[j], ol[j]);
        }
        uint4 uh, ul;
        uh.x = pk2(oh[0], oh[1]); uh.y = pk2(oh[2], oh[3]);
        uh.z = pk2(oh[4], oh[5]); uh.w = pk2(oh[6], oh[7]);
        ul.x = pk2(ol[0], ol[1]); ul.y = pk2(ol[2], ol[3]);
        ul.z = pk2(ol[4], ol[5]); ul.w = pk2(ol[6], ol[7]);
        *(uint4*)(g_lnh + (size_t)row * DD + lane * 8) = uh;
        *(uint4*)(g_lnl + (size_t)row * DD + lane * 8) = ul;
    }
    grid_barrier();

    // ---- gemm1 (512 tiles) ----
    for (int t = bid; t < 512; t += nbk)
        gemm_tile(s_raw, g_lnh, g_lnl, iwh, iwl, g_v, HH, DD, 0,
                  (t >> 3) * 128, (t & 7) * 64);
}

// ---------------- kernel MID: conv + dt + scan (64-reg class, 4 blk/SM) ----------------
#define MID_SMEM 9216
__global__ __launch_bounds__(256, 4) void kernel_mid(
    const float* __restrict__ cw,
    const float* __restrict__ Apw, const float* __restrict__ Dpw,
    const float* __restrict__ w1,  const float* __restrict__ b1,
    const float* __restrict__ w2,  const float* __restrict__ b2)
{
    __shared__ __align__(16) char s_raw[MID_SMEM];
    const int bid = blockIdx.x;
    const int nbk = gridDim.x;
    const int tid = threadIdx.x;

    // ---- conv(k=3)+silu+transpose: g_v[bt][h] -> g_vcT[h][bt] (4096 tasks) ----
    {
        float (*tile)[33] = (float(*)[33])(s_raw);
        for (int task = bid; task < BB * 16 * 32; task += nbk) {
            const int b  = task >> 9;
            const int h0 = ((task >> 5) & 15) * 32;
            const int t0 = (task & 31) * 32;
            #pragma unroll
            for (int i = tid; i < 34 * 32; i += 256) {
                int tt = i >> 5;
                int hh = i & 31;
                int t  = t0 + tt - 1;
                float v = 0.f;
                if (t >= 0 && t < TT)
                    v = g_v[((size_t)b * TT + t) * HH + h0 + hh];
                tile[tt][hh] = v;
            }
            __syncthreads();
            const int tl = tid & 31;
            const int hq = tid >> 5;
            #pragma unroll
            for (int j = 0; j < 4; j++) {
                int hh = hq * 4 + j;
                int h  = h0 + hh;
                float w0 = cw[h * 3 + 0], w1v = cw[h * 3 + 1], w2v = cw[h * 3 + 2];
                float acc = tile[tl][hh] * w0;
                acc = fmaf(tile[tl + 1][hh], w1v, acc);
                acc = fmaf(tile[tl + 2][hh], w2v, acc);
                g_vcT[(size_t)h * BT + b * TT + t0 + tl] = silu_f(acc);
            }
            __syncthreads();
        }
    }
    grid_barrier();

    // ---- dt1 + dt2 fused -> g_dtT[h][bt] (128 tasks of 64 bt) ----
    {
        float (*red)[64][9] = (float(*)[64][9])(s_raw);          // [3][64][9]
        float (*dtrs)[9]    = (float(*)[9])(s_raw + 6912);
        const int btl = tid & 63;
        const int q   = tid >> 6;       // 0..3
        for (int task = bid; task < BT / 64; task += nbk) {
            const int bt0 = task * 64;
            float acc[RR];
            #pragma unroll
            for (int r = 0; r < RR; r++) acc[r] = 0.f;
            const int hbase = q * 128;
            #pragma unroll 4
            for (int hh = 0; hh < 128; hh++) {
                int h = hbase + hh;
                float v = g_vcT[(size_t)h * BT + bt0 + btl];
                #pragma unroll
                for (int r = 0; r < RR; r++) acc[r] = fmaf(v, w1[r * HH + h], acc[r]);
            }
            if (q > 0) {
                #pragma unroll
                for (int r = 0; r < RR; r++) red[q - 1][btl][r] = acc[r];
            }
            __syncthreads();
            if (q == 0) {
                #pragma unroll
                for (int r = 0; r < RR; r++)
                    dtrs[btl][r] = fmaxf(acc[r] + red[0][btl][r] + red[1][btl][r]
                                         + red[2][btl][r] + b1[r], 0.f);
            }
            __syncthreads();
            for (int hh = q; hh < HH; hh += 4) {
                float wreg[RR];
                #pragma unroll
                for (int r = 0; r < RR; r++) wreg[r] = w2[hh * RR + r];
                float a2 = b2[hh];
                #pragma unroll
                for (int r = 0; r < RR; r++) a2 = fmaf(dtrs[btl][r], wreg[r], a2);
                float sp = (a2 > 15.f) ? a2 : log1pf(__expf(a2));
                g_dtT[(size_t)hh * BT + bt0 + btl] = sp;
            }
            __syncthreads();
        }
    }
    grid_barrier();

    // ---- scan pass 1: chunk summaries (P, e) into g_v scratch ----
    {
        float2* scr = (float2*)g_v;
        const int u = tid >> 4;
        const int n = tid & 15;
        for (int task = bid; task < BB * 32 * 32; task += nbk) {
            const int b  = task >> 10;
            const int hb = (task >> 5) & 31;
            const int ck = task & 31;
            const int h  = hb * 16 + u;
            const int ch = b * HH + h;
            float Ap = Apw[h * NN + n];
            float A  = -__expf(Ap);
            float invA = (fabsf(A) < 1e-5f) ? 1.f : (1.f / A);
            const float* xr = g_vcT + (size_t)h * BT + b * TT + ck * 32;
            const float* dr = g_dtT + (size_t)h * BT + b * TT + ck * 32;
            float state = 0.f, P = 1.f;
            #pragma unroll 8
            for (int t = 0; t < 32; t++) {
                float dtv = dr[t];
                float x   = xr[t];
                float dA = __expf(A * dtv);
                float dB = (dA - 1.f) * invA * dtv;
                state = fmaf(dA, state, dB * x);
                P *= dA;
            }
            scr[((size_t)ch * 32 + ck) * 16 + n] = make_float2(P, state);
        }
    }
    grid_barrier();

    // ---- scan pass 2: serial carry per (ch, n); stored in-place (.x) ----
    {
        float2* scr = (float2*)g_v;
        for (int i = bid * 256 + tid; i < CH * NN; i += nbk * 256) {
            float2* base = scr + ((size_t)(i >> 4) * 32) * 16 + (i & 15);
            float c = 0.f;
            #pragma unroll 8
            for (int j = 0; j < 32; j++) {
                float2 s = base[(size_t)j * 16];
                base[(size_t)j * 16].x = c;
                c = fmaf(s.x, c, s.y);
            }
        }
    }
    grid_barrier();

    // ---- scan pass 3: re-scan with carry init, emit y ----
    {
        float2* scr = (float2*)g_v;
        bf16 (*s_yh)[16] = (bf16(*)[16])(s_raw);
        bf16 (*s_yl)[16] = (bf16(*)[16])(s_raw + 1024);
        const int u = tid >> 4;
        const int n = tid & 15;
        const int fl_t = tid >> 3;      // 0..31
        const int fl_h = (tid & 7) * 2; // 0..14
        for (int task = bid; task < BB * 32 * 32; task += nbk) {
            const int b  = task >> 10;
            const int hb = (task >> 5) & 31;
            const int ck = task & 31;
            const int h  = hb * 16 + u;
            const int ch = b * HH + h;
            float Ap = Apw[h * NN + n];
            float A  = -__expf(Ap);
            float invA = (fabsf(A) < 1e-5f) ? 1.f : (1.f / A);
            float Dp = Dpw[h];
            const float* xr = g_vcT + (size_t)h * BT + b * TT + ck * 32;
            const float* dr = g_dtT + (size_t)h * BT + b * TT + ck * 32;
            float state = scr[((size_t)ch * 32 + ck) * 16 + n].x;
            #pragma unroll 8
            for (int t = 0; t < 32; t++) {
                float dtv = dr[t];
                float x   = xr[t];
                float dA = __expf(A * dtv);
                float dB = (dA - 1.f) * invA * dtv;
                state = fmaf(dA, state, dB * x);
                float part = state * Ap;
                part += __shfl_xor_sync(0xffffffffu, part, 8);
                part += __shfl_xor_sync(0xffffffffu, part, 4);
                part += __shfl_xor_sync(0xffffffffu, part, 2);
                part += __shfl_xor_sync(0xffffffffu, part, 1);
                if (n == 0) {
                    float y = fmaf(Dp, x, part);
                    bf16 hh_, ll_;
                    split_bf16(y, hh_, ll_);
                    s_yh[t][u] = hh_;
                    s_yl[t][u] = ll_;
                }
            }
            __syncthreads();
            size_t base = (size_t)(b * TT + ck * 32 + fl_t) * HH + hb * 16 + fl_h;
            *(unsigned int*)(g_yh + base) = *(unsigned int*)&s_yh[fl_t][fl_h];
            *(unsigned int*)(g_yl + base) = *(unsigned int*)&s_yl[fl_t][fl_h];
            __syncthreads();
        }
    }
}

// ---------------- kernel B: gemm2 (one tile per block) ----------------
__global__ __launch_bounds__(256, 2) void kernel_b(
    const bf16* __restrict__ owh, const bf16* __restrict__ owl)
{
    __shared__ __align__(16) char s_raw[GEMM_SMEM];
    const int t = blockIdx.x;   // 256 tiles: 64 m x 4 n
    gemm_tile(s_raw, g_yh, g_yl, owh, owl, g_h, DD, HH, 1,
              (t >> 2) * 128, (t & 3) * 64);
}

// ---------------- final LN (last token) + head1(silu) + head2 ----------------
__global__ void final_kernel(const float* __restrict__ fg,
                             const float* __restrict__ fb,
                             const float* __restrict__ w1,
                             const float* __restrict__ b1,
                             const float* __restrict__ w2,
                             const float* __restrict__ b2,
                             float* __restrict__ out) {
    int b = blockIdx.x;
    int tid = threadIdx.x;
    __shared__ float red1[8], red2[8];
    __shared__ float s_ln[DD];
    __shared__ float s_h1[DD];
    const float* row = g_h + (size_t)(b * TT + (TT - 1)) * DD;
    float v = row[tid];
    float s = v;
    #pragma unroll
    for (int o = 16; o; o >>= 1) s += __shfl_xor_sync(0xffffffffu, s, o);
    if ((tid & 31) == 0) red1[tid >> 5] = s;
    __syncthreads();
    float mean = 0.f;
    #pragma unroll
    for (int i = 0; i < 8; i++) mean += red1[i];
    mean *= (1.f / 256.f);
    float c = v - mean;
    float cc = c * c;
    #pragma unroll
    for (int o = 16; o; o >>= 1) cc += __shfl_xor_sync(0xffffffffu, cc, o);
    if ((tid & 31) == 0) red2[tid >> 5] = cc;
    __syncthreads();
    float var = 0.f;
    #pragma unroll
    for (int i = 0; i < 8; i++) var += red2[i];
    var *= (1.f / 256.f);
    s_ln[tid] = c * rsqrtf(var + 1e-5f) * fg[tid] + fb[tid];
    __syncthreads();
    float acc = b1[tid];
    const float* w1r = w1 + tid * DD;
    #pragma unroll 8
    for (int k = 0; k < DD; k++) acc = fmaf(s_ln[k], w1r[k], acc);
    s_h1[tid] = silu_f(acc);
    __syncthreads();
    if (tid < 96) {
        float a2 = b2[tid];
        const float* w2r = w2 + tid * DD;
        #pragma unroll 8
        for (int k = 0; k < DD; k++) a2 = fmaf(s_h1[k], w2r[k], a2);
        out[b * 96 + tid] = a2;
    }
}

// ---------------- launcher: 14 graph nodes ----------------
extern "C" void kernel_launch(void* const* d_in, const int* in_sizes, int n_in,
                              void* d_out, int out_size) {
    const float* x      = (const float*)d_in[0];
    const float* emb_w  = (const float*)d_in[1];
    const float* emb_b  = (const float*)d_in[2];
    const float* norm_g = (const float*)d_in[3];
    const float* norm_b = (const float*)d_in[4];
    const float* in_w   = (const float*)d_in[5];
    const float* conv_w = (const float*)d_in[6];
    const float* A_p    = (const float*)d_in[7];
    const float* D_p    = (const float*)d_in[8];
    const float* dt1_w  = (const float*)d_in[9];
    const float* dt1_b  = (const float*)d_in[10];
    const float* dt2_w  = (const float*)d_in[11];
    const float* dt2_b  = (const float*)d_in[12];
    const float* out_w  = (const float*)d_in[13];
    const float* fin_g  = (const float*)d_in[14];
    const float* fin_b  = (const float*)d_in[15];
    const float* h1_w   = (const float*)d_in[16];
    const float* h1_b   = (const float*)d_in[17];
    const float* h2_w   = (const float*)d_in[18];
    const float* h2_b   = (const float*)d_in[19];
    float* out = (float*)d_out;

    bf16 *piwh, *piwl, *powh, *powl;
    cudaGetSymbolAddress((void**)&piwh, g_iwh);
    cudaGetSymbolAddress((void**)&piwl, g_iwl);
    cudaGetSymbolAddress((void**)&powh, g_owh);
    cudaGetSymbolAddress((void**)&powl, g_owl);

    emb_split_kernel<<<BT + (2 * NW) / 256, 256>>>(x, emb_w, emb_b, in_w, out_w);

    for (int l = 0; l < LL; l++) {
        kernel_a<<<GRID_A, 256>>>(
            norm_g + l * DD, norm_b + l * DD,
            piwh + (size_t)l * HH * DD, piwl + (size_t)l * HH * DD);

        kernel_mid<<<GRID_MID, 256>>>(
            conv_w + (size_t)l * HH * 3,
            A_p + (size_t)l * HH * NN, D_p + l * HH,
            dt1_w + (size_t)l * RR * HH, dt1_b + l * RR,
            dt2_w + (size_t)l * HH * RR, dt2_b + l * HH);

        kernel_b<<<256, 256>>>(
            powh + (size_t)l * DD * HH, powl + (size_t)l * DD * HH);
    }

    final_kernel<<<BB, 256>>>(fin_g, fin_b, h1_w, h1_b, h2_w, h2_b, out);
}

// round 10
// speedup vs baseline: 1.4905x; 1.2857x over previous
#include <cuda_runtime.h>
#include <cuda_bf16.h>
#include <cstdint>
#include <math.h>

typedef __nv_bfloat16 bf16;

// ---------------- problem constants ----------------
#define BB   8
#define TT   1024
#define DD   256
#define HH   512
#define NN   16
#define RR   8
#define LL   4
#define BT   (BB*TT)        // 8192
#define BTH  (BB*TT*HH)     // 4194304
#define BTD  (BB*TT*DD)     // 2097152
#define NW   (LL*HH*DD)     // 524288
#define CH   (BB*HH)        // 4096 channels

#define GRID_A   256        // gemm1: 512 tiles -> exactly 2 per block
#define GRID_MID 592        // 148 SMs x 4 blocks (64-reg class)

// ---------------- scratch (static device globals; no allocation) ----------------
__device__ float g_h  [BTD];
__device__ float g_v  [BTH];        // gemm1 out; reused as scan scratch (float2 summaries)
__device__ float g_vcT[BTH];        // [h][bt]
__device__ float g_dtT[BTH];        // [h][bt]
__device__ bf16 g_lnh[BTD], g_lnl[BTD];
__device__ bf16 g_yh [BTH], g_yl [BTH];   // [bt][h]
__device__ bf16 g_iwh[NW],  g_iwl[NW];
__device__ bf16 g_owh[NW],  g_owl[NW];

// ---------------- grid-wide spin barrier ----------------
__device__ unsigned int g_bar_cnt;
__device__ unsigned int g_bar_gen;

__device__ __forceinline__ void grid_barrier() {
    __syncthreads();
    if (threadIdx.x == 0) {
        __threadfence();
        unsigned int gen = atomicAdd(&g_bar_gen, 0u);
        unsigned int arrived = atomicAdd(&g_bar_cnt, 1u);
        if (arrived == gridDim.x - 1) {
            g_bar_cnt = 0;
            __threadfence();
            atomicAdd(&g_bar_gen, 1u);
        } else {
            while (atomicAdd(&g_bar_gen, 0u) == gen) __nanosleep(128);
        }
        __threadfence();
    }
    __syncthreads();
}

// ---------------- helpers ----------------
__device__ __forceinline__ float silu_f(float x) {
    return x / (1.f + __expf(-x));
}

__device__ __forceinline__ float ex2f(float x) {
    float r;
    asm("ex2.approx.ftz.f32 %0, %1;" : "=f"(r) : "f"(x));
    return r;
}

__device__ __forceinline__ void split_bf16(float v, bf16& h, bf16& l) {
    h = __float2bfloat16(v);
    l = __float2bfloat16(v - __bfloat162float(h));
}

__device__ __forceinline__ unsigned int pk2(bf16 a, bf16 b) {
    return (unsigned int)__bfloat16_as_ushort(a) |
           ((unsigned int)__bfloat16_as_ushort(b) << 16);
}

__device__ __forceinline__ void ldsm4(unsigned int r[4], const void* p) {
    unsigned int a = (unsigned int)__cvta_generic_to_shared(p);
    asm volatile("ldmatrix.sync.aligned.m8n8.x4.shared.b16 {%0,%1,%2,%3}, [%4];"
                 : "=r"(r[0]), "=r"(r[1]), "=r"(r[2]), "=r"(r[3]) : "r"(a));
}

__device__ __forceinline__ void mma_bf16(float c[4], const unsigned int a[4],
                                         unsigned int b0, unsigned int b1) {
    asm volatile(
        "mma.sync.aligned.m16n8k16.row.col.f32.bf16.bf16.f32 "
        "{%0,%1,%2,%3},{%4,%5,%6,%7},{%8,%9},{%0,%1,%2,%3};"
        : "+f"(c[0]), "+f"(c[1]), "+f"(c[2]), "+f"(c[3])
        : "r"(a[0]), "r"(a[1]), "r"(a[2]), "r"(a[3]), "r"(b0), "r"(b1));
}

// ---------------- gemm tile ----------------
#define PADK 40
#define GEMM_SMEM 30720
__device__ void gemm_tile(char* s_raw,
    const bf16* __restrict__ Ah, const bf16* __restrict__ Al,
    const bf16* __restrict__ Wh, const bf16* __restrict__ Wl,
    float* __restrict__ C, int N, int K, int accumulate, int bm, int bn)
{
    bf16 (*sAh)[PADK] = (bf16(*)[PADK])(s_raw);
    bf16 (*sAl)[PADK] = (bf16(*)[PADK])(s_raw + 10240);
    bf16 (*sWh)[PADK] = (bf16(*)[PADK])(s_raw + 20480);
    bf16 (*sWl)[PADK] = (bf16(*)[PADK])(s_raw + 25600);

    const int tid  = threadIdx.x;
    const int lane = tid & 31;
    const int wid  = tid >> 5;
    const int wm   = (wid & 3) * 32;
    const int wn   = (wid >> 2) * 32;

    float acc[2][4][4];
    #pragma unroll
    for (int a = 0; a < 2; a++)
        #pragma unroll
        for (int b = 0; b < 4; b++)
            #pragma unroll
            for (int c = 0; c < 4; c++) acc[a][b][c] = 0.f;

    const int lrow = tid >> 2;
    const int lcol = (tid & 3) * 8;

    const int a_row = lane & 15;
    const int a_col = (lane >> 4) << 3;
    const int bq    = lane >> 3;
    const int b_row = (lane & 7) + ((bq >> 1) << 3);
    const int b_col = (bq & 1) << 3;

    for (int kt = 0; kt < K; kt += 32) {
        const bf16* pA = Ah + (size_t)(bm + lrow) * K + kt + lcol;
        const bf16* pa = Al + (size_t)(bm + lrow) * K + kt + lcol;
        *(uint4*)&sAh[lrow     ][lcol] = *(const uint4*)pA;
        *(uint4*)&sAh[lrow + 64][lcol] = *(const uint4*)(pA + (size_t)64 * K);
        *(uint4*)&sAl[lrow     ][lcol] = *(const uint4*)pa;
        *(uint4*)&sAl[lrow + 64][lcol] = *(const uint4*)(pa + (size_t)64 * K);
        const bf16* pW = Wh + (size_t)(bn + lrow) * K + kt + lcol;
        const bf16* pw = Wl + (size_t)(bn + lrow) * K + kt + lcol;
        *(uint4*)&sWh[lrow][lcol] = *(const uint4*)pW;
        *(uint4*)&sWl[lrow][lcol] = *(const uint4*)pw;
        __syncthreads();

        #pragma unroll
        for (int ks = 0; ks < 2; ks++) {
            const int k0 = ks * 16;
            unsigned int ah[2][4], al[2][4];
            #pragma unroll
            for (int mt = 0; mt < 2; mt++) {
                ldsm4(ah[mt], &sAh[wm + mt * 16 + a_row][k0 + a_col]);
                ldsm4(al[mt], &sAl[wm + mt * 16 + a_row][k0 + a_col]);
            }
            unsigned int bh[2][4], bl[2][4];
            #pragma unroll
            for (int nb = 0; nb < 2; nb++) {
                ldsm4(bh[nb], &sWh[wn + nb * 16 + b_row][k0 + b_col]);
                ldsm4(bl[nb], &sWl[wn + nb * 16 + b_row][k0 + b_col]);
            }
            #pragma unroll
            for (int mt = 0; mt < 2; mt++) {
                #pragma unroll
                for (int nt = 0; nt < 4; nt++) {
                    const int nb = nt >> 1, hf = (nt & 1) * 2;
                    mma_bf16(acc[mt][nt], ah[mt], bh[nb][hf], bh[nb][hf + 1]);
                    mma_bf16(acc[mt][nt], ah[mt], bl[nb][hf], bl[nb][hf + 1]);
                    mma_bf16(acc[mt][nt], al[mt], bh[nb][hf], bh[nb][hf + 1]);
                }
            }
        }
        __syncthreads();
    }

    const int cg = lane >> 2;
    const int ct = (lane & 3) * 2;
    #pragma unroll
    for (int mt = 0; mt < 2; mt++) {
        #pragma unroll
        for (int nt = 0; nt < 4; nt++) {
            int r0 = bm + wm + mt * 16 + cg;
            int c0 = bn + wn + nt * 8 + ct;
            float2* p0 = (float2*)(C + (size_t)r0 * N + c0);
            float2* p1 = (float2*)(C + (size_t)(r0 + 8) * N + c0);
            float2 v0 = make_float2(acc[mt][nt][0], acc[mt][nt][1]);
            float2 v1 = make_float2(acc[mt][nt][2], acc[mt][nt][3]);
            if (accumulate) {
                float2 o0 = *p0, o1 = *p1;
                v0.x += o0.x; v0.y += o0.y;
                v1.x += o1.x; v1.y += o1.y;
            }
            *p0 = v0; *p1 = v1;
        }
    }
}

// ---------------- merged embed + pos-encoding + weight split ----------------
__global__ void emb_split_kernel(const float* __restrict__ x,
                                 const float* __restrict__ emb_w,
                                 const float* __restrict__ emb_b,
                                 const float* __restrict__ in_w,
                                 const float* __restrict__ out_w) {
    if (blockIdx.x < BT) {
        int bt = blockIdx.x;
        int d  = threadIdx.x;
        __shared__ float sx[32];
        if (d < 32) sx[d] = x[bt * 32 + d];
        __syncthreads();
        float acc = emb_b[d];
        const float* w = emb_w + d * 32;
        #pragma unroll
        for (int i = 0; i < 32; i++) acc = fmaf(sx[i], w[i], acc);
        int t = bt & (TT - 1);
        int k2 = d & ~1;
        float div = __expf((float)k2 * (-9.210340371976184f / 256.0f));
        float ang = (float)t * div;
        acc += (d & 1) ? cosf(ang) : sinf(ang);
        g_h[bt * DD + d] = acc;
    } else {
        int i = (blockIdx.x - BT) * 256 + threadIdx.x;
        if (i < NW) {
            split_bf16(in_w[i], g_iwh[i], g_iwl[i]);
        } else {
            int j = i - NW;
            split_bf16(out_w[j], g_owh[j], g_owl[j]);
        }
    }
}

// ---------------- kernel A: LN + gemm1 (128-reg class) ----------------
__global__ __launch_bounds__(256, 2) void kernel_a(
    const float* __restrict__ ng,  const float* __restrict__ nb_,
    const bf16* __restrict__ iwh,  const bf16* __restrict__ iwl)
{
    __shared__ __align__(16) char s_raw[GEMM_SMEM];
    const int bid = blockIdx.x;
    const int nbk = gridDim.x;
    const int tid = threadIdx.x;
    const int lane = tid & 31;
    const int warp = tid >> 5;

    // ---- LN (warp per row) -> g_lnh/g_lnl ----
    for (int row = bid * 8 + warp; row < BT; row += nbk * 8) {
        const float* p = g_h + (size_t)row * DD + lane * 8;
        float4 a = *(const float4*)p;
        float4 c = *(const float4*)(p + 4);
        float v[8] = {a.x, a.y, a.z, a.w, c.x, c.y, c.z, c.w};
        float s = 0.f;
        #pragma unroll
        for (int j = 0; j < 8; j++) s += v[j];
        #pragma unroll
        for (int o = 16; o; o >>= 1) s += __shfl_xor_sync(0xffffffffu, s, o);
        float mean = s * (1.f / 256.f);
        float vv = 0.f;
        #pragma unroll
        for (int j = 0; j < 8; j++) { float d0 = v[j] - mean; vv += d0 * d0; }
        #pragma unroll
        for (int o = 16; o; o >>= 1) vv += __shfl_xor_sync(0xffffffffu, vv, o);
        float rstd = rsqrtf(vv * (1.f / 256.f) + 1e-5f);
        float4 gg0 = *(const float4*)(ng + lane * 8);
        float4 gg1 = *(const float4*)(ng + lane * 8 + 4);
        float4 bb0 = *(const float4*)(nb_ + lane * 8);
        float4 bb1 = *(const float4*)(nb_ + lane * 8 + 4);
        float gv[8] = {gg0.x, gg0.y, gg0.z, gg0.w, gg1.x, gg1.y, gg1.z, gg1.w};
        float bv[8] = {bb0.x, bb0.y, bb0.z, bb0.w, bb1.x, bb1.y, bb1.z, bb1.w};
        bf16 oh[8], ol[8];
        #pragma unroll
        for (int j = 0; j < 8; j++) {
            float o = (v[j] - mean) * rstd * gv[j] + bv[j];
            split_bf16(o, oh[j], ol[j]);
        }
        uint4 uh, ul;
        uh.x = pk2(oh[0], oh[1]); uh.y = pk2(oh[2], oh[3]);
        uh.z = pk2(oh[4], oh[5]); uh.w = pk2(oh[6], oh[7]);
        ul.x = pk2(ol[0], ol[1]); ul.y = pk2(ol[2], ol[3]);
        ul.z = pk2(ol[4], ol[5]); ul.w = pk2(ol[6], ol[7]);
        *(uint4*)(g_lnh + (size_t)row * DD + lane * 8) = uh;
        *(uint4*)(g_lnl + (size_t)row * DD + lane * 8) = ul;
    }
    grid_barrier();

    // ---- gemm1 (512 tiles, exactly 2 per block) ----
    for (int t = bid; t < 512; t += nbk)
        gemm_tile(s_raw, g_lnh, g_lnl, iwh, iwl, g_v, HH, DD, 0,
                  (t >> 3) * 128, (t & 7) * 64);
}

// ---------------- kernel MID: conv + dt + scan (64-reg class, 4 blk/SM) ----------------
#define MID_SMEM 16384
__global__ __launch_bounds__(256, 4) void kernel_mid(
    const float* __restrict__ cw,
    const float* __restrict__ Apw, const float* __restrict__ Dpw,
    const float* __restrict__ w1,  const float* __restrict__ b1,
    const float* __restrict__ w2,  const float* __restrict__ b2)
{
    __shared__ __align__(16) char s_raw[MID_SMEM];
    const int bid = blockIdx.x;
    const int nbk = gridDim.x;
    const int tid = threadIdx.x;
    const int lane = tid & 31;
    const int warp = tid >> 5;

    // ---- conv(k=3)+silu+transpose: g_v[bt][h] -> g_vcT[h][bt] (4096 tasks) ----
    {
        float (*tile)[33] = (float(*)[33])(s_raw);
        for (int task = bid; task < BB * 16 * 32; task += nbk) {
            const int b  = task >> 9;
            const int h0 = ((task >> 5) & 15) * 32;
            const int t0 = (task & 31) * 32;
            #pragma unroll
            for (int i = tid; i < 34 * 32; i += 256) {
                int tt = i >> 5;
                int hh = i & 31;
                int t  = t0 + tt - 1;
                float v = 0.f;
                if (t >= 0 && t < TT)
                    v = g_v[((size_t)b * TT + t) * HH + h0 + hh];
                tile[tt][hh] = v;
            }
            __syncthreads();
            const int tl = tid & 31;
            const int hq = tid >> 5;
            #pragma unroll
            for (int j = 0; j < 4; j++) {
                int hh = hq * 4 + j;
                int h  = h0 + hh;
                float w0 = cw[h * 3 + 0], w1v = cw[h * 3 + 1], w2v = cw[h * 3 + 2];
                float acc = tile[tl][hh] * w0;
                acc = fmaf(tile[tl + 1][hh], w1v, acc);
                acc = fmaf(tile[tl + 2][hh], w2v, acc);
                g_vcT[(size_t)h * BT + b * TT + t0 + tl] = silu_f(acc);
            }
            __syncthreads();
        }
    }
    grid_barrier();

    // ---- dt1 + dt2 fused -> g_dtT[h][bt] (128 tasks of 64 bt) ----
    {
        float (*red)[64][9] = (float(*)[64][9])(s_raw);          // [3][64][9]
        float (*dtrs)[9]    = (float(*)[9])(s_raw + 6912);
        const int btl = tid & 63;
        const int q   = tid >> 6;       // 0..3
        for (int task = bid; task < BT / 64; task += nbk) {
            const int bt0 = task * 64;
            float acc[RR];
            #pragma unroll
            for (int r = 0; r < RR; r++) acc[r] = 0.f;
            const int hbase = q * 128;
            #pragma unroll 4
            for (int hh = 0; hh < 128; hh++) {
                int h = hbase + hh;
                float v = g_vcT[(size_t)h * BT + bt0 + btl];
                #pragma unroll
                for (int r = 0; r < RR; r++) acc[r] = fmaf(v, w1[r * HH + h], acc[r]);
            }
            if (q > 0) {
                #pragma unroll
                for (int r = 0; r < RR; r++) red[q - 1][btl][r] = acc[r];
            }
            __syncthreads();
            if (q == 0) {
                #pragma unroll
                for (int r = 0; r < RR; r++)
                    dtrs[btl][r] = fmaxf(acc[r] + red[0][btl][r] + red[1][btl][r]
                                         + red[2][btl][r] + b1[r], 0.f);
            }
            __syncthreads();
            for (int hh = q; hh < HH; hh += 4) {
                float wreg[RR];
                #pragma unroll
                for (int r = 0; r < RR; r++) wreg[r] = w2[hh * RR + r];
                float a2 = b2[hh];
                #pragma unroll
                for (int r = 0; r < RR; r++) a2 = fmaf(dtrs[btl][r], wreg[r], a2);
                float sp = (a2 > 15.f) ? a2 : log1pf(__expf(a2));
                g_dtT[(size_t)hh * BT + bt0 + btl] = sp;
            }
            __syncthreads();
        }
    }
    grid_barrier();

    // ---- scan pass 1: chunk summaries (P, e) — 2 lanes/channel, 8 n/lane ----
    // warp = 16 channels x 2 halves; task = (b, hb, ck); 8192 warp-tasks
    {
        float2* scr = (float2*)g_v;
        const int u = lane >> 1;    // channel in warp
        const int p = lane & 1;     // n half
        for (int wt = bid * 8 + warp; wt < BB * 32 * 32; wt += nbk * 8) {
            const int b  = wt >> 10;
            const int hb = (wt >> 5) & 31;
            const int ck = wt & 31;
            const int h  = hb * 16 + u;
            const int ch = b * HH + h;
            float A2[8], iA[8];
            #pragma unroll
            for (int j = 0; j < 8; j++) {
                float Ap = Apw[h * NN + p * 8 + j];
                float A  = -__expf(Ap);
                A2[j] = A * 1.4426950408889634f;
                iA[j] = (fabsf(A) < 1e-5f) ? 1.f : (1.f / A);
            }
            const float* xr = g_vcT + (size_t)h * BT + b * TT + ck * 32;
            const float* dr = g_dtT + (size_t)h * BT + b * TT + ck * 32;
            float s[8], P[8];
            #pragma unroll
            for (int j = 0; j < 8; j++) { s[j] = 0.f; P[j] = 1.f; }
            #pragma unroll 2
            for (int t4 = 0; t4 < 32; t4 += 4) {
                float4 xv = *(const float4*)(xr + t4);
                float4 dv = *(const float4*)(dr + t4);
                #pragma unroll
                for (int k = 0; k < 4; k++) {
                    float x   = ((const float*)&xv)[k];
                    float dtv = ((const float*)&dv)[k];
                    float c = dtv * x;
                    #pragma unroll
                    for (int j = 0; j < 8; j++) {
                        float dA = ex2f(A2[j] * dtv);
                        float e  = iA[j] * c;
                        s[j] = fmaf(dA, s[j] + e, -e);
                        P[j] *= dA;
                    }
                }
            }
            float2* out = scr + ((size_t)ch * 32 + ck) * 16 + p * 8;
            #pragma unroll
            for (int j = 0; j < 8; j++) out[j] = make_float2(P[j], s[j]);
        }
    }
    grid_barrier();

    // ---- scan pass 2: serial carry per (ch, n); stored in-place (.x) ----
    {
        float2* scr = (float2*)g_v;
        for (int i = bid * 256 + tid; i < CH * NN; i += nbk * 256) {
            float2* base = scr + ((size_t)(i >> 4) * 32) * 16 + (i & 15);
            float c = 0.f;
            #pragma unroll 8
            for (int j = 0; j < 32; j++) {
                float2 s = base[(size_t)j * 16];
                base[(size_t)j * 16].x = c;
                c = fmaf(s.x, c, s.y);
            }
        }
    }
    grid_barrier();

    // ---- scan pass 3: re-scan with carry init, emit y ----
    {
        float2* scr = (float2*)g_v;
        bf16 (*s_yh)[16] = (bf16(*)[16])(s_raw + warp * 2048);
        bf16 (*s_yl)[16] = (bf16(*)[16])(s_raw + warp * 2048 + 1024);
        const int u = lane >> 1;
        const int p = lane & 1;
        for (int wt = bid * 8 + warp; wt < BB * 32 * 32; wt += nbk * 8) {
            const int b  = wt >> 10;
            const int hb = (wt >> 5) & 31;
            const int ck = wt & 31;
            const int h  = hb * 16 + u;
            const int ch = b * HH + h;
            float A2[8], iA[8], Apv[8];
            #pragma unroll
            for (int j = 0; j < 8; j++) {
                float Ap = Apw[h * NN + p * 8 + j];
                Apv[j] = Ap;
                float A  = -__expf(Ap);
                A2[j] = A * 1.4426950408889634f;
                iA[j] = (fabsf(A) < 1e-5f) ? 1.f : (1.f / A);
            }
            float Dp = Dpw[h];
            const float* xr = g_vcT + (size_t)h * BT + b * TT + ck * 32;
            const float* dr = g_dtT + (size_t)h * BT + b * TT + ck * 32;
            const float2* cin = scr + ((size_t)ch * 32 + ck) * 16 + p * 8;
            float s[8];
            #pragma unroll
            for (int j = 0; j < 8; j++) s[j] = cin[j].x;
            #pragma unroll 2
            for (int t4 = 0; t4 < 32; t4 += 4) {
                float4 xv = *(const float4*)(xr + t4);
                float4 dv = *(const float4*)(dr + t4);
                #pragma unroll
                for (int k = 0; k < 4; k++) {
                    float x   = ((const float*)&xv)[k];
                    float dtv = ((const float*)&dv)[k];
                    float c = dtv * x;
                    float part = 0.f;
                    #pragma unroll
                    for (int j = 0; j < 8; j++) {
                        float dA = ex2f(A2[j] * dtv);
                        float e  = iA[j] * c;
                        s[j] = fmaf(dA, s[j] + e, -e);
                        part = fmaf(Apv[j], s[j], part);
                    }
                    part += __shfl_xor_sync(0xffffffffu, part, 1);
                    if (p == 0) {
                        float y = fmaf(Dp, x, part);
                        bf16 hh_, ll_;
                        split_bf16(y, hh_, ll_);
                        s_yh[t4 + k][u] = hh_;
                        s_yl[t4 + k][u] = ll_;
                    }
                }
            }
            __syncwarp();
            // coalesced flush: lane = t row, 32 rows x 16 ch
            {
                size_t rbase = (size_t)(b * TT + ck * 32 + lane) * HH + hb * 16;
                uint4* sh = (uint4*)&s_yh[lane][0];
                uint4* sl = (uint4*)&s_yl[lane][0];
                *(uint4*)(g_yh + rbase)     = sh[0];
                *(uint4*)(g_yh + rbase + 8) = sh[1];
                *(uint4*)(g_yl + rbase)     = sl[0];
                *(uint4*)(g_yl + rbase + 8) = sl[1];
            }
            __syncwarp();
        }
    }
}

// ---------------- kernel B: gemm2 (one tile per block) ----------------
__global__ __launch_bounds__(256, 2) void kernel_b(
    const bf16* __restrict__ owh, const bf16* __restrict__ owl)
{
    __shared__ __align__(16) char s_raw[GEMM_SMEM];
    const int t = blockIdx.x;   // 256 tiles: 64 m x 4 n
    gemm_tile(s_raw, g_yh, g_yl, owh, owl, g_h, DD, HH, 1,
              (t >> 2) * 128, (t & 3) * 64);
}

// ---------------- final LN (last token) + head1(silu) + head2 ----------------
__global__ void final_kernel(const float* __restrict__ fg,
                             const float* __restrict__ fb,
                             const float* __restrict__ w1,
                             const float* __restrict__ b1,
                             const float* __restrict__ w2,
                             const float* __restrict__ b2,
                             float* __restrict__ out) {
    int b = blockIdx.x;
    int tid = threadIdx.x;
    __shared__ float red1[8], red2[8];
    __shared__ float s_ln[DD];
    __shared__ float s_h1[DD];
    const float* row = g_h + (size_t)(b * TT + (TT - 1)) * DD;
    float v = row[tid];
    float s = v;
    #pragma unroll
    for (int o = 16; o; o >>= 1) s += __shfl_xor_sync(0xffffffffu, s, o);
    if ((tid & 31) == 0) red1[tid >> 5] = s;
    __syncthreads();
    float mean = 0.f;
    #pragma unroll
    for (int i = 0; i < 8; i++) mean += red1[i];
    mean *= (1.f / 256.f);
    float c = v - mean;
    float cc = c * c;
    #pragma unroll
    for (int o = 16; o; o >>= 1) cc += __shfl_xor_sync(0xffffffffu, cc, o);
    if ((tid & 31) == 0) red2[tid >> 5] = cc;
    __syncthreads();
    float var = 0.f;
    #pragma unroll
    for (int i = 0; i < 8; i++) var += red2[i];
    var *= (1.f / 256.f);
    s_ln[tid] = c * rsqrtf(var + 1e-5f) * fg[tid] + fb[tid];
    __syncthreads();
    float acc = b1[tid];
    const float* w1r = w1 + tid * DD;
    #pragma unroll 8
    for (int k = 0; k < DD; k++) acc = fmaf(s_ln[k], w1r[k], acc);
    s_h1[tid] = silu_f(acc);
    __syncthreads();
    if (tid < 96) {
        float a2 = b2[tid];
        const float* w2r = w2 + tid * DD;
        #pragma unroll 8
        for (int k = 0; k < DD; k++) a2 = fmaf(s_h1[k], w2r[k], a2);
        out[b * 96 + tid] = a2;
    }
}

// ---------------- launcher: 14 graph nodes ----------------
extern "C" void kernel_launch(void* const* d_in, const int* in_sizes, int n_in,
                              void* d_out, int out_size) {
    const float* x      = (const float*)d_in[0];
    const float* emb_w  = (const float*)d_in[1];
    const float* emb_b  = (const float*)d_in[2];
    const float* norm_g = (const float*)d_in[3];
    const float* norm_b = (const float*)d_in[4];
    const float* in_w   = (const float*)d_in[5];
    const float* conv_w = (const float*)d_in[6];
    const float* A_p    = (const float*)d_in[7];
    const float* D_p    = (const float*)d_in[8];
    const float* dt1_w  = (const float*)d_in[9];
    const float* dt1_b  = (const float*)d_in[10];
    const float* dt2_w  = (const float*)d_in[11];
    const float* dt2_b  = (const float*)d_in[12];
    const float* out_w  = (const float*)d_in[13];
    const float* fin_g  = (const float*)d_in[14];
    const float* fin_b  = (const float*)d_in[15];
    const float* h1_w   = (const float*)d_in[16];
    const float* h1_b   = (const float*)d_in[17];
    const float* h2_w   = (const float*)d_in[18];
    const float* h2_b   = (const float*)d_in[19];
    float* out = (float*)d_out;

    bf16 *piwh, *piwl, *powh, *powl;
    cudaGetSymbolAddress((void**)&piwh, g_iwh);
    cudaGetSymbolAddress((void**)&piwl, g_iwl);
    cudaGetSymbolAddress((void**)&powh, g_owh);
    cudaGetSymbolAddress((void**)&powl, g_owl);

    emb_split_kernel<<<BT + (2 * NW) / 256, 256>>>(x, emb_w, emb_b, in_w, out_w);

    for (int l = 0; l < LL; l++) {
        kernel_a<<<GRID_A, 256>>>(
            norm_g + l * DD, norm_b + l * DD,
            piwh + (size_t)l * HH * DD, piwl + (size_t)l * HH * DD);

        kernel_mid<<<GRID_MID, 256>>>(
            conv_w + (size_t)l * HH * 3,
            A_p + (size_t)l * HH * NN, D_p + l * HH,
            dt1_w + (size_t)l * RR * HH, dt1_b + l * RR,
            dt2_w + (size_t)l * HH * RR, dt2_b + l * HH);

        kernel_b<<<256, 256>>>(
            powh + (size_t)l * DD * HH, powl + (size_t)l * DD * HH);
    }

    final_kernel<<<BB, 256>>>(fin_g, fin_b, h1_w, h1_b, h2_w, h2_b, out);
}

// round 11
// speedup vs baseline: 1.5198x; 1.0196x over previous
#include <cuda_runtime.h>
#include <cuda_bf16.h>
#include <cstdint>
#include <math.h>

typedef __nv_bfloat16 bf16;

// ---------------- problem constants ----------------
#define BB   8
#define TT   1024
#define DD   256
#define HH   512
#define NN   16
#define RR   8
#define LL   4
#define BT   (BB*TT)        // 8192
#define BTH  (BB*TT*HH)     // 4194304
#define BTD  (BB*TT*DD)     // 2097152
#define NW   (LL*HH*DD)     // 524288
#define CH   (BB*HH)        // 4096 channels

#define GRID_MID 592        // 148 SMs x 4 blocks (64-reg class)

// ---------------- scratch (static device globals; no allocation) ----------------
__device__ float g_h  [BTD];
__device__ float g_v  [BTH];        // gemm1 out; reused as scan scratch (float2 summaries)
__device__ float g_vcT[BTH];        // [h][bt]
__device__ float g_dtT[BTH];        // [h][bt]
__device__ bf16 g_lnh[BTD], g_lnl[BTD];
__device__ bf16 g_yh [BTH], g_yl [BTH];   // [bt][h]
__device__ bf16 g_iwh[NW],  g_iwl[NW];
__device__ bf16 g_owh[NW],  g_owl[NW];

// ---------------- grid-wide spin barrier (used by kernel_mid only) ----------------
__device__ unsigned int g_bar_cnt;
__device__ unsigned int g_bar_gen;

__device__ __forceinline__ void grid_barrier() {
    __syncthreads();
    if (threadIdx.x == 0) {
        __threadfence();
        unsigned int gen = atomicAdd(&g_bar_gen, 0u);
        unsigned int arrived = atomicAdd(&g_bar_cnt, 1u);
        if (arrived == gridDim.x - 1) {
            g_bar_cnt = 0;
            __threadfence();
            atomicAdd(&g_bar_gen, 1u);
        } else {
            while (atomicAdd(&g_bar_gen, 0u) == gen) __nanosleep(128);
        }
        __threadfence();
    }
    __syncthreads();
}

// ---------------- helpers ----------------
__device__ __forceinline__ float silu_f(float x) {
    return x / (1.f + __expf(-x));
}

__device__ __forceinline__ float ex2f(float x) {
    float r;
    asm("ex2.approx.ftz.f32 %0, %1;" : "=f"(r) : "f"(x));
    return r;
}

__device__ __forceinline__ void split_bf16(float v, bf16& h, bf16& l) {
    h = __float2bfloat16(v);
    l = __float2bfloat16(v - __bfloat162float(h));
}

__device__ __forceinline__ unsigned int pk2(bf16 a, bf16 b) {
    return (unsigned int)__bfloat16_as_ushort(a) |
           ((unsigned int)__bfloat16_as_ushort(b) << 16);
}

__device__ __forceinline__ void ldsm4(unsigned int r[4], const void* p) {
    unsigned int a = (unsigned int)__cvta_generic_to_shared(p);
    asm volatile("ldmatrix.sync.aligned.m8n8.x4.shared.b16 {%0,%1,%2,%3}, [%4];"
                 : "=r"(r[0]), "=r"(r[1]), "=r"(r[2]), "=r"(r[3]) : "r"(a));
}

__device__ __forceinline__ void mma_bf16(float c[4], const unsigned int a[4],
                                         unsigned int b0, unsigned int b1) {
    asm volatile(
        "mma.sync.aligned.m16n8k16.row.col.f32.bf16.bf16.f32 "
        "{%0,%1,%2,%3},{%4,%5,%6,%7},{%8,%9},{%0,%1,%2,%3};"
        : "+f"(c[0]), "+f"(c[1]), "+f"(c[2]), "+f"(c[3])
        : "r"(a[0]), "r"(a[1]), "r"(a[2]), "r"(a[3]), "r"(b0), "r"(b1));
}

__device__ __forceinline__ void cp16(void* smem, const void* gmem) {
    unsigned int s = (unsigned int)__cvta_generic_to_shared(smem);
    asm volatile("cp.async.cg.shared.global [%0], [%1], 16;" :: "r"(s), "l"(gmem));
}
#define CP_COMMIT()  asm volatile("cp.async.commit_group;")
#define CP_WAIT(n)   asm volatile("cp.async.wait_group %0;" :: "n"(n))

// ---------------- gemm tile: 2-stage cp.async pipeline ----------------
// dynamic smem: 2 stages x 30720 B = 61440 B
#define PADK 40
#define STAGE_BYTES 30720
#define GEMM_SMEM_DYN (2 * STAGE_BYTES)

__device__ void gemm_tile_pipe(char* s_raw,
    const bf16* __restrict__ Ah, const bf16* __restrict__ Al,
    const bf16* __restrict__ Wh, const bf16* __restrict__ Wl,
    float* __restrict__ C, int N, int K, int accumulate, int bm, int bn)
{
    const int tid  = threadIdx.x;
    const int lane = tid & 31;
    const int wid  = tid >> 5;
    const int wm   = (wid & 3) * 32;
    const int wn   = (wid >> 2) * 32;

    float acc[2][4][4];
    #pragma unroll
    for (int a = 0; a < 2; a++)
        #pragma unroll
        for (int b = 0; b < 4; b++)
            #pragma unroll
            for (int c = 0; c < 4; c++) acc[a][b][c] = 0.f;

    const int lrow = tid >> 2;
    const int lcol = (tid & 3) * 8;

    const int a_row = lane & 15;
    const int a_col = (lane >> 4) << 3;
    const int bq    = lane >> 3;
    const int b_row = (lane & 7) + ((bq >> 1) << 3);
    const int b_col = (bq & 1) << 3;

    const bf16* pAh0 = Ah + (size_t)(bm + lrow) * K + lcol;
    const bf16* pAh1 = pAh0 + (size_t)64 * K;
    const bf16* pAl0 = Al + (size_t)(bm + lrow) * K + lcol;
    const bf16* pAl1 = pAl0 + (size_t)64 * K;
    const bf16* pWh  = Wh + (size_t)(bn + lrow) * K + lcol;
    const bf16* pWl  = Wl + (size_t)(bn + lrow) * K + lcol;

    const int niter = K >> 5;

    // stage loader
    auto load_stage = [&](int stage, int kt) {
        char* sb = s_raw + stage * STAGE_BYTES;
        bf16 (*sAh)[PADK] = (bf16(*)[PADK])(sb);
        bf16 (*sAl)[PADK] = (bf16(*)[PADK])(sb + 10240);
        bf16 (*sWh)[PADK] = (bf16(*)[PADK])(sb + 20480);
        bf16 (*sWl)[PADK] = (bf16(*)[PADK])(sb + 25600);
        cp16(&sAh[lrow     ][lcol], pAh0 + kt);
        cp16(&sAh[lrow + 64][lcol], pAh1 + kt);
        cp16(&sAl[lrow     ][lcol], pAl0 + kt);
        cp16(&sAl[lrow + 64][lcol], pAl1 + kt);
        cp16(&sWh[lrow][lcol], pWh + kt);
        cp16(&sWl[lrow][lcol], pWl + kt);
    };

    load_stage(0, 0);
    CP_COMMIT();

    for (int it = 0; it < niter; it++) {
        const int cur = it & 1;
        if (it + 1 < niter) {
            load_stage(cur ^ 1, (it + 1) << 5);
            CP_COMMIT();
            CP_WAIT(1);
        } else {
            CP_WAIT(0);
        }
        __syncthreads();

        char* sb = s_raw + cur * STAGE_BYTES;
        bf16 (*sAh)[PADK] = (bf16(*)[PADK])(sb);
        bf16 (*sAl)[PADK] = (bf16(*)[PADK])(sb + 10240);
        bf16 (*sWh)[PADK] = (bf16(*)[PADK])(sb + 20480);
        bf16 (*sWl)[PADK] = (bf16(*)[PADK])(sb + 25600);

        #pragma unroll
        for (int ks = 0; ks < 2; ks++) {
            const int k0 = ks * 16;
            unsigned int ah[2][4], al[2][4];
            #pragma unroll
            for (int mt = 0; mt < 2; mt++) {
                ldsm4(ah[mt], &sAh[wm + mt * 16 + a_row][k0 + a_col]);
                ldsm4(al[mt], &sAl[wm + mt * 16 + a_row][k0 + a_col]);
            }
            unsigned int bh[2][4], bl[2][4];
            #pragma unroll
            for (int nb = 0; nb < 2; nb++) {
                ldsm4(bh[nb], &sWh[wn + nb * 16 + b_row][k0 + b_col]);
                ldsm4(bl[nb], &sWl[wn + nb * 16 + b_row][k0 + b_col]);
            }
            #pragma unroll
            for (int mt = 0; mt < 2; mt++) {
                #pragma unroll
                for (int nt = 0; nt < 4; nt++) {
                    const int nb = nt >> 1, hf = (nt & 1) * 2;
                    mma_bf16(acc[mt][nt], ah[mt], bh[nb][hf], bh[nb][hf + 1]);
                    mma_bf16(acc[mt][nt], ah[mt], bl[nb][hf], bl[nb][hf + 1]);
                    mma_bf16(acc[mt][nt], al[mt], bh[nb][hf], bh[nb][hf + 1]);
                }
            }
        }
        __syncthreads();
    }

    const int cg = lane >> 2;
    const int ct = (lane & 3) * 2;
    #pragma unroll
    for (int mt = 0; mt < 2; mt++) {
        #pragma unroll
        for (int nt = 0; nt < 4; nt++) {
            int r0 = bm + wm + mt * 16 + cg;
            int c0 = bn + wn + nt * 8 + ct;
            float2* p0 = (float2*)(C + (size_t)r0 * N + c0);
            float2* p1 = (float2*)(C + (size_t)(r0 + 8) * N + c0);
            float2 v0 = make_float2(acc[mt][nt][0], acc[mt][nt][1]);
            float2 v1 = make_float2(acc[mt][nt][2], acc[mt][nt][3]);
            if (accumulate) {
                float2 o0 = *p0, o1 = *p1;
                v0.x += o0.x; v0.y += o0.y;
                v1.x += o1.x; v1.y += o1.y;
            }
            *p0 = v0; *p1 = v1;
        }
    }
}

// ---------------- merged embed + pos-encoding + weight split ----------------
__global__ void emb_split_kernel(const float* __restrict__ x,
                                 const float* __restrict__ emb_w,
                                 const float* __restrict__ emb_b,
                                 const float* __restrict__ in_w,
                                 const float* __restrict__ out_w) {
    if (blockIdx.x < BT) {
        int bt = blockIdx.x;
        int d  = threadIdx.x;
        __shared__ float sx[32];
        if (d < 32) sx[d] = x[bt * 32 + d];
        __syncthreads();
        float acc = emb_b[d];
        const float* w = emb_w + d * 32;
        #pragma unroll
        for (int i = 0; i < 32; i++) acc = fmaf(sx[i], w[i], acc);
        int t = bt & (TT - 1);
        int k2 = d & ~1;
        float div = __expf((float)k2 * (-9.210340371976184f / 256.0f));
        float ang = (float)t * div;
        acc += (d & 1) ? cosf(ang) : sinf(ang);
        g_h[bt * DD + d] = acc;
    } else {
        int i = (blockIdx.x - BT) * 256 + threadIdx.x;
        if (i < NW) {
            split_bf16(in_w[i], g_iwh[i], g_iwl[i]);
        } else {
            int j = i - NW;
            split_bf16(out_w[j], g_owh[j], g_owl[j]);
        }
    }
}

// ---------------- LN kernel (warp per row) ----------------
__global__ __launch_bounds__(256) void ln_kernel(
    const float* __restrict__ ng, const float* __restrict__ nb_)
{
    const int lane = threadIdx.x & 31;
    const int row  = blockIdx.x * 8 + (threadIdx.x >> 5);
    const float* p = g_h + (size_t)row * DD + lane * 8;
    float4 a = *(const float4*)p;
    float4 c = *(const float4*)(p + 4);
    float v[8] = {a.x, a.y, a.z, a.w, c.x, c.y, c.z, c.w};
    float s = 0.f;
    #pragma unroll
    for (int j = 0; j < 8; j++) s += v[j];
    #pragma unroll
    for (int o = 16; o; o >>= 1) s += __shfl_xor_sync(0xffffffffu, s, o);
    float mean = s * (1.f / 256.f);
    float vv = 0.f;
    #pragma unroll
    for (int j = 0; j < 8; j++) { float d0 = v[j] - mean; vv += d0 * d0; }
    #pragma unroll
    for (int o = 16; o; o >>= 1) vv += __shfl_xor_sync(0xffffffffu, vv, o);
    float rstd = rsqrtf(vv * (1.f / 256.f) + 1e-5f);
    float4 gg0 = *(const float4*)(ng + lane * 8);
    float4 gg1 = *(const float4*)(ng + lane * 8 + 4);
    float4 bb0 = *(const float4*)(nb_ + lane * 8);
    float4 bb1 = *(const float4*)(nb_ + lane * 8 + 4);
    float gv[8] = {gg0.x, gg0.y, gg0.z, gg0.w, gg1.x, gg1.y, gg1.z, gg1.w};
    float bv[8] = {bb0.x, bb0.y, bb0.z, bb0.w, bb1.x, bb1.y, bb1.z, bb1.w};
    bf16 oh[8], ol[8];
    #pragma unroll
    for (int j = 0; j < 8; j++) {
        float o = (v[j] - mean) * rstd * gv[j] + bv[j];
        split_bf16(o, oh[j], ol[j]);
    }
    uint4 uh, ul;
    uh.x = pk2(oh[0], oh[1]); uh.y = pk2(oh[2], oh[3]);
    uh.z = pk2(oh[4], oh[5]); uh.w = pk2(oh[6], oh[7]);
    ul.x = pk2(ol[0], ol[1]); ul.y = pk2(ol[2], ol[3]);
    ul.z = pk2(ol[4], ol[5]); ul.w = pk2(ol[6], ol[7]);
    *(uint4*)(g_lnh + (size_t)row * DD + lane * 8) = uh;
    *(uint4*)(g_lnl + (size_t)row * DD + lane * 8) = ul;
}

// ---------------- gemm1: 512 blocks, 1 tile each ----------------
__global__ __launch_bounds__(256, 2) void kernel_g1(
    const bf16* __restrict__ iwh, const bf16* __restrict__ iwl)
{
    extern __shared__ __align__(16) char s_dyn[];
    const int t = blockIdx.x;   // 512 tiles: 64 m x 8 n
    gemm_tile_pipe(s_dyn, g_lnh, g_lnl, iwh, iwl, g_v, HH, DD, 0,
                   (t >> 3) * 128, (t & 7) * 64);
}

// ---------------- gemm2: 256 blocks, 1 tile each ----------------
__global__ __launch_bounds__(256, 2) void kernel_b(
    const bf16* __restrict__ owh, const bf16* __restrict__ owl)
{
    extern __shared__ __align__(16) char s_dyn[];
    const int t = blockIdx.x;   // 256 tiles: 64 m x 4 n
    gemm_tile_pipe(s_dyn, g_yh, g_yl, owh, owl, g_h, DD, HH, 1,
                   (t >> 2) * 128, (t & 3) * 64);
}

// ---------------- kernel MID: conv + dt + scan (64-reg class, 4 blk/SM) ----------------
#define MID_SMEM 16384
__global__ __launch_bounds__(256, 4) void kernel_mid(
    const float* __restrict__ cw,
    const float* __restrict__ Apw, const float* __restrict__ Dpw,
    const float* __restrict__ w1,  const float* __restrict__ b1,
    const float* __restrict__ w2,  const float* __restrict__ b2)
{
    __shared__ __align__(16) char s_raw[MID_SMEM];
    const int bid = blockIdx.x;
    const int nbk = gridDim.x;
    const int tid = threadIdx.x;
    const int lane = tid & 31;
    const int warp = tid >> 5;

    // ---- conv(k=3)+silu+transpose: g_v[bt][h] -> g_vcT[h][bt] (4096 tasks) ----
    {
        float (*tile)[33] = (float(*)[33])(s_raw);
        for (int task = bid; task < BB * 16 * 32; task += nbk) {
            const int b  = task >> 9;
            const int h0 = ((task >> 5) & 15) * 32;
            const int t0 = (task & 31) * 32;
            #pragma unroll
            for (int i = tid; i < 34 * 32; i += 256) {
                int tt = i >> 5;
                int hh = i & 31;
                int t  = t0 + tt - 1;
                float v = 0.f;
                if (t >= 0 && t < TT)
                    v = g_v[((size_t)b * TT + t) * HH + h0 + hh];
                tile[tt][hh] = v;
            }
            __syncthreads();
            const int tl = tid & 31;
            const int hq = tid >> 5;
            #pragma unroll
            for (int j = 0; j < 4; j++) {
                int hh = hq * 4 + j;
                int h  = h0 + hh;
                float w0 = cw[h * 3 + 0], w1v = cw[h * 3 + 1], w2v = cw[h * 3 + 2];
                float acc = tile[tl][hh] * w0;
                acc = fmaf(tile[tl + 1][hh], w1v, acc);
                acc = fmaf(tile[tl + 2][hh], w2v, acc);
                g_vcT[(size_t)h * BT + b * TT + t0 + tl] = silu_f(acc);
            }
            __syncthreads();
        }
    }
    grid_barrier();

    // ---- dt1 + dt2 fused -> g_dtT[h][bt] (128 tasks of 64 bt) ----
    {
        float (*red)[64][9] = (float(*)[64][9])(s_raw);          // [3][64][9]
        float (*dtrs)[9]    = (float(*)[9])(s_raw + 6912);
        const int btl = tid & 63;
        const int q   = tid >> 6;       // 0..3
        for (int task = bid; task < BT / 64; task += nbk) {
            const int bt0 = task * 64;
            float acc[RR];
            #pragma unroll
            for (int r = 0; r < RR; r++) acc[r] = 0.f;
            const int hbase = q * 128;
            #pragma unroll 4
            for (int hh = 0; hh < 128; hh++) {
                int h = hbase + hh;
                float v = g_vcT[(size_t)h * BT + bt0 + btl];
                #pragma unroll
                for (int r = 0; r < RR; r++) acc[r] = fmaf(v, w1[r * HH + h], acc[r]);
            }
            if (q > 0) {
                #pragma unroll
                for (int r = 0; r < RR; r++) red[q - 1][btl][r] = acc[r];
            }
            __syncthreads();
            if (q == 0) {
                #pragma unroll
                for (int r = 0; r < RR; r++)
                    dtrs[btl][r] = fmaxf(acc[r] + red[0][btl][r] + red[1][btl][r]
                                         + red[2][btl][r] + b1[r], 0.f);
            }
            __syncthreads();
            for (int hh = q; hh < HH; hh += 4) {
                float wreg[RR];
                #pragma unroll
                for (int r = 0; r < RR; r++) wreg[r] = w2[hh * RR + r];
                float a2 = b2[hh];
                #pragma unroll
                for (int r = 0; r < RR; r++) a2 = fmaf(dtrs[btl][r], wreg[r], a2);
                float sp = (a2 > 15.f) ? a2 : log1pf(__expf(a2));
                g_dtT[(size_t)hh * BT + bt0 + btl] = sp;
            }
            __syncthreads();
        }
    }
    grid_barrier();

    // ---- scan pass 1: chunk summaries (P, e) — 2 lanes/channel, 8 n/lane ----
    {
        float2* scr = (float2*)g_v;
        const int u = lane >> 1;    // channel in warp
        const int p = lane & 1;     // n half
        for (int wt = bid * 8 + warp; wt < BB * 32 * 32; wt += nbk * 8) {
            const int b  = wt >> 10;
            const int hb = (wt >> 5) & 31;
            const int ck = wt & 31;
            const int h  = hb * 16 + u;
            const int ch = b * HH + h;
            float A2[8], iA[8];
            #pragma unroll
            for (int j = 0; j < 8; j++) {
                float Ap = Apw[h * NN + p * 8 + j];
                float A  = -__expf(Ap);
                A2[j] = A * 1.4426950408889634f;
                iA[j] = (fabsf(A) < 1e-5f) ? 1.f : (1.f / A);
            }
            const float* xr = g_vcT + (size_t)h * BT + b * TT + ck * 32;
            const float* dr = g_dtT + (size_t)h * BT + b * TT + ck * 32;
            float s[8], P[8];
            #pragma unroll
            for (int j = 0; j < 8; j++) { s[j] = 0.f; P[j] = 1.f; }
            #pragma unroll 2
            for (int t4 = 0; t4 < 32; t4 += 4) {
                float4 xv = *(const float4*)(xr + t4);
                float4 dv = *(const float4*)(dr + t4);
                #pragma unroll
                for (int k = 0; k < 4; k++) {
                    float x   = ((const float*)&xv)[k];
                    float dtv = ((const float*)&dv)[k];
                    float c = dtv * x;
                    #pragma unroll
                    for (int j = 0; j < 8; j++) {
                        float dA = ex2f(A2[j] * dtv);
                        float e  = iA[j] * c;
                        s[j] = fmaf(dA, s[j] + e, -e);
                        P[j] *= dA;
                    }
                }
            }
            float2* out = scr + ((size_t)ch * 32 + ck) * 16 + p * 8;
            #pragma unroll
            for (int j = 0; j < 8; j++) out[j] = make_float2(P[j], s[j]);
        }
    }
    grid_barrier();

    // ---- scan pass 2: serial carry per (ch, n); stored in-place (.x) ----
    {
        float2* scr = (float2*)g_v;
        for (int i = bid * 256 + tid; i < CH * NN; i += nbk * 256) {
            float2* base = scr + ((size_t)(i >> 4) * 32) * 16 + (i & 15);
            float c = 0.f;
            #pragma unroll 8
            for (int j = 0; j < 32; j++) {
                float2 s = base[(size_t)j * 16];
                base[(size_t)j * 16].x = c;
                c = fmaf(s.x, c, s.y);
            }
        }
    }
    grid_barrier();

    // ---- scan pass 3: re-scan with carry init, emit y ----
    {
        float2* scr = (float2*)g_v;
        bf16 (*s_yh)[16] = (bf16(*)[16])(s_raw + warp * 2048);
        bf16 (*s_yl)[16] = (bf16(*)[16])(s_raw + warp * 2048 + 1024);
        const int u = lane >> 1;
        const int p = lane & 1;
        for (int wt = bid * 8 + warp; wt < BB * 32 * 32; wt += nbk * 8) {
            const int b  = wt >> 10;
            const int hb = (wt >> 5) & 31;
            const int ck = wt & 31;
            const int h  = hb * 16 + u;
            const int ch = b * HH + h;
            float A2[8], iA[8], Apv[8];
            #pragma unroll
            for (int j = 0; j < 8; j++) {
                float Ap = Apw[h * NN + p * 8 + j];
                Apv[j] = Ap;
                float A  = -__expf(Ap);
                A2[j] = A * 1.4426950408889634f;
                iA[j] = (fabsf(A) < 1e-5f) ? 1.f : (1.f / A);
            }
            float Dp = Dpw[h];
            const float* xr = g_vcT + (size_t)h * BT + b * TT + ck * 32;
            const float* dr = g_dtT + (size_t)h * BT + b * TT + ck * 32;
            const float2* cin = scr + ((size_t)ch * 32 + ck) * 16 + p * 8;
            float s[8];
            #pragma unroll
            for (int j = 0; j < 8; j++) s[j] = cin[j].x;
            #pragma unroll 2
            for (int t4 = 0; t4 < 32; t4 += 4) {
                float4 xv = *(const float4*)(xr + t4);
                float4 dv = *(const float4*)(dr + t4);
                #pragma unroll
                for (int k = 0; k < 4; k++) {
                    float x   = ((const float*)&xv)[k];
                    float dtv = ((const float*)&dv)[k];
                    float c = dtv * x;
                    float part = 0.f;
                    #pragma unroll
                    for (int j = 0; j < 8; j++) {
                        float dA = ex2f(A2[j] * dtv);
                        float e  = iA[j] * c;
                        s[j] = fmaf(dA, s[j] + e, -e);
                        part = fmaf(Apv[j], s[j], part);
                    }
                    part += __shfl_xor_sync(0xffffffffu, part, 1);
                    if (p == 0) {
                        float y = fmaf(Dp, x, part);
                        bf16 hh_, ll_;
                        split_bf16(y, hh_, ll_);
                        s_yh[t4 + k][u] = hh_;
                        s_yl[t4 + k][u] = ll_;
                    }
                }
            }
            __syncwarp();
            {
                size_t rbase = (size_t)(b * TT + ck * 32 + lane) * HH + hb * 16;
                uint4* sh = (uint4*)&s_yh[lane][0];
                uint4* sl = (uint4*)&s_yl[lane][0];
                *(uint4*)(g_yh + rbase)     = sh[0];
                *(uint4*)(g_yh + rbase + 8) = sh[1];
                *(uint4*)(g_yl + rbase)     = sl[0];
                *(uint4*)(g_yl + rbase + 8) = sl[1];
            }
            __syncwarp();
        }
    }
}

// ---------------- final LN (last token) + head1(silu) + head2 ----------------
__global__ void final_kernel(const float* __restrict__ fg,
                             const float* __restrict__ fb,
                             const float* __restrict__ w1,
                             const float* __restrict__ b1,
                             const float* __restrict__ w2,
                             const float* __restrict__ b2,
                             float* __restrict__ out) {
    int b = blockIdx.x;
    int tid = threadIdx.x;
    __shared__ float red1[8], red2[8];
    __shared__ float s_ln[DD];
    __shared__ float s_h1[DD];
    const float* row = g_h + (size_t)(b * TT + (TT - 1)) * DD;
    float v = row[tid];
    float s = v;
    #pragma unroll
    for (int o = 16; o; o >>= 1) s += __shfl_xor_sync(0xffffffffu, s, o);
    if ((tid & 31) == 0) red1[tid >> 5] = s;
    __syncthreads();
    float mean = 0.f;
    #pragma unroll
    for (int i = 0; i < 8; i++) mean += red1[i];
    mean *= (1.f / 256.f);
    float c = v - mean;
    float cc = c * c;
    #pragma unroll
    for (int o = 16; o; o >>= 1) cc += __shfl_xor_sync(0xffffffffu, cc, o);
    if ((tid & 31) == 0) red2[tid >> 5] = cc;
    __syncthreads();
    float var = 0.f;
    #pragma unroll
    for (int i = 0; i < 8; i++) var += red2[i];
    var *= (1.f / 256.f);
    s_ln[tid] = c * rsqrtf(var + 1e-5f) * fg[tid] + fb[tid];
    __syncthreads();
    float acc = b1[tid];
    const float* w1r = w1 + tid * DD;
    #pragma unroll 8
    for (int k = 0; k < DD; k++) acc = fmaf(s_ln[k], w1r[k], acc);
    s_h1[tid] = silu_f(acc);
    __syncthreads();
    if (tid < 96) {
        float a2 = b2[tid];
        const float* w2r = w2 + tid * DD;
        #pragma unroll 8
        for (int k = 0; k < DD; k++) a2 = fmaf(s_h1[k], w2r[k], a2);
        out[b * 96 + tid] = a2;
    }
}

// ---------------- launcher: 18 graph nodes ----------------
extern "C" void kernel_launch(void* const* d_in, const int* in_sizes, int n_in,
                              void* d_out, int out_size) {
    const float* x      = (const float*)d_in[0];
    const float* emb_w  = (const float*)d_in[1];
    const float* emb_b  = (const float*)d_in[2];
    const float* norm_g = (const float*)d_in[3];
    const float* norm_b = (const float*)d_in[4];
    const float* in_w   = (const float*)d_in[5];
    const float* conv_w = (const float*)d_in[6];
    const float* A_p    = (const float*)d_in[7];
    const float* D_p    = (const float*)d_in[8];
    const float* dt1_w  = (const float*)d_in[9];
    const float* dt1_b  = (const float*)d_in[10];
    const float* dt2_w  = (const float*)d_in[11];
    const float* dt2_b  = (const float*)d_in[12];
    const float* out_w  = (const float*)d_in[13];
    const float* fin_g  = (const float*)d_in[14];
    const float* fin_b  = (const float*)d_in[15];
    const float* h1_w   = (const float*)d_in[16];
    const float* h1_b   = (const float*)d_in[17];
    const float* h2_w   = (const float*)d_in[18];
    const float* h2_b   = (const float*)d_in[19];
    float* out = (float*)d_out;

    bf16 *piwh, *piwl, *powh, *powl;
    cudaGetSymbolAddress((void**)&piwh, g_iwh);
    cudaGetSymbolAddress((void**)&piwl, g_iwl);
    cudaGetSymbolAddress((void**)&powh, g_owh);
    cudaGetSymbolAddress((void**)&powl, g_owl);

    cudaFuncSetAttribute(kernel_g1, cudaFuncAttributeMaxDynamicSharedMemorySize,
                         GEMM_SMEM_DYN);
    cudaFuncSetAttribute(kernel_b, cudaFuncAttributeMaxDynamicSharedMemorySize,
                         GEMM_SMEM_DYN);

    emb_split_kernel<<<BT + (2 * NW) / 256, 256>>>(x, emb_w, emb_b, in_w, out_w);

    for (int l = 0; l < LL; l++) {
        ln_kernel<<<BT / 8, 256>>>(norm_g + l * DD, norm_b + l * DD);

        kernel_g1<<<512, 256, GEMM_SMEM_DYN>>>(
            piwh + (size_t)l * HH * DD, piwl + (size_t)l * HH * DD);

        kernel_mid<<<GRID_MID, 256>>>(
            conv_w + (size_t)l * HH * 3,
            A_p + (size_t)l * HH * NN, D_p + l * HH,
            dt1_w + (size_t)l * RR * HH, dt1_b + l * RR,
            dt2_w + (size_t)l * HH * RR, dt2_b + l * HH);

        kernel_b<<<256, 256, GEMM_SMEM_DYN>>>(
            powh + (size_t)l * DD * HH, powl + (size_t)l * DD * HH);
    }

    final_kernel<<<BB, 256>>>(fin_g, fin_b, h1_w, h1_b, h2_w, h2_b, out);
}

// round 12
// speedup vs baseline: 1.8351x; 1.2075x over previous
#include <cuda_runtime.h>
#include <cuda_bf16.h>
#include <cstdint>
#include <math.h>

typedef __nv_bfloat16 bf16;

// ---------------- problem constants ----------------
#define BB   8
#define TT   1024
#define DD   256
#define HH   512
#define NN   16
#define RR   8
#define LL   4
#define BT   (BB*TT)        // 8192
#define BTH  (BB*TT*HH)     // 4194304
#define BTD  (BB*TT*DD)     // 2097152
#define NW   (LL*HH*DD)     // 524288
#define CH   (BB*HH)        // 4096 channels

#define GRID_MID 592        // 148 SMs x 4 blocks (64-reg class)

// ---------------- scratch (static device globals; no allocation) ----------------
__device__ float g_h  [BTD];
__device__ float g_v  [BTH];        // gemm1 out; reused as scan scratch (float2 summaries)
__device__ float g_vcT[BTH];        // [h][bt]
__device__ float g_dtT[BTH];        // [h][bt]
__device__ bf16 g_lnh[BTD], g_lnl[BTD];
__device__ bf16 g_yh [BTH], g_yl [BTH];   // [bt][h]
__device__ bf16 g_iwh[NW],  g_iwl[NW];
__device__ bf16 g_owh[NW],  g_owl[NW];

// ---------------- grid-wide spin barrier (used by kernel_mid only) ----------------
__device__ unsigned int g_bar_cnt;
__device__ unsigned int g_bar_gen;

__device__ __forceinline__ void grid_barrier() {
    __syncthreads();
    if (threadIdx.x == 0) {
        __threadfence();
        unsigned int gen = atomicAdd(&g_bar_gen, 0u);
        unsigned int arrived = atomicAdd(&g_bar_cnt, 1u);
        if (arrived == gridDim.x - 1) {
            g_bar_cnt = 0;
            __threadfence();
            atomicAdd(&g_bar_gen, 1u);
        } else {
            while (atomicAdd(&g_bar_gen, 0u) == gen) __nanosleep(128);
        }
        __threadfence();
    }
    __syncthreads();
}

// ---------------- helpers ----------------
__device__ __forceinline__ float silu_f(float x) {
    return x / (1.f + __expf(-x));
}

__device__ __forceinline__ float ex2f(float x) {
    float r;
    asm("ex2.approx.ftz.f32 %0, %1;" : "=f"(r) : "f"(x));
    return r;
}

__device__ __forceinline__ void split_bf16(float v, bf16& h, bf16& l) {
    h = __float2bfloat16(v);
    l = __float2bfloat16(v - __bfloat162float(h));
}

__device__ __forceinline__ unsigned int pk2(bf16 a, bf16 b) {
    return (unsigned int)__bfloat16_as_ushort(a) |
           ((unsigned int)__bfloat16_as_ushort(b) << 16);
}

__device__ __forceinline__ void ldsm4(unsigned int r[4], const void* p) {
    unsigned int a = (unsigned int)__cvta_generic_to_shared(p);
    asm volatile("ldmatrix.sync.aligned.m8n8.x4.shared.b16 {%0,%1,%2,%3}, [%4];"
                 : "=r"(r[0]), "=r"(r[1]), "=r"(r[2]), "=r"(r[3]) : "r"(a));
}

__device__ __forceinline__ void mma_bf16(float c[4], const unsigned int a[4],
                                         unsigned int b0, unsigned int b1) {
    asm volatile(
        "mma.sync.aligned.m16n8k16.row.col.f32.bf16.bf16.f32 "
        "{%0,%1,%2,%3},{%4,%5,%6,%7},{%8,%9},{%0,%1,%2,%3};"
        : "+f"(c[0]), "+f"(c[1]), "+f"(c[2]), "+f"(c[3])
        : "r"(a[0]), "r"(a[1]), "r"(a[2]), "r"(a[3]), "r"(b0), "r"(b1));
}

__device__ __forceinline__ void cp16(void* smem, const void* gmem) {
    unsigned int s = (unsigned int)__cvta_generic_to_shared(smem);
    asm volatile("cp.async.cg.shared.global [%0], [%1], 16;" :: "r"(s), "l"(gmem));
}
#define CP_COMMIT()  asm volatile("cp.async.commit_group;")
#define CP_WAIT(n)   asm volatile("cp.async.wait_group %0;" :: "n"(n))

// ---------------- gemm tile: 2-stage cp.async pipeline ----------------
#define PADK 40
#define STAGE_BYTES 30720
#define GEMM_SMEM_DYN (2 * STAGE_BYTES)

__device__ void gemm_tile_pipe(char* s_raw,
    const bf16* __restrict__ Ah, const bf16* __restrict__ Al,
    const bf16* __restrict__ Wh, const bf16* __restrict__ Wl,
    float* __restrict__ C, int N, int K, int accumulate, int bm, int bn)
{
    const int tid  = threadIdx.x;
    const int lane = tid & 31;
    const int wid  = tid >> 5;
    const int wm   = (wid & 3) * 32;
    const int wn   = (wid >> 2) * 32;

    float acc[2][4][4];
    #pragma unroll
    for (int a = 0; a < 2; a++)
        #pragma unroll
        for (int b = 0; b < 4; b++)
            #pragma unroll
            for (int c = 0; c < 4; c++) acc[a][b][c] = 0.f;

    const int lrow = tid >> 2;
    const int lcol = (tid & 3) * 8;

    const int a_row = lane & 15;
    const int a_col = (lane >> 4) << 3;
    const int bq    = lane >> 3;
    const int b_row = (lane & 7) + ((bq >> 1) << 3);
    const int b_col = (bq & 1) << 3;

    const bf16* pAh0 = Ah + (size_t)(bm + lrow) * K + lcol;
    const bf16* pAh1 = pAh0 + (size_t)64 * K;
    const bf16* pAl0 = Al + (size_t)(bm + lrow) * K + lcol;
    const bf16* pAl1 = pAl0 + (size_t)64 * K;
    const bf16* pWh  = Wh + (size_t)(bn + lrow) * K + lcol;
    const bf16* pWl  = Wl + (size_t)(bn + lrow) * K + lcol;

    const int niter = K >> 5;

    auto load_stage = [&](int stage, int kt) {
        char* sb = s_raw + stage * STAGE_BYTES;
        bf16 (*sAh)[PADK] = (bf16(*)[PADK])(sb);
        bf16 (*sAl)[PADK] = (bf16(*)[PADK])(sb + 10240);
        bf16 (*sWh)[PADK] = (bf16(*)[PADK])(sb + 20480);
        bf16 (*sWl)[PADK] = (bf16(*)[PADK])(sb + 25600);
        cp16(&sAh[lrow     ][lcol], pAh0 + kt);
        cp16(&sAh[lrow + 64][lcol], pAh1 + kt);
        cp16(&sAl[lrow     ][lcol], pAl0 + kt);
        cp16(&sAl[lrow + 64][lcol], pAl1 + kt);
        cp16(&sWh[lrow][lcol], pWh + kt);
        cp16(&sWl[lrow][lcol], pWl + kt);
    };

    load_stage(0, 0);
    CP_COMMIT();

    for (int it = 0; it < niter; it++) {
        const int cur = it & 1;
        if (it + 1 < niter) {
            load_stage(cur ^ 1, (it + 1) << 5);
            CP_COMMIT();
            CP_WAIT(1);
        } else {
            CP_WAIT(0);
        }
        __syncthreads();

        char* sb = s_raw + cur * STAGE_BYTES;
        bf16 (*sAh)[PADK] = (bf16(*)[PADK])(sb);
        bf16 (*sAl)[PADK] = (bf16(*)[PADK])(sb + 10240);
        bf16 (*sWh)[PADK] = (bf16(*)[PADK])(sb + 20480);
        bf16 (*sWl)[PADK] = (bf16(*)[PADK])(sb + 25600);

        #pragma unroll
        for (int ks = 0; ks < 2; ks++) {
            const int k0 = ks * 16;
            unsigned int ah[2][4], al[2][4];
            #pragma unroll
            for (int mt = 0; mt < 2; mt++) {
                ldsm4(ah[mt], &sAh[wm + mt * 16 + a_row][k0 + a_col]);
                ldsm4(al[mt], &sAl[wm + mt * 16 + a_row][k0 + a_col]);
            }
            unsigned int bh[2][4], bl[2][4];
            #pragma unroll
            for (int nb = 0; nb < 2; nb++) {
                ldsm4(bh[nb], &sWh[wn + nb * 16 + b_row][k0 + b_col]);
                ldsm4(bl[nb], &sWl[wn + nb * 16 + b_row][k0 + b_col]);
            }
            #pragma unroll
            for (int mt = 0; mt < 2; mt++) {
                #pragma unroll
                for (int nt = 0; nt < 4; nt++) {
                    const int nb = nt >> 1, hf = (nt & 1) * 2;
                    mma_bf16(acc[mt][nt], ah[mt], bh[nb][hf], bh[nb][hf + 1]);
                    mma_bf16(acc[mt][nt], ah[mt], bl[nb][hf], bl[nb][hf + 1]);
                    mma_bf16(acc[mt][nt], al[mt], bh[nb][hf], bh[nb][hf + 1]);
                }
            }
        }
        __syncthreads();
    }

    const int cg = lane >> 2;
    const int ct = (lane & 3) * 2;
    #pragma unroll
    for (int mt = 0; mt < 2; mt++) {
        #pragma unroll
        for (int nt = 0; nt < 4; nt++) {
            int r0 = bm + wm + mt * 16 + cg;
            int c0 = bn + wn + nt * 8 + ct;
            float2* p0 = (float2*)(C + (size_t)r0 * N + c0);
            float2* p1 = (float2*)(C + (size_t)(r0 + 8) * N + c0);
            float2 v0 = make_float2(acc[mt][nt][0], acc[mt][nt][1]);
            float2 v1 = make_float2(acc[mt][nt][2], acc[mt][nt][3]);
            if (accumulate) {
                float2 o0 = *p0, o1 = *p1;
                v0.x += o0.x; v0.y += o0.y;
                v1.x += o1.x; v1.y += o1.y;
            }
            *p0 = v0; *p1 = v1;
        }
    }
}

// ---------------- merged embed + pos-encoding + weight split ----------------
__global__ void emb_split_kernel(const float* __restrict__ x,
                                 const float* __restrict__ emb_w,
                                 const float* __restrict__ emb_b,
                                 const float* __restrict__ in_w,
                                 const float* __restrict__ out_w) {
    if (blockIdx.x < BT) {
        int bt = blockIdx.x;
        int d  = threadIdx.x;
        __shared__ float sx[32];
        if (d < 32) sx[d] = x[bt * 32 + d];
        __syncthreads();
        float acc = emb_b[d];
        const float* w = emb_w + d * 32;
        #pragma unroll
        for (int i = 0; i < 32; i++) acc = fmaf(sx[i], w[i], acc);
        int t = bt & (TT - 1);
        int k2 = d & ~1;
        float div = __expf((float)k2 * (-9.210340371976184f / 256.0f));
        float ang = (float)t * div;
        acc += (d & 1) ? cosf(ang) : sinf(ang);
        g_h[bt * DD + d] = acc;
    } else {
        int i = (blockIdx.x - BT) * 256 + threadIdx.x;
        if (i < NW) {
            split_bf16(in_w[i], g_iwh[i], g_iwl[i]);
        } else {
            int j = i - NW;
            split_bf16(out_w[j], g_owh[j], g_owl[j]);
        }
    }
}

// ---------------- LN kernel (warp per row) ----------------
__global__ __launch_bounds__(256) void ln_kernel(
    const float* __restrict__ ng, const float* __restrict__ nb_)
{
    const int lane = threadIdx.x & 31;
    const int row  = blockIdx.x * 8 + (threadIdx.x >> 5);
    const float* p = g_h + (size_t)row * DD + lane * 8;
    float4 a = *(const float4*)p;
    float4 c = *(const float4*)(p + 4);
    float v[8] = {a.x, a.y, a.z, a.w, c.x, c.y, c.z, c.w};
    float s = 0.f;
    #pragma unroll
    for (int j = 0; j < 8; j++) s += v[j];
    #pragma unroll
    for (int o = 16; o; o >>= 1) s += __shfl_xor_sync(0xffffffffu, s, o);
    float mean = s * (1.f / 256.f);
    float vv = 0.f;
    #pragma unroll
    for (int j = 0; j < 8; j++) { float d0 = v[j] - mean; vv += d0 * d0; }
    #pragma unroll
    for (int o = 16; o; o >>= 1) vv += __shfl_xor_sync(0xffffffffu, vv, o);
    float rstd = rsqrtf(vv * (1.f / 256.f) + 1e-5f);
    float4 gg0 = *(const float4*)(ng + lane * 8);
    float4 gg1 = *(const float4*)(ng + lane * 8 + 4);
    float4 bb0 = *(const float4*)(nb_ + lane * 8);
    float4 bb1 = *(const float4*)(nb_ + lane * 8 + 4);
    float gv[8] = {gg0.x, gg0.y, gg0.z, gg0.w, gg1.x, gg1.y, gg1.z, gg1.w};
    float bv[8] = {bb0.x, bb0.y, bb0.z, bb0.w, bb1.x, bb1.y, bb1.z, bb1.w};
    bf16 oh[8], ol[8];
    #pragma unroll
    for (int j = 0; j < 8; j++) {
        float o = (v[j] - mean) * rstd * gv[j] + bv[j];
        split_bf16(o, oh[j], ol[j]);
    }
    uint4 uh, ul;
    uh.x = pk2(oh[0], oh[1]); uh.y = pk2(oh[2], oh[3]);
    uh.z = pk2(oh[4], oh[5]); uh.w = pk2(oh[6], oh[7]);
    ul.x = pk2(ol[0], ol[1]); ul.y = pk2(ol[2], ol[3]);
    ul.z = pk2(ol[4], ol[5]); ul.w = pk2(ol[6], ol[7]);
    *(uint4*)(g_lnh + (size_t)row * DD + lane * 8) = uh;
    *(uint4*)(g_lnl + (size_t)row * DD + lane * 8) = ul;
}

// ---------------- gemm1: 512 blocks, 1 tile each ----------------
__global__ __launch_bounds__(256, 2) void kernel_g1(
    const bf16* __restrict__ iwh, const bf16* __restrict__ iwl)
{
    extern __shared__ __align__(16) char s_dyn[];
    const int t = blockIdx.x;
    gemm_tile_pipe(s_dyn, g_lnh, g_lnl, iwh, iwl, g_v, HH, DD, 0,
                   (t >> 3) * 128, (t & 7) * 64);
}

// ---------------- gemm2: 256 blocks, 1 tile each ----------------
__global__ __launch_bounds__(256, 2) void kernel_b(
    const bf16* __restrict__ owh, const bf16* __restrict__ owl)
{
    extern __shared__ __align__(16) char s_dyn[];
    const int t = blockIdx.x;
    gemm_tile_pipe(s_dyn, g_yh, g_yl, owh, owl, g_h, DD, HH, 1,
                   (t >> 2) * 128, (t & 3) * 64);
}

// ---------------- kernel MID: conv + dt + scan (64-reg class, 4 blk/SM) ----------------
#define MID_SMEM 16384
__global__ __launch_bounds__(256, 4) void kernel_mid(
    const float* __restrict__ cw,
    const float* __restrict__ Apw, const float* __restrict__ Dpw,
    const float* __restrict__ w1,  const float* __restrict__ b1,
    const float* __restrict__ w2,  const float* __restrict__ b2)
{
    __shared__ __align__(16) char s_raw[MID_SMEM];
    const int bid = blockIdx.x;
    const int nbk = gridDim.x;
    const int tid = threadIdx.x;
    const int lane = tid & 31;
    const int warp = tid >> 5;

    // ---- conv(k=3)+silu+transpose: g_v[bt][h] -> g_vcT[h][bt] (4096 tasks) ----
    {
        float (*tile)[33] = (float(*)[33])(s_raw);
        for (int task = bid; task < BB * 16 * 32; task += nbk) {
            const int b  = task >> 9;
            const int h0 = ((task >> 5) & 15) * 32;
            const int t0 = (task & 31) * 32;
            #pragma unroll
            for (int i = tid; i < 34 * 32; i += 256) {
                int tt = i >> 5;
                int hh = i & 31;
                int t  = t0 + tt - 1;
                float v = 0.f;
                if (t >= 0 && t < TT)
                    v = g_v[((size_t)b * TT + t) * HH + h0 + hh];
                tile[tt][hh] = v;
            }
            __syncthreads();
            const int tl = tid & 31;
            const int hq = tid >> 5;
            #pragma unroll
            for (int j = 0; j < 4; j++) {
                int hh = hq * 4 + j;
                int h  = h0 + hh;
                float w0 = cw[h * 3 + 0], w1v = cw[h * 3 + 1], w2v = cw[h * 3 + 2];
                float acc = tile[tl][hh] * w0;
                acc = fmaf(tile[tl + 1][hh], w1v, acc);
                acc = fmaf(tile[tl + 2][hh], w2v, acc);
                g_vcT[(size_t)h * BT + b * TT + t0 + tl] = silu_f(acc);
            }
            __syncthreads();
        }
    }
    grid_barrier();

    // ---- dt1 + dt2 fused -> g_dtT[h][bt] (512 tasks of 16 bt) ----
    {
        float (*red)[16][9] = (float(*)[16][9])(s_raw);           // [15][16][9]
        float (*dtrs)[9]    = (float(*)[9])(s_raw + 8640);        // [16][9]
        const int btl = tid & 15;
        const int q   = tid >> 4;       // 0..15
        for (int task = bid; task < BT / 16; task += nbk) {
            const int bt0 = task * 16;
            float acc[RR];
            #pragma unroll
            for (int r = 0; r < RR; r++) acc[r] = 0.f;
            const int hbase = q * 32;
            #pragma unroll 4
            for (int hh = 0; hh < 32; hh++) {
                int h = hbase + hh;
                float v = g_vcT[(size_t)h * BT + bt0 + btl];
                #pragma unroll
                for (int r = 0; r < RR; r++) acc[r] = fmaf(v, w1[r * HH + h], acc[r]);
            }
            if (q > 0) {
                #pragma unroll
                for (int r = 0; r < RR; r++) red[q - 1][btl][r] = acc[r];
            }
            __syncthreads();
            if (q == 0) {
                #pragma unroll
                for (int r = 0; r < RR; r++) {
                    float s = acc[r] + b1[r];
                    #pragma unroll
                    for (int g = 0; g < 15; g++) s += red[g][btl][r];
                    dtrs[btl][r] = fmaxf(s, 0.f);
                }
            }
            __syncthreads();
            #pragma unroll 4
            for (int hh = q; hh < HH; hh += 16) {
                float wreg[RR];
                #pragma unroll
                for (int r = 0; r < RR; r++) wreg[r] = w2[hh * RR + r];
                float a2 = b2[hh];
                #pragma unroll
                for (int r = 0; r < RR; r++) a2 = fmaf(dtrs[btl][r], wreg[r], a2);
                float sp = (a2 > 15.f) ? a2 : log1pf(__expf(a2));
                g_dtT[(size_t)hh * BT + bt0 + btl] = sp;
            }
            __syncthreads();
        }
    }
    grid_barrier();

    // ---- scan pass 1: chunk summaries (P, e), pipelined loads, P from Σdt ----
    {
        float2* scr = (float2*)g_v;
        const int u = lane >> 1;    // channel in warp
        const int p = lane & 1;     // n half
        for (int wt = bid * 8 + warp; wt < BB * 32 * 32; wt += nbk * 8) {
            const int b  = wt >> 10;
            const int hb = (wt >> 5) & 31;
            const int ck = wt & 31;
            const int h  = hb * 16 + u;
            const int ch = b * HH + h;
            float A2[8], iA[8];
            #pragma unroll
            for (int j = 0; j < 8; j++) {
                float Ap = Apw[h * NN + p * 8 + j];
                float A  = -__expf(Ap);
                A2[j] = A * 1.4426950408889634f;
                iA[j] = (fabsf(A) < 1e-5f) ? 1.f : (1.f / A);
            }
            const float* xr = g_vcT + (size_t)h * BT + b * TT + ck * 32;
            const float* dr = g_dtT + (size_t)h * BT + b * TT + ck * 32;
            float s[8];
            #pragma unroll
            for (int j = 0; j < 8; j++) s[j] = 0.f;
            float sdt = 0.f;
            float4 xv = *(const float4*)xr;
            float4 dv = *(const float4*)dr;
            #pragma unroll
            for (int t4 = 0; t4 < 32; t4 += 4) {
                float4 xn, dn;
                if (t4 < 28) {
                    xn = *(const float4*)(xr + t4 + 4);
                    dn = *(const float4*)(dr + t4 + 4);
                }
                #pragma unroll
                for (int k = 0; k < 4; k++) {
                    float x   = ((const float*)&xv)[k];
                    float dtv = ((const float*)&dv)[k];
                    float c = dtv * x;
                    sdt += dtv;
                    #pragma unroll
                    for (int j = 0; j < 8; j++) {
                        float dA = ex2f(A2[j] * dtv);
                        float e  = iA[j] * c;
                        s[j] = fmaf(dA, s[j] + e, -e);
                    }
                }
                xv = xn; dv = dn;
            }
            float2* out = scr + ((size_t)ch * 32 + ck) * 16 + p * 8;
            #pragma unroll
            for (int j = 0; j < 8; j++)
                out[j] = make_float2(ex2f(A2[j] * sdt), s[j]);
        }
    }
    grid_barrier();

    // ---- scan pass 2: serial carry per (ch, n); stored in-place (.x) ----
    {
        float2* scr = (float2*)g_v;
        for (int i = bid * 256 + tid; i < CH * NN; i += nbk * 256) {
            float2* base = scr + ((size_t)(i >> 4) * 32) * 16 + (i & 15);
            float c = 0.f;
            #pragma unroll 8
            for (int j = 0; j < 32; j++) {
                float2 s = base[(size_t)j * 16];
                base[(size_t)j * 16].x = c;
                c = fmaf(s.x, c, s.y);
            }
        }
    }
    grid_barrier();

    // ---- scan pass 3: re-scan with carry init, pipelined loads, emit y ----
    {
        float2* scr = (float2*)g_v;
        bf16 (*s_yh)[16] = (bf16(*)[16])(s_raw + warp * 2048);
        bf16 (*s_yl)[16] = (bf16(*)[16])(s_raw + warp * 2048 + 1024);
        const int u = lane >> 1;
        const int p = lane & 1;
        for (int wt = bid * 8 + warp; wt < BB * 32 * 32; wt += nbk * 8) {
            const int b  = wt >> 10;
            const int hb = (wt >> 5) & 31;
            const int ck = wt & 31;
            const int h  = hb * 16 + u;
            const int ch = b * HH + h;
            float A2[8], iA[8], Apv[8];
            #pragma unroll
            for (int j = 0; j < 8; j++) {
                float Ap = Apw[h * NN + p * 8 + j];
                Apv[j] = Ap;
                float A  = -__expf(Ap);
                A2[j] = A * 1.4426950408889634f;
                iA[j] = (fabsf(A) < 1e-5f) ? 1.f : (1.f / A);
            }
            float Dp = Dpw[h];
            const float* xr = g_vcT + (size_t)h * BT + b * TT + ck * 32;
            const float* dr = g_dtT + (size_t)h * BT + b * TT + ck * 32;
            const float2* cin = scr + ((size_t)ch * 32 + ck) * 16 + p * 8;
            float s[8];
            #pragma unroll
            for (int j = 0; j < 8; j++) s[j] = cin[j].x;
            float4 xv = *(const float4*)xr;
            float4 dv = *(const float4*)dr;
            #pragma unroll
            for (int t4 = 0; t4 < 32; t4 += 4) {
                float4 xn, dn;
                if (t4 < 28) {
                    xn = *(const float4*)(xr + t4 + 4);
                    dn = *(const float4*)(dr + t4 + 4);
                }
                #pragma unroll
                for (int k = 0; k < 4; k++) {
                    float x   = ((const float*)&xv)[k];
                    float dtv = ((const float*)&dv)[k];
                    float c = dtv * x;
                    float part = 0.f;
                    #pragma unroll
                    for (int j = 0; j < 8; j++) {
                        float dA = ex2f(A2[j] * dtv);
                        float e  = iA[j] * c;
                        s[j] = fmaf(dA, s[j] + e, -e);
                        part = fmaf(Apv[j], s[j], part);
                    }
                    part += __shfl_xor_sync(0xffffffffu, part, 1);
                    if (p == 0) {
                        float y = fmaf(Dp, x, part);
                        bf16 hh_, ll_;
                        split_bf16(y, hh_, ll_);
                        s_yh[t4 + k][u] = hh_;
                        s_yl[t4 + k][u] = ll_;
                    }
                }
                xv = xn; dv = dn;
            }
            __syncwarp();
            {
                size_t rbase = (size_t)(b * TT + ck * 32 + lane) * HH + hb * 16;
                uint4* sh = (uint4*)&s_yh[lane][0];
                uint4* sl = (uint4*)&s_yl[lane][0];
                *(uint4*)(g_yh + rbase)     = sh[0];
                *(uint4*)(g_yh + rbase + 8) = sh[1];
                *(uint4*)(g_yl + rbase)     = sl[0];
                *(uint4*)(g_yl + rbase + 8) = sl[1];
            }
            __syncwarp();
        }
    }
}

// ---------------- final LN (last token) + head1(silu) + head2 ----------------
__global__ void final_kernel(const float* __restrict__ fg,
                             const float* __restrict__ fb,
                             const float* __restrict__ w1,
                             const float* __restrict__ b1,
                             const float* __restrict__ w2,
                             const float* __restrict__ b2,
                             float* __restrict__ out) {
    int b = blockIdx.x;
    int tid = threadIdx.x;
    __shared__ float red1[8], red2[8];
    __shared__ float s_ln[DD];
    __shared__ float s_h1[DD];
    const float* row = g_h + (size_t)(b * TT + (TT - 1)) * DD;
    float v = row[tid];
    float s = v;
    #pragma unroll
    for (int o = 16; o; o >>= 1) s += __shfl_xor_sync(0xffffffffu, s, o);
    if ((tid & 31) == 0) red1[tid >> 5] = s;
    __syncthreads();
    float mean = 0.f;
    #pragma unroll
    for (int i = 0; i < 8; i++) mean += red1[i];
    mean *= (1.f / 256.f);
    float c = v - mean;
    float cc = c * c;
    #pragma unroll
    for (int o = 16; o; o >>= 1) cc += __shfl_xor_sync(0xffffffffu, cc, o);
    if ((tid & 31) == 0) red2[tid >> 5] = cc;
    __syncthreads();
    float var = 0.f;
    #pragma unroll
    for (int i = 0; i < 8; i++) var += red2[i];
    var *= (1.f / 256.f);
    s_ln[tid] = c * rsqrtf(var + 1e-5f) * fg[tid] + fb[tid];
    __syncthreads();
    float acc = b1[tid];
    const float* w1r = w1 + tid * DD;
    #pragma unroll 8
    for (int k = 0; k < DD; k++) acc = fmaf(s_ln[k], w1r[k], acc);
    s_h1[tid] = silu_f(acc);
    __syncthreads();
    if (tid < 96) {
        float a2 = b2[tid];
        const float* w2r = w2 + tid * DD;
        #pragma unroll 8
        for (int k = 0; k < DD; k++) a2 = fmaf(s_h1[k], w2r[k], a2);
        out[b * 96 + tid] = a2;
    }
}

// ---------------- launcher: 18 graph nodes ----------------
extern "C" void kernel_launch(void* const* d_in, const int* in_sizes, int n_in,
                              void* d_out, int out_size) {
    const float* x      = (const float*)d_in[0];
    const float* emb_w  = (const float*)d_in[1];
    const float* emb_b  = (const float*)d_in[2];
    const float* norm_g = (const float*)d_in[3];
    const float* norm_b = (const float*)d_in[4];
    const float* in_w   = (const float*)d_in[5];
    const float* conv_w = (const float*)d_in[6];
    const float* A_p    = (const float*)d_in[7];
    const float* D_p    = (const float*)d_in[8];
    const float* dt1_w  = (const float*)d_in[9];
    const float* dt1_b  = (const float*)d_in[10];
    const float* dt2_w  = (const float*)d_in[11];
    const float* dt2_b  = (const float*)d_in[12];
    const float* out_w  = (const float*)d_in[13];
    const float* fin_g  = (const float*)d_in[14];
    const float* fin_b  = (const float*)d_in[15];
    const float* h1_w   = (const float*)d_in[16];
    const float* h1_b   = (const float*)d_in[17];
    const float* h2_w   = (const float*)d_in[18];
    const float* h2_b   = (const float*)d_in[19];
    float* out = (float*)d_out;

    bf16 *piwh, *piwl, *powh, *powl;
    cudaGetSymbolAddress((void**)&piwh, g_iwh);
    cudaGetSymbolAddress((void**)&piwl, g_iwl);
    cudaGetSymbolAddress((void**)&powh, g_owh);
    cudaGetSymbolAddress((void**)&powl, g_owl);

    cudaFuncSetAttribute(kernel_g1, cudaFuncAttributeMaxDynamicSharedMemorySize,
                         GEMM_SMEM_DYN);
    cudaFuncSetAttribute(kernel_b, cudaFuncAttributeMaxDynamicSharedMemorySize,
                         GEMM_SMEM_DYN);

    emb_split_kernel<<<BT + (2 * NW) / 256, 256>>>(x, emb_w, emb_b, in_w, out_w);

    for (int l = 0; l < LL; l++) {
        ln_kernel<<<BT / 8, 256>>>(norm_g + l * DD, norm_b + l * DD);

        kernel_g1<<<512, 256, GEMM_SMEM_DYN>>>(
            piwh + (size_t)l * HH * DD, piwl + (size_t)l * HH * DD);

        kernel_mid<<<GRID_MID, 256>>>(
            conv_w + (size_t)l * HH * 3,
            A_p + (size_t)l * HH * NN, D_p + l * HH,
            dt1_w + (size_t)l * RR * HH, dt1_b + l * RR,
            dt2_w + (size_t)l * HH * RR, dt2_b + l * HH);

        kernel_b<<<256, 256, GEMM_SMEM_DYN>>>(
            powh + (size_t)l * DD * HH, powl + (size_t)l * DD * HH);
    }

    final_kernel<<<BB, 256>>>(fin_g, fin_b, h1_w, h1_b, h2_w, h2_b, out);
}

// round 13
// speedup vs baseline: 1.8633x; 1.0154x over previous
#include <cuda_runtime.h>
#include <cuda_bf16.h>
#include <cstdint>
#include <math.h>

typedef __nv_bfloat16 bf16;

// ---------------- problem constants ----------------
#define BB   8
#define TT   1024
#define DD   256
#define HH   512
#define NN   16
#define RR   8
#define LL   4
#define BT   (BB*TT)        // 8192
#define BTH  (BB*TT*HH)     // 4194304
#define BTD  (BB*TT*DD)     // 2097152
#define NW   (LL*HH*DD)     // 524288
#define CH   (BB*HH)        // 4096 channels
#define NTAB (LL*HH*NN)     // 32768 table entries

#define GRID_MID 592        // 148 SMs x 4 blocks (64-reg class)

// ---------------- scratch (static device globals; no allocation) ----------------
__device__ float g_h  [BTD];
__device__ float g_v  [BTH];        // gemm1 out; reused as scan scratch (float2 summaries)
__device__ float g_vcT[BTH];        // [h][bt]
__device__ float g_dtT[BTH];        // [h][bt]
__device__ float2 g_tab[NTAB];      // per (l,h,n): {A*log2e, 1/A}
__device__ bf16 g_lnh[BTD], g_lnl[BTD];
__device__ bf16 g_yh [BTH], g_yl [BTH];   // [bt][h]
__device__ bf16 g_iwh[NW],  g_iwl[NW];
__device__ bf16 g_owh[NW],  g_owl[NW];

// ---------------- grid-wide barrier: atomic arrive, volatile-load spin ----------------
__device__ unsigned int g_bar_cnt;
__device__ unsigned int g_bar_gen;

__device__ __forceinline__ void grid_barrier() {
    __syncthreads();
    if (threadIdx.x == 0) {
        volatile unsigned int* genp = (volatile unsigned int*)&g_bar_gen;
        unsigned int gen = *genp;          // stable: release can't happen until we arrive
        __threadfence();
        unsigned int arrived = atomicAdd(&g_bar_cnt, 1u);
        if (arrived == gridDim.x - 1) {
            g_bar_cnt = 0;
            __threadfence();
            *genp = gen + 1;               // release (volatile store, L2-visible)
        } else {
            while (*genp == gen) __nanosleep(64);   // plain L2 reads: no atom-ALU serialization
            __threadfence();
        }
    }
    __syncthreads();
}

// ---------------- helpers ----------------
__device__ __forceinline__ float silu_f(float x) {
    return x / (1.f + __expf(-x));
}

__device__ __forceinline__ float ex2f(float x) {
    float r;
    asm("ex2.approx.ftz.f32 %0, %1;" : "=f"(r) : "f"(x));
    return r;
}

__device__ __forceinline__ void split_bf16(float v, bf16& h, bf16& l) {
    h = __float2bfloat16(v);
    l = __float2bfloat16(v - __bfloat162float(h));
}

__device__ __forceinline__ unsigned int pk2(bf16 a, bf16 b) {
    return (unsigned int)__bfloat16_as_ushort(a) |
           ((unsigned int)__bfloat16_as_ushort(b) << 16);
}

__device__ __forceinline__ void ldsm4(unsigned int r[4], const void* p) {
    unsigned int a = (unsigned int)__cvta_generic_to_shared(p);
    asm volatile("ldmatrix.sync.aligned.m8n8.x4.shared.b16 {%0,%1,%2,%3}, [%4];"
                 : "=r"(r[0]), "=r"(r[1]), "=r"(r[2]), "=r"(r[3]) : "r"(a));
}

__device__ __forceinline__ void mma_bf16(float c[4], const unsigned int a[4],
                                         unsigned int b0, unsigned int b1) {
    asm volatile(
        "mma.sync.aligned.m16n8k16.row.col.f32.bf16.bf16.f32 "
        "{%0,%1,%2,%3},{%4,%5,%6,%7},{%8,%9},{%0,%1,%2,%3};"
        : "+f"(c[0]), "+f"(c[1]), "+f"(c[2]), "+f"(c[3])
        : "r"(a[0]), "r"(a[1]), "r"(a[2]), "r"(a[3]), "r"(b0), "r"(b1));
}

__device__ __forceinline__ void cp16(void* smem, const void* gmem) {
    unsigned int s = (unsigned int)__cvta_generic_to_shared(smem);
    asm volatile("cp.async.cg.shared.global [%0], [%1], 16;" :: "r"(s), "l"(gmem));
}
#define CP_COMMIT()  asm volatile("cp.async.commit_group;")
#define CP_WAIT(n)   asm volatile("cp.async.wait_group %0;" :: "n"(n))

// ---------------- gemm tile: 3-stage cp.async pipeline ----------------
#define PADK 40
#define STAGE_BYTES 30720
#define GEMM_SMEM_DYN (3 * STAGE_BYTES)

__device__ void gemm_tile_pipe(char* s_raw,
    const bf16* __restrict__ Ah, const bf16* __restrict__ Al,
    const bf16* __restrict__ Wh, const bf16* __restrict__ Wl,
    float* __restrict__ C, int N, int K, int accumulate, int bm, int bn)
{
    const int tid  = threadIdx.x;
    const int lane = tid & 31;
    const int wid  = tid >> 5;
    const int wm   = (wid & 3) * 32;
    const int wn   = (wid >> 2) * 32;

    float acc[2][4][4];
    #pragma unroll
    for (int a = 0; a < 2; a++)
        #pragma unroll
        for (int b = 0; b < 4; b++)
            #pragma unroll
            for (int c = 0; c < 4; c++) acc[a][b][c] = 0.f;

    const int lrow = tid >> 2;
    const int lcol = (tid & 3) * 8;

    const int a_row = lane & 15;
    const int a_col = (lane >> 4) << 3;
    const int bq    = lane >> 3;
    const int b_row = (lane & 7) + ((bq >> 1) << 3);
    const int b_col = (bq & 1) << 3;

    const bf16* pAh0 = Ah + (size_t)(bm + lrow) * K + lcol;
    const bf16* pAh1 = pAh0 + (size_t)64 * K;
    const bf16* pAl0 = Al + (size_t)(bm + lrow) * K + lcol;
    const bf16* pAl1 = pAl0 + (size_t)64 * K;
    const bf16* pWh  = Wh + (size_t)(bn + lrow) * K + lcol;
    const bf16* pWl  = Wl + (size_t)(bn + lrow) * K + lcol;

    const int niter = K >> 5;

    auto load_stage = [&](int stage, int kt) {
        char* sb = s_raw + stage * STAGE_BYTES;
        bf16 (*sAh)[PADK] = (bf16(*)[PADK])(sb);
        bf16 (*sAl)[PADK] = (bf16(*)[PADK])(sb + 10240);
        bf16 (*sWh)[PADK] = (bf16(*)[PADK])(sb + 20480);
        bf16 (*sWl)[PADK] = (bf16(*)[PADK])(sb + 25600);
        cp16(&sAh[lrow     ][lcol], pAh0 + kt);
        cp16(&sAh[lrow + 64][lcol], pAh1 + kt);
        cp16(&sAl[lrow     ][lcol], pAl0 + kt);
        cp16(&sAl[lrow + 64][lcol], pAl1 + kt);
        cp16(&sWh[lrow][lcol], pWh + kt);
        cp16(&sWl[lrow][lcol], pWl + kt);
    };

    load_stage(0, 0);
    CP_COMMIT();
    load_stage(1, 32);
    CP_COMMIT();

    int st = 0;
    for (int it = 0; it < niter; it++) {
        if (it + 2 < niter) {
            int s2 = st + 2; if (s2 >= 3) s2 -= 3;
            load_stage(s2, (it + 2) << 5);
            CP_COMMIT();
            CP_WAIT(2);
        } else {
            CP_COMMIT();          // empty group
            CP_WAIT(2);
        }
        __syncthreads();

        char* sb = s_raw + st * STAGE_BYTES;
        bf16 (*sAh)[PADK] = (bf16(*)[PADK])(sb);
        bf16 (*sAl)[PADK] = (bf16(*)[PADK])(sb + 10240);
        bf16 (*sWh)[PADK] = (bf16(*)[PADK])(sb + 20480);
        bf16 (*sWl)[PADK] = (bf16(*)[PADK])(sb + 25600);

        #pragma unroll
        for (int ks = 0; ks < 2; ks++) {
            const int k0 = ks * 16;
            unsigned int ah[2][4], al[2][4];
            #pragma unroll
            for (int mt = 0; mt < 2; mt++) {
                ldsm4(ah[mt], &sAh[wm + mt * 16 + a_row][k0 + a_col]);
                ldsm4(al[mt], &sAl[wm + mt * 16 + a_row][k0 + a_col]);
            }
            unsigned int bh[2][4], bl[2][4];
            #pragma unroll
            for (int nb = 0; nb < 2; nb++) {
                ldsm4(bh[nb], &sWh[wn + nb * 16 + b_row][k0 + b_col]);
                ldsm4(bl[nb], &sWl[wn + nb * 16 + b_row][k0 + b_col]);
            }
            #pragma unroll
            for (int mt = 0; mt < 2; mt++) {
                #pragma unroll
                for (int nt = 0; nt < 4; nt++) {
                    const int nb = nt >> 1, hf = (nt & 1) * 2;
                    mma_bf16(acc[mt][nt], ah[mt], bh[nb][hf], bh[nb][hf + 1]);
                    mma_bf16(acc[mt][nt], ah[mt], bl[nb][hf], bl[nb][hf + 1]);
                    mma_bf16(acc[mt][nt], al[mt], bh[nb][hf], bh[nb][hf + 1]);
                }
            }
        }
        __syncthreads();
        if (++st == 3) st = 0;
    }

    const int cg = lane >> 2;
    const int ct = (lane & 3) * 2;
    #pragma unroll
    for (int mt = 0; mt < 2; mt++) {
        #pragma unroll
        for (int nt = 0; nt < 4; nt++) {
            int r0 = bm + wm + mt * 16 + cg;
            int c0 = bn + wn + nt * 8 + ct;
            float2* p0 = (float2*)(C + (size_t)r0 * N + c0);
            float2* p1 = (float2*)(C + (size_t)(r0 + 8) * N + c0);
            float2 v0 = make_float2(acc[mt][nt][0], acc[mt][nt][1]);
            float2 v1 = make_float2(acc[mt][nt][2], acc[mt][nt][3]);
            if (accumulate) {
                float2 o0 = *p0, o1 = *p1;
                v0.x += o0.x; v0.y += o0.y;
                v1.x += o1.x; v1.y += o1.y;
            }
            *p0 = v0; *p1 = v1;
        }
    }
}

// ---------------- merged embed + pos-encoding + weight split + A-tables ----------------
__global__ void emb_split_kernel(const float* __restrict__ x,
                                 const float* __restrict__ emb_w,
                                 const float* __restrict__ emb_b,
                                 const float* __restrict__ in_w,
                                 const float* __restrict__ out_w,
                                 const float* __restrict__ A_p) {
    if (blockIdx.x < BT) {
        int bt = blockIdx.x;
        int d  = threadIdx.x;
        __shared__ float sx[32];
        if (d < 32) sx[d] = x[bt * 32 + d];
        __syncthreads();
        float acc = emb_b[d];
        const float* w = emb_w + d * 32;
        #pragma unroll
        for (int i = 0; i < 32; i++) acc = fmaf(sx[i], w[i], acc);
        int t = bt & (TT - 1);
        int k2 = d & ~1;
        float div = __expf((float)k2 * (-9.210340371976184f / 256.0f));
        float ang = (float)t * div;
        acc += (d & 1) ? cosf(ang) : sinf(ang);
        g_h[bt * DD + d] = acc;
    } else {
        int i = (blockIdx.x - BT) * 256 + threadIdx.x;
        if (i < NW) {
            split_bf16(in_w[i], g_iwh[i], g_iwl[i]);
        } else if (i < 2 * NW) {
            int j = i - NW;
            split_bf16(out_w[j], g_owh[j], g_owl[j]);
        } else {
            int j = i - 2 * NW;
            if (j < NTAB) {
                float A = -__expf(A_p[j]);
                float iA = (fabsf(A) < 1e-5f) ? 1.f : (1.f / A);
                g_tab[j] = make_float2(A * 1.4426950408889634f, iA);
            }
        }
    }
}

// ---------------- LN kernel (warp per row) ----------------
__global__ __launch_bounds__(256) void ln_kernel(
    const float* __restrict__ ng, const float* __restrict__ nb_)
{
    const int lane = threadIdx.x & 31;
    const int row  = blockIdx.x * 8 + (threadIdx.x >> 5);
    const float* p = g_h + (size_t)row * DD + lane * 8;
    float4 a = *(const float4*)p;
    float4 c = *(const float4*)(p + 4);
    float v[8] = {a.x, a.y, a.z, a.w, c.x, c.y, c.z, c.w};
    float s = 0.f;
    #pragma unroll
    for (int j = 0; j < 8; j++) s += v[j];
    #pragma unroll
    for (int o = 16; o; o >>= 1) s += __shfl_xor_sync(0xffffffffu, s, o);
    float mean = s * (1.f / 256.f);
    float vv = 0.f;
    #pragma unroll
    for (int j = 0; j < 8; j++) { float d0 = v[j] - mean; vv += d0 * d0; }
    #pragma unroll
    for (int o = 16; o; o >>= 1) vv += __shfl_xor_sync(0xffffffffu, vv, o);
    float rstd = rsqrtf(vv * (1.f / 256.f) + 1e-5f);
    float4 gg0 = *(const float4*)(ng + lane * 8);
    float4 gg1 = *(const float4*)(ng + lane * 8 + 4);
    float4 bb0 = *(const float4*)(nb_ + lane * 8);
    float4 bb1 = *(const float4*)(nb_ + lane * 8 + 4);
    float gv[8] = {gg0.x, gg0.y, gg0.z, gg0.w, gg1.x, gg1.y, gg1.z, gg1.w};
    float bv[8] = {bb0.x, bb0.y, bb0.z, bb0.w, bb1.x, bb1.y, bb1.z, bb1.w};
    bf16 oh[8], ol[8];
    #pragma unroll
    for (int j = 0; j < 8; j++) {
        float o = (v[j] - mean) * rstd * gv[j] + bv[j];
        split_bf16(o, oh[j], ol[j]);
    }
    uint4 uh, ul;
    uh.x = pk2(oh[0], oh[1]); uh.y = pk2(oh[2], oh[3]);
    uh.z = pk2(oh[4], oh[5]); uh.w = pk2(oh[6], oh[7]);
    ul.x = pk2(ol[0], ol[1]); ul.y = pk2(ol[2], ol[3]);
    ul.z = pk2(ol[4], ol[5]); ul.w = pk2(ol[6], ol[7]);
    *(uint4*)(g_lnh + (size_t)row * DD + lane * 8) = uh;
    *(uint4*)(g_lnl + (size_t)row * DD + lane * 8) = ul;
}

// ---------------- gemm1: 512 blocks, 1 tile each ----------------
__global__ __launch_bounds__(256, 2) void kernel_g1(
    const bf16* __restrict__ iwh, const bf16* __restrict__ iwl)
{
    extern __shared__ __align__(16) char s_dyn[];
    const int t = blockIdx.x;
    gemm_tile_pipe(s_dyn, g_lnh, g_lnl, iwh, iwl, g_v, HH, DD, 0,
                   (t >> 3) * 128, (t & 7) * 64);
}

// ---------------- gemm2: 256 blocks, 1 tile each ----------------
__global__ __launch_bounds__(256, 2) void kernel_b(
    const bf16* __restrict__ owh, const bf16* __restrict__ owl)
{
    extern __shared__ __align__(16) char s_dyn[];
    const int t = blockIdx.x;
    gemm_tile_pipe(s_dyn, g_yh, g_yl, owh, owl, g_h, DD, HH, 1,
                   (t >> 2) * 128, (t & 3) * 64);
}

// ---------------- kernel MID: conv + dt + scan (64-reg class, 4 blk/SM) ----------------
#define MID_SMEM 16384
__global__ __launch_bounds__(256, 4) void kernel_mid(
    const float* __restrict__ cw,
    const float* __restrict__ Apw, const float* __restrict__ Dpw,
    const float2* __restrict__ tab,
    const float* __restrict__ w1,  const float* __restrict__ b1,
    const float* __restrict__ w2,  const float* __restrict__ b2)
{
    __shared__ __align__(16) char s_raw[MID_SMEM];
    const int bid = blockIdx.x;
    const int nbk = gridDim.x;
    const int tid = threadIdx.x;
    const int lane = tid & 31;
    const int warp = tid >> 5;

    // ---- conv(k=3)+silu+transpose: g_v[bt][h] -> g_vcT[h][bt] (4096 tasks) ----
    {
        float (*tile)[33] = (float(*)[33])(s_raw);
        for (int task = bid; task < BB * 16 * 32; task += nbk) {
            const int b  = task >> 9;
            const int h0 = ((task >> 5) & 15) * 32;
            const int t0 = (task & 31) * 32;
            #pragma unroll
            for (int i = tid; i < 34 * 32; i += 256) {
                int tt = i >> 5;
                int hh = i & 31;
                int t  = t0 + tt - 1;
                float v = 0.f;
                if (t >= 0 && t < TT)
                    v = g_v[((size_t)b * TT + t) * HH + h0 + hh];
                tile[tt][hh] = v;
            }
            __syncthreads();
            const int tl = tid & 31;
            const int hq = tid >> 5;
            #pragma unroll
            for (int j = 0; j < 4; j++) {
                int hh = hq * 4 + j;
                int h  = h0 + hh;
                float w0 = cw[h * 3 + 0], w1v = cw[h * 3 + 1], w2v = cw[h * 3 + 2];
                float acc = tile[tl][hh] * w0;
                acc = fmaf(tile[tl + 1][hh], w1v, acc);
                acc = fmaf(tile[tl + 2][hh], w2v, acc);
                g_vcT[(size_t)h * BT + b * TT + t0 + tl] = silu_f(acc);
            }
            __syncthreads();
        }
    }
    grid_barrier();

    // ---- dt1 + dt2 fused -> g_dtT[h][bt] (512 tasks of 16 bt) ----
    {
        float (*red)[16][9] = (float(*)[16][9])(s_raw);           // [15][16][9]
        float (*dtrs)[9]    = (float(*)[9])(s_raw + 8640);        // [16][9]
        const int btl = tid & 15;
        const int q   = tid >> 4;       // 0..15
        for (int task = bid; task < BT / 16; task += nbk) {
            const int bt0 = task * 16;
            float acc[RR];
            #pragma unroll
            for (int r = 0; r < RR; r++) acc[r] = 0.f;
            const int hbase = q * 32;
            #pragma unroll 4
            for (int hh = 0; hh < 32; hh++) {
                int h = hbase + hh;
                float v = g_vcT[(size_t)h * BT + bt0 + btl];
                #pragma unroll
                for (int r = 0; r < RR; r++) acc[r] = fmaf(v, w1[r * HH + h], acc[r]);
            }
            if (q > 0) {
                #pragma unroll
                for (int r = 0; r < RR; r++) red[q - 1][btl][r] = acc[r];
            }
            __syncthreads();
            if (q == 0) {
                #pragma unroll
                for (int r = 0; r < RR; r++) {
                    float s = acc[r] + b1[r];
                    #pragma unroll
                    for (int g = 0; g < 15; g++) s += red[g][btl][r];
                    dtrs[btl][r] = fmaxf(s, 0.f);
                }
            }
            __syncthreads();
            #pragma unroll 4
            for (int hh = q; hh < HH; hh += 16) {
                float wreg[RR];
                #pragma unroll
                for (int r = 0; r < RR; r++) wreg[r] = w2[hh * RR + r];
                float a2 = b2[hh];
                #pragma unroll
                for (int r = 0; r < RR; r++) a2 = fmaf(dtrs[btl][r], wreg[r], a2);
                float sp = (a2 > 15.f) ? a2 : log1pf(__expf(a2));
                g_dtT[(size_t)hh * BT + bt0 + btl] = sp;
            }
            __syncthreads();
        }
    }
    grid_barrier();

    // ---- scan pass 1: chunk summaries (P, e), table coefficients ----
    {
        float2* scr = (float2*)g_v;
        const int u = lane >> 1;    // channel in warp
        const int p = lane & 1;     // n half
        for (int wt = bid * 8 + warp; wt < BB * 32 * 32; wt += nbk * 8) {
            const int b  = wt >> 10;
            const int hb = (wt >> 5) & 31;
            const int ck = wt & 31;
            const int h  = hb * 16 + u;
            const int ch = b * HH + h;
            float A2[8], iA[8];
            const float2* tp = tab + h * NN + p * 8;
            #pragma unroll
            for (int j = 0; j < 8; j += 2) {
                float4 tv = *(const float4*)(tp + j);
                A2[j] = tv.x; iA[j] = tv.y;
                A2[j + 1] = tv.z; iA[j + 1] = tv.w;
            }
            const float* xr = g_vcT + (size_t)h * BT + b * TT + ck * 32;
            const float* dr = g_dtT + (size_t)h * BT + b * TT + ck * 32;
            float s[8];
            #pragma unroll
            for (int j = 0; j < 8; j++) s[j] = 0.f;
            float sdt = 0.f;
            float4 xv = *(const float4*)xr;
            float4 dv = *(const float4*)dr;
            #pragma unroll
            for (int t4 = 0; t4 < 32; t4 += 4) {
                float4 xn, dn;
                if (t4 < 28) {
                    xn = *(const float4*)(xr + t4 + 4);
                    dn = *(const float4*)(dr + t4 + 4);
                }
                #pragma unroll
                for (int k = 0; k < 4; k++) {
                    float x   = ((const float*)&xv)[k];
                    float dtv = ((const float*)&dv)[k];
                    float c = dtv * x;
                    sdt += dtv;
                    #pragma unroll
                    for (int j = 0; j < 8; j++) {
                        float dA = ex2f(A2[j] * dtv);
                        float e  = iA[j] * c;
                        s[j] = fmaf(dA, s[j] + e, -e);
                    }
                }
                xv = xn; dv = dn;
            }
            float2* out = scr + ((size_t)ch * 32 + ck) * 16 + p * 8;
            #pragma unroll
            for (int j = 0; j < 8; j++)
                out[j] = make_float2(ex2f(A2[j] * sdt), s[j]);
        }
    }
    grid_barrier();

    // ---- scan pass 2: serial carry per (ch, n); stored in-place (.x) ----
    {
        float2* scr = (float2*)g_v;
        for (int i = bid * 256 + tid; i < CH * NN; i += nbk * 256) {
            float2* base = scr + ((size_t)(i >> 4) * 32) * 16 + (i & 15);
            float c = 0.f;
            #pragma unroll 8
            for (int j = 0; j < 32; j++) {
                float2 s = base[(size_t)j * 16];
                base[(size_t)j * 16].x = c;
                c = fmaf(s.x, c, s.y);
            }
        }
    }
    grid_barrier();

    // ---- scan pass 3: re-scan with carry init, emit y ----
    {
        float2* scr = (float2*)g_v;
        bf16 (*s_yh)[16] = (bf16(*)[16])(s_raw + warp * 2048);
        bf16 (*s_yl)[16] = (bf16(*)[16])(s_raw + warp * 2048 + 1024);
        const int u = lane >> 1;
        const int p = lane & 1;
        for (int wt = bid * 8 + warp; wt < BB * 32 * 32; wt += nbk * 8) {
            const int b  = wt >> 10;
            const int hb = (wt >> 5) & 31;
            const int ck = wt & 31;
            const int h  = hb * 16 + u;
            const int ch = b * HH + h;
            float A2[8], iA[8], Apv[8];
            const float2* tp = tab + h * NN + p * 8;
            #pragma unroll
            for (int j = 0; j < 8; j += 2) {
                float4 tv = *(const float4*)(tp + j);
                A2[j] = tv.x; iA[j] = tv.y;
                A2[j + 1] = tv.z; iA[j + 1] = tv.w;
            }
            const float* app = Apw + h * NN + p * 8;
            #pragma unroll
            for (int j = 0; j < 8; j += 4) {
                float4 av = *(const float4*)(app + j);
                Apv[j] = av.x; Apv[j + 1] = av.y;
                Apv[j + 2] = av.z; Apv[j + 3] = av.w;
            }
            float Dp = Dpw[h];
            const float* xr = g_vcT + (size_t)h * BT + b * TT + ck * 32;
            const float* dr = g_dtT + (size_t)h * BT + b * TT + ck * 32;
            const float2* cin = scr + ((size_t)ch * 32 + ck) * 16 + p * 8;
            float s[8];
            #pragma unroll
            for (int j = 0; j < 8; j++) s[j] = cin[j].x;
            float4 xv = *(const float4*)xr;
            float4 dv = *(const float4*)dr;
            #pragma unroll
            for (int t4 = 0; t4 < 32; t4 += 4) {
                float4 xn, dn;
                if (t4 < 28) {
                    xn = *(const float4*)(xr + t4 + 4);
                    dn = *(const float4*)(dr + t4 + 4);
                }
                #pragma unroll
                for (int k = 0; k < 4; k++) {
                    float x   = ((const float*)&xv)[k];
                    float dtv = ((const float*)&dv)[k];
                    float c = dtv * x;
                    float part = 0.f;
                    #pragma unroll
                    for (int j = 0; j < 8; j++) {
                        float dA = ex2f(A2[j] * dtv);
                        float e  = iA[j] * c;
                        s[j] = fmaf(dA, s[j] + e, -e);
                        part = fmaf(Apv[j], s[j], part);
                    }
                    part += __shfl_xor_sync(0xffffffffu, part, 1);
                    if (p == 0) {
                        float y = fmaf(Dp, x, part);
                        bf16 hh_, ll_;
                        split_bf16(y, hh_, ll_);
                        s_yh[t4 + k][u] = hh_;
                        s_yl[t4 + k][u] = ll_;
                    }
                }
                xv = xn; dv = dn;
            }
            __syncwarp();
            {
                size_t rbase = (size_t)(b * TT + ck * 32 + lane) * HH + hb * 16;
                uint4* sh = (uint4*)&s_yh[lane][0];
                uint4* sl = (uint4*)&s_yl[lane][0];
                *(uint4*)(g_yh + rbase)     = sh[0];
                *(uint4*)(g_yh + rbase + 8) = sh[1];
                *(uint4*)(g_yl + rbase)     = sl[0];
                *(uint4*)(g_yl + rbase + 8) = sl[1];
            }
            __syncwarp();
        }
    }
}

// ---------------- final LN (last token) + head1(silu) + head2 ----------------
__global__ void final_kernel(const float* __restrict__ fg,
                             const float* __restrict__ fb,
                             const float* __restrict__ w1,
                             const float* __restrict__ b1,
                             const float* __restrict__ w2,
                             const float* __restrict__ b2,
                             float* __restrict__ out) {
    int b = blockIdx.x;
    int tid = threadIdx.x;
    __shared__ float red1[8], red2[8];
    __shared__ float s_ln[DD];
    __shared__ float s_h1[DD];
    const float* row = g_h + (size_t)(b * TT + (TT - 1)) * DD;
    float v = row[tid];
    float s = v;
    #pragma unroll
    for (int o = 16; o; o >>= 1) s += __shfl_xor_sync(0xffffffffu, s, o);
    if ((tid & 31) == 0) red1[tid >> 5] = s;
    __syncthreads();
    float mean = 0.f;
    #pragma unroll
    for (int i = 0; i < 8; i++) mean += red1[i];
    mean *= (1.f / 256.f);
    float c = v - mean;
    float cc = c * c;
    #pragma unroll
    for (int o = 16; o; o >>= 1) cc += __shfl_xor_sync(0xffffffffu, cc, o);
    if ((tid & 31) == 0) red2[tid >> 5] = cc;
    __syncthreads();
    float var = 0.f;
    #pragma unroll
    for (int i = 0; i < 8; i++) var += red2[i];
    var *= (1.f / 256.f);
    s_ln[tid] = c * rsqrtf(var + 1e-5f) * fg[tid] + fb[tid];
    __syncthreads();
    float acc = b1[tid];
    const float* w1r = w1 + tid * DD;
    #pragma unroll 8
    for (int k = 0; k < DD; k++) acc = fmaf(s_ln[k], w1r[k], acc);
    s_h1[tid] = silu_f(acc);
    __syncthreads();
    if (tid < 96) {
        float a2 = b2[tid];
        const float* w2r = w2 + tid * DD;
        #pragma unroll 8
        for (int k = 0; k < DD; k++) a2 = fmaf(s_h1[k], w2r[k], a2);
        out[b * 96 + tid] = a2;
    }
}

// ---------------- launcher: 18 graph nodes ----------------
extern "C" void kernel_launch(void* const* d_in, const int* in_sizes, int n_in,
                              void* d_out, int out_size) {
    const float* x      = (const float*)d_in[0];
    const float* emb_w  = (const float*)d_in[1];
    const float* emb_b  = (const float*)d_in[2];
    const float* norm_g = (const float*)d_in[3];
    const float* norm_b = (const float*)d_in[4];
    const float* in_w   = (const float*)d_in[5];
    const float* conv_w = (const float*)d_in[6];
    const float* A_p    = (const float*)d_in[7];
    const float* D_p    = (const float*)d_in[8];
    const float* dt1_w  = (const float*)d_in[9];
    const float* dt1_b  = (const float*)d_in[10];
    const float* dt2_w  = (const float*)d_in[11];
    const float* dt2_b  = (const float*)d_in[12];
    const float* out_w  = (const float*)d_in[13];
    const float* fin_g  = (const float*)d_in[14];
    const float* fin_b  = (const float*)d_in[15];
    const float* h1_w   = (const float*)d_in[16];
    const float* h1_b   = (const float*)d_in[17];
    const float* h2_w   = (const float*)d_in[18];
    const float* h2_b   = (const float*)d_in[19];
    float* out = (float*)d_out;

    bf16 *piwh, *piwl, *powh, *powl;
    float2* ptab;
    cudaGetSymbolAddress((void**)&piwh, g_iwh);
    cudaGetSymbolAddress((void**)&piwl, g_iwl);
    cudaGetSymbolAddress((void**)&powh, g_owh);
    cudaGetSymbolAddress((void**)&powl, g_owl);
    cudaGetSymbolAddress((void**)&ptab, g_tab);

    cudaFuncSetAttribute(kernel_g1, cudaFuncAttributeMaxDynamicSharedMemorySize,
                         GEMM_SMEM_DYN);
    cudaFuncSetAttribute(kernel_b, cudaFuncAttributeMaxDynamicSharedMemorySize,
                         GEMM_SMEM_DYN);

    // blocks: BT for embed, 2*NW/256 for weight split, NTAB/256 for A-tables
    emb_split_kernel<<<BT + (2 * NW + NTAB) / 256, 256>>>(
        x, emb_w, emb_b, in_w, out_w, A_p);

    for (int l = 0; l < LL; l++) {
        ln_kernel<<<BT / 8, 256>>>(norm_g + l * DD, norm_b + l * DD);

        kernel_g1<<<512, 256, GEMM_SMEM_DYN>>>(
            piwh + (size_t)l * HH * DD, piwl + (size_t)l * HH * DD);

        kernel_mid<<<GRID_MID, 256>>>(
            conv_w + (size_t)l * HH * 3,
            A_p + (size_t)l * HH * NN, D_p + l * HH,
            ptab + (size_t)l * HH * NN,
            dt1_w + (size_t)l * RR * HH, dt1_b + l * RR,
            dt2_w + (size_t)l * HH * RR, dt2_b + l * HH);

        kernel_b<<<256, 256, GEMM_SMEM_DYN>>>(
            powh + (size_t)l * DD * HH, powl + (size_t)l * DD * HH);
    }

    final_kernel<<<BB, 256>>>(fin_g, fin_b, h1_w, h1_b, h2_w, h2_b, out);
}

// round 14
// speedup vs baseline: 1.9199x; 1.0304x over previous
#include <cuda_runtime.h>
#include <cuda_bf16.h>
#include <cstdint>
#include <math.h>

typedef __nv_bfloat16 bf16;

// ---------------- problem constants ----------------
#define BB   8
#define TT   1024
#define DD   256
#define HH   512
#define NN   16
#define RR   8
#define LL   4
#define BT   (BB*TT)        // 8192
#define BTH  (BB*TT*HH)     // 4194304
#define BTD  (BB*TT*DD)     // 2097152
#define NW   (LL*HH*DD)     // 524288
#define CH   (BB*HH)        // 4096 channels
#define NTAB (LL*HH*NN)     // 32768
#define CK   64             // scan chunk length
#define NCK  (TT/CK)        // 16 chunks per channel

#define GRID_MID 592        // 148 SMs x 4 blocks

// ---------------- scratch (static device globals; no allocation) ----------------
__device__ float g_h  [BTD];
__device__ float g_v  [BTH];        // gemm1 out; reused as scan scratch (float2 summaries)
__device__ float g_vcT[BTH];        // [h][bt]
__device__ float g_dtT[BTH];        // [h][bt]
__device__ float2 g_tab[NTAB];      // per (l,h,n): {A*log2e, 1/A}
__device__ bf16 g_lnh[BTD], g_lnl[BTD];
__device__ bf16 g_yh [BTH], g_yl [BTH];   // [bt][h]
__device__ bf16 g_iwh[NW],  g_iwl[NW];
__device__ bf16 g_owh[NW],  g_owl[NW];

// ---------------- grid-wide barrier: atomic arrive, volatile-load spin ----------------
__device__ unsigned int g_bar_cnt;
__device__ unsigned int g_bar_gen;

__device__ __forceinline__ void grid_barrier() {
    __syncthreads();
    if (threadIdx.x == 0) {
        volatile unsigned int* genp = (volatile unsigned int*)&g_bar_gen;
        unsigned int gen = *genp;
        __threadfence();
        unsigned int arrived = atomicAdd(&g_bar_cnt, 1u);
        if (arrived == gridDim.x - 1) {
            g_bar_cnt = 0;
            __threadfence();
            *genp = gen + 1;
        } else {
            while (*genp == gen) __nanosleep(64);
            __threadfence();
        }
    }
    __syncthreads();
}

// ---------------- helpers ----------------
__device__ __forceinline__ float silu_f(float x) {
    return x / (1.f + __expf(-x));
}

__device__ __forceinline__ float ex2f(float x) {
    float r;
    asm("ex2.approx.ftz.f32 %0, %1;" : "=f"(r) : "f"(x));
    return r;
}

__device__ __forceinline__ void split_bf16(float v, bf16& h, bf16& l) {
    h = __float2bfloat16(v);
    l = __float2bfloat16(v - __bfloat162float(h));
}

__device__ __forceinline__ unsigned int pk2(bf16 a, bf16 b) {
    return (unsigned int)__bfloat16_as_ushort(a) |
           ((unsigned int)__bfloat16_as_ushort(b) << 16);
}

__device__ __forceinline__ void ldsm4(unsigned int r[4], const void* p) {
    unsigned int a = (unsigned int)__cvta_generic_to_shared(p);
    asm volatile("ldmatrix.sync.aligned.m8n8.x4.shared.b16 {%0,%1,%2,%3}, [%4];"
                 : "=r"(r[0]), "=r"(r[1]), "=r"(r[2]), "=r"(r[3]) : "r"(a));
}

__device__ __forceinline__ void mma_bf16(float c[4], const unsigned int a[4],
                                         unsigned int b0, unsigned int b1) {
    asm volatile(
        "mma.sync.aligned.m16n8k16.row.col.f32.bf16.bf16.f32 "
        "{%0,%1,%2,%3},{%4,%5,%6,%7},{%8,%9},{%0,%1,%2,%3};"
        : "+f"(c[0]), "+f"(c[1]), "+f"(c[2]), "+f"(c[3])
        : "r"(a[0]), "r"(a[1]), "r"(a[2]), "r"(a[3]), "r"(b0), "r"(b1));
}

__device__ __forceinline__ void cp16(void* smem, const void* gmem) {
    unsigned int s = (unsigned int)__cvta_generic_to_shared(smem);
    asm volatile("cp.async.cg.shared.global [%0], [%1], 16;" :: "r"(s), "l"(gmem));
}
#define CP_COMMIT()  asm volatile("cp.async.commit_group;")
#define CP_WAIT(n)   asm volatile("cp.async.wait_group %0;" :: "n"(n))

// ---------------- gemm tile: 3-stage cp.async pipeline ----------------
// epilogue mode: 0 = store, 1 = load-add-store, 2 = atomicAdd
#define PADK 40
#define STAGE_BYTES 30720
#define GEMM_SMEM_DYN (3 * STAGE_BYTES)

__device__ void gemm_tile_pipe(char* s_raw,
    const bf16* __restrict__ Ah, const bf16* __restrict__ Al,
    const bf16* __restrict__ Wh, const bf16* __restrict__ Wl,
    float* __restrict__ C, int N, int K, int Klen, int kbase,
    int mode, int bm, int bn)
{
    const int tid  = threadIdx.x;
    const int lane = tid & 31;
    const int wid  = tid >> 5;
    const int wm   = (wid & 3) * 32;
    const int wn   = (wid >> 2) * 32;

    float acc[2][4][4];
    #pragma unroll
    for (int a = 0; a < 2; a++)
        #pragma unroll
        for (int b = 0; b < 4; b++)
            #pragma unroll
            for (int c = 0; c < 4; c++) acc[a][b][c] = 0.f;

    const int lrow = tid >> 2;
    const int lcol = (tid & 3) * 8;

    const int a_row = lane & 15;
    const int a_col = (lane >> 4) << 3;
    const int bq    = lane >> 3;
    const int b_row = (lane & 7) + ((bq >> 1) << 3);
    const int b_col = (bq & 1) << 3;

    const bf16* pAh0 = Ah + (size_t)(bm + lrow) * K + kbase + lcol;
    const bf16* pAh1 = pAh0 + (size_t)64 * K;
    const bf16* pAl0 = Al + (size_t)(bm + lrow) * K + kbase + lcol;
    const bf16* pAl1 = pAl0 + (size_t)64 * K;
    const bf16* pWh  = Wh + (size_t)(bn + lrow) * K + kbase + lcol;
    const bf16* pWl  = Wl + (size_t)(bn + lrow) * K + kbase + lcol;

    const int niter = Klen >> 5;

    auto load_stage = [&](int stage, int kt) {
        char* sb = s_raw + stage * STAGE_BYTES;
        bf16 (*sAh)[PADK] = (bf16(*)[PADK])(sb);
        bf16 (*sAl)[PADK] = (bf16(*)[PADK])(sb + 10240);
        bf16 (*sWh)[PADK] = (bf16(*)[PADK])(sb + 20480);
        bf16 (*sWl)[PADK] = (bf16(*)[PADK])(sb + 25600);
        cp16(&sAh[lrow     ][lcol], pAh0 + kt);
        cp16(&sAh[lrow + 64][lcol], pAh1 + kt);
        cp16(&sAl[lrow     ][lcol], pAl0 + kt);
        cp16(&sAl[lrow + 64][lcol], pAl1 + kt);
        cp16(&sWh[lrow][lcol], pWh + kt);
        cp16(&sWl[lrow][lcol], pWl + kt);
    };

    load_stage(0, 0);
    CP_COMMIT();
    load_stage(1, 32);
    CP_COMMIT();

    int st = 0;
    for (int it = 0; it < niter; it++) {
        if (it + 2 < niter) {
            int s2 = st + 2; if (s2 >= 3) s2 -= 3;
            load_stage(s2, (it + 2) << 5);
            CP_COMMIT();
            CP_WAIT(2);
        } else {
            CP_COMMIT();
            CP_WAIT(2);
        }
        __syncthreads();

        char* sb = s_raw + st * STAGE_BYTES;
        bf16 (*sAh)[PADK] = (bf16(*)[PADK])(sb);
        bf16 (*sAl)[PADK] = (bf16(*)[PADK])(sb + 10240);
        bf16 (*sWh)[PADK] = (bf16(*)[PADK])(sb + 20480);
        bf16 (*sWl)[PADK] = (bf16(*)[PADK])(sb + 25600);

        #pragma unroll
        for (int ks = 0; ks < 2; ks++) {
            const int k0 = ks * 16;
            unsigned int ah[2][4], al[2][4];
            #pragma unroll
            for (int mt = 0; mt < 2; mt++) {
                ldsm4(ah[mt], &sAh[wm + mt * 16 + a_row][k0 + a_col]);
                ldsm4(al[mt], &sAl[wm + mt * 16 + a_row][k0 + a_col]);
            }
            unsigned int bh[2][4], bl[2][4];
            #pragma unroll
            for (int nb = 0; nb < 2; nb++) {
                ldsm4(bh[nb], &sWh[wn + nb * 16 + b_row][k0 + b_col]);
                ldsm4(bl[nb], &sWl[wn + nb * 16 + b_row][k0 + b_col]);
            }
            #pragma unroll
            for (int mt = 0; mt < 2; mt++) {
                #pragma unroll
                for (int nt = 0; nt < 4; nt++) {
                    const int nb = nt >> 1, hf = (nt & 1) * 2;
                    mma_bf16(acc[mt][nt], ah[mt], bh[nb][hf], bh[nb][hf + 1]);
                    mma_bf16(acc[mt][nt], ah[mt], bl[nb][hf], bl[nb][hf + 1]);
                    mma_bf16(acc[mt][nt], al[mt], bh[nb][hf], bh[nb][hf + 1]);
                }
            }
        }
        __syncthreads();
        if (++st == 3) st = 0;
    }

    const int cg = lane >> 2;
    const int ct = (lane & 3) * 2;
    #pragma unroll
    for (int mt = 0; mt < 2; mt++) {
        #pragma unroll
        for (int nt = 0; nt < 4; nt++) {
            int r0 = bm + wm + mt * 16 + cg;
            int c0 = bn + wn + nt * 8 + ct;
            float* p0 = C + (size_t)r0 * N + c0;
            float* p1 = C + (size_t)(r0 + 8) * N + c0;
            if (mode == 2) {
                atomicAdd(p0,     acc[mt][nt][0]);
                atomicAdd(p0 + 1, acc[mt][nt][1]);
                atomicAdd(p1,     acc[mt][nt][2]);
                atomicAdd(p1 + 1, acc[mt][nt][3]);
            } else {
                float2 v0 = make_float2(acc[mt][nt][0], acc[mt][nt][1]);
                float2 v1 = make_float2(acc[mt][nt][2], acc[mt][nt][3]);
                if (mode == 1) {
                    float2 o0 = *(float2*)p0, o1 = *(float2*)p1;
                    v0.x += o0.x; v0.y += o0.y;
                    v1.x += o1.x; v1.y += o1.y;
                }
                *(float2*)p0 = v0; *(float2*)p1 = v1;
            }
        }
    }
}

// ---------------- merged embed + pos-encoding + weight split + A-tables ----------------
__global__ void emb_split_kernel(const float* __restrict__ x,
                                 const float* __restrict__ emb_w,
                                 const float* __restrict__ emb_b,
                                 const float* __restrict__ in_w,
                                 const float* __restrict__ out_w,
                                 const float* __restrict__ A_p) {
    if (blockIdx.x < BT) {
        int bt = blockIdx.x;
        int d  = threadIdx.x;
        __shared__ float sx[32];
        if (d < 32) sx[d] = x[bt * 32 + d];
        __syncthreads();
        float acc = emb_b[d];
        const float* w = emb_w + d * 32;
        #pragma unroll
        for (int i = 0; i < 32; i++) acc = fmaf(sx[i], w[i], acc);
        int t = bt & (TT - 1);
        int k2 = d & ~1;
        float div = __expf((float)k2 * (-9.210340371976184f / 256.0f));
        float ang = (float)t * div;
        acc += (d & 1) ? cosf(ang) : sinf(ang);
        g_h[bt * DD + d] = acc;
    } else {
        int i = (blockIdx.x - BT) * 256 + threadIdx.x;
        if (i < NW) {
            split_bf16(in_w[i], g_iwh[i], g_iwl[i]);
        } else if (i < 2 * NW) {
            int j = i - NW;
            split_bf16(out_w[j], g_owh[j], g_owl[j]);
        } else {
            int j = i - 2 * NW;
            if (j < NTAB) {
                float A = -__expf(A_p[j]);
                float iA = (fabsf(A) < 1e-5f) ? 1.f : (1.f / A);
                g_tab[j] = make_float2(A * 1.4426950408889634f, iA);
            }
        }
    }
}

// ---------------- LN kernel (warp per row) ----------------
__global__ __launch_bounds__(256) void ln_kernel(
    const float* __restrict__ ng, const float* __restrict__ nb_)
{
    const int lane = threadIdx.x & 31;
    const int row  = blockIdx.x * 8 + (threadIdx.x >> 5);
    const float* p = g_h + (size_t)row * DD + lane * 8;
    float4 a = *(const float4*)p;
    float4 c = *(const float4*)(p + 4);
    float v[8] = {a.x, a.y, a.z, a.w, c.x, c.y, c.z, c.w};
    float s = 0.f;
    #pragma unroll
    for (int j = 0; j < 8; j++) s += v[j];
    #pragma unroll
    for (int o = 16; o; o >>= 1) s += __shfl_xor_sync(0xffffffffu, s, o);
    float mean = s * (1.f / 256.f);
    float vv = 0.f;
    #pragma unroll
    for (int j = 0; j < 8; j++) { float d0 = v[j] - mean; vv += d0 * d0; }
    #pragma unroll
    for (int o = 16; o; o >>= 1) vv += __shfl_xor_sync(0xffffffffu, vv, o);
    float rstd = rsqrtf(vv * (1.f / 256.f) + 1e-5f);
    float4 gg0 = *(const float4*)(ng + lane * 8);
    float4 gg1 = *(const float4*)(ng + lane * 8 + 4);
    float4 bb0 = *(const float4*)(nb_ + lane * 8);
    float4 bb1 = *(const float4*)(nb_ + lane * 8 + 4);
    float gv[8] = {gg0.x, gg0.y, gg0.z, gg0.w, gg1.x, gg1.y, gg1.z, gg1.w};
    float bv[8] = {bb0.x, bb0.y, bb0.z, bb0.w, bb1.x, bb1.y, bb1.z, bb1.w};
    bf16 oh[8], ol[8];
    #pragma unroll
    for (int j = 0; j < 8; j++) {
        float o = (v[j] - mean) * rstd * gv[j] + bv[j];
        split_bf16(o, oh[j], ol[j]);
    }
    uint4 uh, ul;
    uh.x = pk2(oh[0], oh[1]); uh.y = pk2(oh[2], oh[3]);
    uh.z = pk2(oh[4], oh[5]); uh.w = pk2(oh[6], oh[7]);
    ul.x = pk2(ol[0], ol[1]); ul.y = pk2(ol[2], ol[3]);
    ul.z = pk2(ol[4], ol[5]); ul.w = pk2(ol[6], ol[7]);
    *(uint4*)(g_lnh + (size_t)row * DD + lane * 8) = uh;
    *(uint4*)(g_lnl + (size_t)row * DD + lane * 8) = ul;
}

// ---------------- gemm1: 512 blocks, 1 tile each ----------------
__global__ __launch_bounds__(256, 2) void kernel_g1(
    const bf16* __restrict__ iwh, const bf16* __restrict__ iwl)
{
    extern __shared__ __align__(16) char s_dyn[];
    const int t = blockIdx.x;
    gemm_tile_pipe(s_dyn, g_lnh, g_lnl, iwh, iwl, g_v, HH, DD, DD, 0,
                   0, (t >> 3) * 128, (t & 7) * 64);
}

// ---------------- gemm2: split-K x2, 512 blocks ----------------
__global__ __launch_bounds__(256, 2) void kernel_b(
    const bf16* __restrict__ owh, const bf16* __restrict__ owl)
{
    extern __shared__ __align__(16) char s_dyn[];
    const int t    = blockIdx.x;     // 512 = 256 tiles x 2 K-halves
    const int tile = t >> 1;
    const int half = t & 1;
    gemm_tile_pipe(s_dyn, g_yh, g_yl, owh, owl, g_h, DD, HH, HH / 2, half * (HH / 2),
                   2, (tile >> 2) * 128, (tile & 3) * 64);
}

// ---------------- kernel MID: conv + dt + scan (64-reg class, 4 blk/SM) ----------------
#define MID_SMEM 32768
__global__ __launch_bounds__(256, 4) void kernel_mid(
    const float* __restrict__ cw,
    const float* __restrict__ Apw, const float* __restrict__ Dpw,
    const float2* __restrict__ tab,
    const float* __restrict__ w1,  const float* __restrict__ b1,
    const float* __restrict__ w2,  const float* __restrict__ b2)
{
    __shared__ __align__(16) char s_raw[MID_SMEM];
    const int bid = blockIdx.x;
    const int nbk = gridDim.x;
    const int tid = threadIdx.x;
    const int lane = tid & 31;
    const int warp = tid >> 5;

    // ---- conv(k=3)+silu+transpose: g_v[bt][h] -> g_vcT[h][bt] (4096 tasks) ----
    {
        float (*tile)[33] = (float(*)[33])(s_raw);
        for (int task = bid; task < BB * 16 * 32; task += nbk) {
            const int b  = task >> 9;
            const int h0 = ((task >> 5) & 15) * 32;
            const int t0 = (task & 31) * 32;
            #pragma unroll
            for (int i = tid; i < 34 * 32; i += 256) {
                int tt = i >> 5;
                int hh = i & 31;
                int t  = t0 + tt - 1;
                float v = 0.f;
                if (t >= 0 && t < TT)
                    v = g_v[((size_t)b * TT + t) * HH + h0 + hh];
                tile[tt][hh] = v;
            }
            __syncthreads();
            const int tl = tid & 31;
            const int hq = tid >> 5;
            #pragma unroll
            for (int j = 0; j < 4; j++) {
                int hh = hq * 4 + j;
                int h  = h0 + hh;
                float w0 = cw[h * 3 + 0], w1v = cw[h * 3 + 1], w2v = cw[h * 3 + 2];
                float acc = tile[tl][hh] * w0;
                acc = fmaf(tile[tl + 1][hh], w1v, acc);
                acc = fmaf(tile[tl + 2][hh], w2v, acc);
                g_vcT[(size_t)h * BT + b * TT + t0 + tl] = silu_f(acc);
            }
            __syncthreads();
        }
    }
    grid_barrier();

    // ---- dt1 + dt2 fused -> g_dtT[h][bt] (512 tasks of 16 bt) ----
    {
        float (*red)[16][9] = (float(*)[16][9])(s_raw);
        float (*dtrs)[9]    = (float(*)[9])(s_raw + 8640);
        const int btl = tid & 15;
        const int q   = tid >> 4;
        for (int task = bid; task < BT / 16; task += nbk) {
            const int bt0 = task * 16;
            float acc[RR];
            #pragma unroll
            for (int r = 0; r < RR; r++) acc[r] = 0.f;
            const int hbase = q * 32;
            #pragma unroll 4
            for (int hh = 0; hh < 32; hh++) {
                int h = hbase + hh;
                float v = g_vcT[(size_t)h * BT + bt0 + btl];
                #pragma unroll
                for (int r = 0; r < RR; r++) acc[r] = fmaf(v, w1[r * HH + h], acc[r]);
            }
            if (q > 0) {
                #pragma unroll
                for (int r = 0; r < RR; r++) red[q - 1][btl][r] = acc[r];
            }
            __syncthreads();
            if (q == 0) {
                #pragma unroll
                for (int r = 0; r < RR; r++) {
                    float s = acc[r] + b1[r];
                    #pragma unroll
                    for (int g = 0; g < 15; g++) s += red[g][btl][r];
                    dtrs[btl][r] = fmaxf(s, 0.f);
                }
            }
            __syncthreads();
            #pragma unroll 4
            for (int hh = q; hh < HH; hh += 16) {
                float wreg[RR];
                #pragma unroll
                for (int r = 0; r < RR; r++) wreg[r] = w2[hh * RR + r];
                float a2 = b2[hh];
                #pragma unroll
                for (int r = 0; r < RR; r++) a2 = fmaf(dtrs[btl][r], wreg[r], a2);
                float sp = (a2 > 15.f) ? a2 : log1pf(__expf(a2));
                g_dtT[(size_t)hh * BT + bt0 + btl] = sp;
            }
            __syncthreads();
        }
    }
    grid_barrier();

    // ---- scan pass 1: chunk summaries (P, e), CK=64, 4096 warp-tasks ----
    {
        float2* scr = (float2*)g_v;
        const int u = lane >> 1;
        const int p = lane & 1;
        for (int wt = bid * 8 + warp; wt < BB * 32 * NCK; wt += nbk * 8) {
            const int b  = wt / (32 * NCK);
            const int hb = (wt / NCK) & 31;
            const int ck = wt & (NCK - 1);
            const int h  = hb * 16 + u;
            const int ch = b * HH + h;
            float A2[8], iA[8];
            const float2* tp = tab + h * NN + p * 8;
            #pragma unroll
            for (int j = 0; j < 8; j += 2) {
                float4 tv = *(const float4*)(tp + j);
                A2[j] = tv.x; iA[j] = tv.y;
                A2[j + 1] = tv.z; iA[j + 1] = tv.w;
            }
            const float* xr = g_vcT + (size_t)h * BT + b * TT + ck * CK;
            const float* dr = g_dtT + (size_t)h * BT + b * TT + ck * CK;
            float s[8];
            #pragma unroll
            for (int j = 0; j < 8; j++) s[j] = 0.f;
            float sdt = 0.f;
            float4 xv = *(const float4*)xr;
            float4 dv = *(const float4*)dr;
            #pragma unroll 4
            for (int t4 = 0; t4 < CK; t4 += 4) {
                float4 xn, dn;
                if (t4 < CK - 4) {
                    xn = *(const float4*)(xr + t4 + 4);
                    dn = *(const float4*)(dr + t4 + 4);
                }
                #pragma unroll
                for (int k = 0; k < 4; k++) {
                    float x   = ((const float*)&xv)[k];
                    float dtv = ((const float*)&dv)[k];
                    float c = dtv * x;
                    sdt += dtv;
                    #pragma unroll
                    for (int j = 0; j < 8; j++) {
                        float dA = ex2f(A2[j] * dtv);
                        float e  = iA[j] * c;
                        s[j] = fmaf(dA, s[j] + e, -e);
                    }
                }
                xv = xn; dv = dn;
            }
            float2* out = scr + ((size_t)ch * NCK + ck) * 16 + p * 8;
            #pragma unroll
            for (int j = 0; j < 8; j++)
                out[j] = make_float2(ex2f(A2[j] * sdt), s[j]);
        }
    }
    grid_barrier();

    // ---- scan pass 2: serial carry per (ch, n), NCK steps ----
    {
        float2* scr = (float2*)g_v;
        for (int i = bid * 256 + tid; i < CH * NN; i += nbk * 256) {
            float2* base = scr + ((size_t)(i >> 4) * NCK) * 16 + (i & 15);
            float c = 0.f;
            #pragma unroll
            for (int j = 0; j < NCK; j++) {
                float2 s = base[(size_t)j * 16];
                base[(size_t)j * 16].x = c;
                c = fmaf(s.x, c, s.y);
            }
        }
    }
    grid_barrier();

    // ---- scan pass 3: re-scan with carry init, emit y (CK=64) ----
    {
        float2* scr = (float2*)g_v;
        bf16 (*s_yh)[16] = (bf16(*)[16])(s_raw + warp * 4096);
        bf16 (*s_yl)[16] = (bf16(*)[16])(s_raw + warp * 4096 + 2048);
        const int u = lane >> 1;
        const int p = lane & 1;
        for (int wt = bid * 8 + warp; wt < BB * 32 * NCK; wt += nbk * 8) {
            const int b  = wt / (32 * NCK);
            const int hb = (wt / NCK) & 31;
            const int ck = wt & (NCK - 1);
            const int h  = hb * 16 + u;
            const int ch = b * HH + h;
            float A2[8], iA[8], Apv[8];
            const float2* tp = tab + h * NN + p * 8;
            #pragma unroll
            for (int j = 0; j < 8; j += 2) {
                float4 tv = *(const float4*)(tp + j);
                A2[j] = tv.x; iA[j] = tv.y;
                A2[j + 1] = tv.z; iA[j + 1] = tv.w;
            }
            const float* app = Apw + h * NN + p * 8;
            #pragma unroll
            for (int j = 0; j < 8; j += 4) {
                float4 av = *(const float4*)(app + j);
                Apv[j] = av.x; Apv[j + 1] = av.y;
                Apv[j + 2] = av.z; Apv[j + 3] = av.w;
            }
            float Dp = Dpw[h];
            const float* xr = g_vcT + (size_t)h * BT + b * TT + ck * CK;
            const float* dr = g_dtT + (size_t)h * BT + b * TT + ck * CK;
            const float2* cin = scr + ((size_t)ch * NCK + ck) * 16 + p * 8;
            float s[8];
            #pragma unroll
            for (int j = 0; j < 8; j++) s[j] = cin[j].x;
            float4 xv = *(const float4*)xr;
            float4 dv = *(const float4*)dr;
            #pragma unroll 4
            for (int t4 = 0; t4 < CK; t4 += 4) {
                float4 xn, dn;
                if (t4 < CK - 4) {
                    xn = *(const float4*)(xr + t4 + 4);
                    dn = *(const float4*)(dr + t4 + 4);
                }
                #pragma unroll
                for (int k = 0; k < 4; k++) {
                    float x   = ((const float*)&xv)[k];
                    float dtv = ((const float*)&dv)[k];
                    float c = dtv * x;
                    float part = 0.f;
                    #pragma unroll
                    for (int j = 0; j < 8; j++) {
                        float dA = ex2f(A2[j] * dtv);
                        float e  = iA[j] * c;
                        s[j] = fmaf(dA, s[j] + e, -e);
                        part = fmaf(Apv[j], s[j], part);
                    }
                    part += __shfl_xor_sync(0xffffffffu, part, 1);
                    if (p == 0) {
                        float y = fmaf(Dp, x, part);
                        bf16 hh_, ll_;
                        split_bf16(y, hh_, ll_);
                        s_yh[t4 + k][u] = hh_;
                        s_yl[t4 + k][u] = ll_;
                    }
                }
                xv = xn; dv = dn;
            }
            __syncwarp();
            {
                // flush 64 rows x 16 ch: each lane handles rows lane and lane+32
                size_t rb0 = (size_t)(b * TT + ck * CK + lane) * HH + hb * 16;
                size_t rb1 = (size_t)(b * TT + ck * CK + lane + 32) * HH + hb * 16;
                uint4* sh0 = (uint4*)&s_yh[lane][0];
                uint4* sl0 = (uint4*)&s_yl[lane][0];
                uint4* sh1 = (uint4*)&s_yh[lane + 32][0];
                uint4* sl1 = (uint4*)&s_yl[lane + 32][0];
                *(uint4*)(g_yh + rb0)     = sh0[0];
                *(uint4*)(g_yh + rb0 + 8) = sh0[1];
                *(uint4*)(g_yl + rb0)     = sl0[0];
                *(uint4*)(g_yl + rb0 + 8) = sl0[1];
                *(uint4*)(g_yh + rb1)     = sh1[0];
                *(uint4*)(g_yh + rb1 + 8) = sh1[1];
                *(uint4*)(g_yl + rb1)     = sl1[0];
                *(uint4*)(g_yl + rb1 + 8) = sl1[1];
            }
            __syncwarp();
        }
    }
}

// ---------------- final LN (last token) + head1(silu) + head2 ----------------
__global__ void final_kernel(const float* __restrict__ fg,
                             const float* __restrict__ fb,
                             const float* __restrict__ w1,
                             const float* __restrict__ b1,
                             const float* __restrict__ w2,
                             const float* __restrict__ b2,
                             float* __restrict__ out) {
    int b = blockIdx.x;
    int tid = threadIdx.x;
    __shared__ float red1[8], red2[8];
    __shared__ float s_ln[DD];
    __shared__ float s_h1[DD];
    const float* row = g_h + (size_t)(b * TT + (TT - 1)) * DD;
    float v = row[tid];
    float s = v;
    #pragma unroll
    for (int o = 16; o; o >>= 1) s += __shfl_xor_sync(0xffffffffu, s, o);
    if ((tid & 31) == 0) red1[tid >> 5] = s;
    __syncthreads();
    float mean = 0.f;
    #pragma unroll
    for (int i = 0; i < 8; i++) mean += red1[i];
    mean *= (1.f / 256.f);
    float c = v - mean;
    float cc = c * c;
    #pragma unroll
    for (int o = 16; o; o >>= 1) cc += __shfl_xor_sync(0xffffffffu, cc, o);
    if ((tid & 31) == 0) red2[tid >> 5] = cc;
    __syncthreads();
    float var = 0.f;
    #pragma unroll
    for (int i = 0; i < 8; i++) var += red2[i];
    var *= (1.f / 256.f);
    s_ln[tid] = c * rsqrtf(var + 1e-5f) * fg[tid] + fb[tid];
    __syncthreads();
    float acc = b1[tid];
    const float* w1r = w1 + tid * DD;
    #pragma unroll 8
    for (int k = 0; k < DD; k++) acc = fmaf(s_ln[k], w1r[k], acc);
    s_h1[tid] = silu_f(acc);
    __syncthreads();
    if (tid < 96) {
        float a2 = b2[tid];
        const float* w2r = w2 + tid * DD;
        #pragma unroll 8
        for (int k = 0; k < DD; k++) a2 = fmaf(s_h1[k], w2r[k], a2);
        out[b * 96 + tid] = a2;
    }
}

// ---------------- launcher: 18 graph nodes ----------------
extern "C" void kernel_launch(void* const* d_in, const int* in_sizes, int n_in,
                              void* d_out, int out_size) {
    const float* x      = (const float*)d_in[0];
    const float* emb_w  = (const float*)d_in[1];
    const float* emb_b  = (const float*)d_in[2];
    const float* norm_g = (const float*)d_in[3];
    const float* norm_b = (const float*)d_in[4];
    const float* in_w   = (const float*)d_in[5];
    const float* conv_w = (const float*)d_in[6];
    const float* A_p    = (const float*)d_in[7];
    const float* D_p    = (const float*)d_in[8];
    const float* dt1_w  = (const float*)d_in[9];
    const float* dt1_b  = (const float*)d_in[10];
    const float* dt2_w  = (const float*)d_in[11];
    const float* dt2_b  = (const float*)d_in[12];
    const float* out_w  = (const float*)d_in[13];
    const float* fin_g  = (const float*)d_in[14];
    const float* fin_b  = (const float*)d_in[15];
    const float* h1_w   = (const float*)d_in[16];
    const float* h1_b   = (const float*)d_in[17];
    const float* h2_w   = (const float*)d_in[18];
    const float* h2_b   = (const float*)d_in[19];
    float* out = (float*)d_out;

    bf16 *piwh, *piwl, *powh, *powl;
    float2* ptab;
    cudaGetSymbolAddress((void**)&piwh, g_iwh);
    cudaGetSymbolAddress((void**)&piwl, g_iwl);
    cudaGetSymbolAddress((void**)&powh, g_owh);
    cudaGetSymbolAddress((void**)&powl, g_owl);
    cudaGetSymbolAddress((void**)&ptab, g_tab);

    cudaFuncSetAttribute(kernel_g1, cudaFuncAttributeMaxDynamicSharedMemorySize,
                         GEMM_SMEM_DYN);
    cudaFuncSetAttribute(kernel_b, cudaFuncAttributeMaxDynamicSharedMemorySize,
                         GEMM_SMEM_DYN);

    emb_split_kernel<<<BT + (2 * NW + NTAB) / 256, 256>>>(
        x, emb_w, emb_b, in_w, out_w, A_p);

    for (int l = 0; l < LL; l++) {
        ln_kernel<<<BT / 8, 256>>>(norm_g + l * DD, norm_b + l * DD);

        kernel_g1<<<512, 256, GEMM_SMEM_DYN>>>(
            piwh + (size_t)l * HH * DD, piwl + (size_t)l * HH * DD);

        kernel_mid<<<GRID_MID, 256>>>(
            conv_w + (size_t)l * HH * 3,
            A_p + (size_t)l * HH * NN, D_p + l * HH,
            ptab + (size_t)l * HH * NN,
            dt1_w + (size_t)l * RR * HH, dt1_b + l * RR,
            dt2_w + (size_t)l * HH * RR, dt2_b + l * HH);

        kernel_b<<<512, 256, GEMM_SMEM_DYN>>>(
            powh + (size_t)l * DD * HH, powl + (size_t)l * DD * HH);
    }

    final_kernel<<<BB, 256>>>(fin_g, fin_b, h1_w, h1_b, h2_w, h2_b, out);
}

// round 16
// speedup vs baseline: 2.0480x; 1.0667x over previous
#include <cuda_runtime.h>
#include <cuda_bf16.h>
#include <cstdint>
#include <math.h>

typedef __nv_bfloat16 bf16;

// ---------------- problem constants ----------------
#define BB   8
#define TT   1024
#define DD   256
#define HH   512
#define NN   16
#define RR   8
#define LL   4
#define BT   (BB*TT)        // 8192
#define BTH  (BB*TT*HH)     // 4194304
#define BTD  (BB*TT*DD)     // 2097152
#define NW   (LL*HH*DD)     // 524288
#define CH   (BB*HH)        // 4096 channels
#define NTAB (LL*HH*NN)     // 32768
#define CK   64             // scan chunk length
#define NCK  (TT/CK)        // 16 chunks per channel

#define GRID_MID 592        // 148 SMs x 4 blocks

// ---------------- scratch (static device globals; no allocation) ----------------
__device__ float g_h  [BTD];
__device__ float g_v  [BTH];        // gemm1 out [h][bt]; later reused as scan scratch
__device__ float g_vcT[BTH];        // [h][bt]
__device__ float g_dtT[BTH];        // [h][bt]
__device__ float2 g_tab[NTAB];      // per (l,h,n): {A*log2e, Ap/A}
__device__ bf16 g_lnh[BTD], g_lnl[BTD];
__device__ bf16 g_yh [BTH], g_yl [BTH];   // [bt][h]
__device__ bf16 g_iwh[NW],  g_iwl[NW];
__device__ bf16 g_owh[NW],  g_owl[NW];

// ---------------- grid-wide barrier: atomic arrive, volatile-load spin ----------------
__device__ unsigned int g_bar_cnt;
__device__ unsigned int g_bar_gen;

__device__ __forceinline__ void grid_barrier() {
    __syncthreads();
    if (threadIdx.x == 0) {
        volatile unsigned int* genp = (volatile unsigned int*)&g_bar_gen;
        unsigned int gen = *genp;
        __threadfence();
        unsigned int arrived = atomicAdd(&g_bar_cnt, 1u);
        if (arrived == gridDim.x - 1) {
            g_bar_cnt = 0;
            __threadfence();
            *genp = gen + 1;
        } else {
            while (*genp == gen) __nanosleep(64);
            __threadfence();
        }
    }
    __syncthreads();
}

// ---------------- helpers ----------------
__device__ __forceinline__ float silu_f(float x) {
    return x / (1.f + __expf(-x));
}

__device__ __forceinline__ float ex2f(float x) {
    float r;
    asm("ex2.approx.ftz.f32 %0, %1;" : "=f"(r) : "f"(x));
    return r;
}

__device__ __forceinline__ void split_bf16(float v, bf16& h, bf16& l) {
    h = __float2bfloat16(v);
    l = __float2bfloat16(v - __bfloat162float(h));
}

__device__ __forceinline__ unsigned int pk2(bf16 a, bf16 b) {
    return (unsigned int)__bfloat16_as_ushort(a) |
           ((unsigned int)__bfloat16_as_ushort(b) << 16);
}

__device__ __forceinline__ void ldsm4(unsigned int r[4], const void* p) {
    unsigned int a = (unsigned int)__cvta_generic_to_shared(p);
    asm volatile("ldmatrix.sync.aligned.m8n8.x4.shared.b16 {%0,%1,%2,%3}, [%4];"
                 : "=r"(r[0]), "=r"(r[1]), "=r"(r[2]), "=r"(r[3]) : "r"(a));
}

__device__ __forceinline__ void mma_bf16(float c[4], const unsigned int a[4],
                                         unsigned int b0, unsigned int b1) {
    asm volatile(
        "mma.sync.aligned.m16n8k16.row.col.f32.bf16.bf16.f32 "
        "{%0,%1,%2,%3},{%4,%5,%6,%7},{%8,%9},{%0,%1,%2,%3};"
        : "+f"(c[0]), "+f"(c[1]), "+f"(c[2]), "+f"(c[3])
        : "r"(a[0]), "r"(a[1]), "r"(a[2]), "r"(a[3]), "r"(b0), "r"(b1));
}

__device__ __forceinline__ void cp16(void* smem, const void* gmem) {
    unsigned int s = (unsigned int)__cvta_generic_to_shared(smem);
    asm volatile("cp.async.cg.shared.global [%0], [%1], 16;" :: "r"(s), "l"(gmem));
}
#define CP_COMMIT()  asm volatile("cp.async.commit_group;")
#define CP_WAIT(n)   asm volatile("cp.async.wait_group %0;" :: "n"(n))

// ---------------- gemm tile: 3-stage cp.async pipeline ----------------
// mode: 0 = store, 1 = load-add-store, 2 = atomicAdd, 3 = transposed store (ld = BT)
#define PADK 40
#define STAGE_BYTES 30720
#define GEMM_SMEM_DYN (3 * STAGE_BYTES)
#define TPAD 132   // transpose tile row stride (multiple of 4 -> 16B-aligned rows)

__device__ void gemm_tile_pipe(char* s_raw,
    const bf16* __restrict__ Ah, const bf16* __restrict__ Al,
    const bf16* __restrict__ Wh, const bf16* __restrict__ Wl,
    float* __restrict__ C, int N, int K, int Klen, int kbase,
    int mode, int bm, int bn)
{
    const int tid  = threadIdx.x;
    const int lane = tid & 31;
    const int wid  = tid >> 5;
    const int wm   = (wid & 3) * 32;
    const int wn   = (wid >> 2) * 32;

    float acc[2][4][4];
    #pragma unroll
    for (int a = 0; a < 2; a++)
        #pragma unroll
        for (int b = 0; b < 4; b++)
            #pragma unroll
            for (int c = 0; c < 4; c++) acc[a][b][c] = 0.f;

    const int lrow = tid >> 2;
    const int lcol = (tid & 3) * 8;

    const int a_row = lane & 15;
    const int a_col = (lane >> 4) << 3;
    const int bq    = lane >> 3;
    const int b_row = (lane & 7) + ((bq >> 1) << 3);
    const int b_col = (bq & 1) << 3;

    const bf16* pAh0 = Ah + (size_t)(bm + lrow) * K + kbase + lcol;
    const bf16* pAh1 = pAh0 + (size_t)64 * K;
    const bf16* pAl0 = Al + (size_t)(bm + lrow) * K + kbase + lcol;
    const bf16* pAl1 = pAl0 + (size_t)64 * K;
    const bf16* pWh  = Wh + (size_t)(bn + lrow) * K + kbase + lcol;
    const bf16* pWl  = Wl + (size_t)(bn + lrow) * K + kbase + lcol;

    const int niter = Klen >> 5;

    auto load_stage = [&](int stage, int kt) {
        char* sb = s_raw + stage * STAGE_BYTES;
        bf16 (*sAh)[PADK] = (bf16(*)[PADK])(sb);
        bf16 (*sAl)[PADK] = (bf16(*)[PADK])(sb + 10240);
        bf16 (*sWh)[PADK] = (bf16(*)[PADK])(sb + 20480);
        bf16 (*sWl)[PADK] = (bf16(*)[PADK])(sb + 25600);
        cp16(&sAh[lrow     ][lcol], pAh0 + kt);
        cp16(&sAh[lrow + 64][lcol], pAh1 + kt);
        cp16(&sAl[lrow     ][lcol], pAl0 + kt);
        cp16(&sAl[lrow + 64][lcol], pAl1 + kt);
        cp16(&sWh[lrow][lcol], pWh + kt);
        cp16(&sWl[lrow][lcol], pWl + kt);
    };

    load_stage(0, 0);
    CP_COMMIT();
    load_stage(1, 32);
    CP_COMMIT();

    int st = 0;
    for (int it = 0; it < niter; it++) {
        if (it + 2 < niter) {
            int s2 = st + 2; if (s2 >= 3) s2 -= 3;
            load_stage(s2, (it + 2) << 5);
            CP_COMMIT();
            CP_WAIT(2);
        } else {
            CP_COMMIT();
            CP_WAIT(2);
        }
        __syncthreads();

        char* sb = s_raw + st * STAGE_BYTES;
        bf16 (*sAh)[PADK] = (bf16(*)[PADK])(sb);
        bf16 (*sAl)[PADK] = (bf16(*)[PADK])(sb + 10240);
        bf16 (*sWh)[PADK] = (bf16(*)[PADK])(sb + 20480);
        bf16 (*sWl)[PADK] = (bf16(*)[PADK])(sb + 25600);

        #pragma unroll
        for (int ks = 0; ks < 2; ks++) {
            const int k0 = ks * 16;
            unsigned int ah[2][4], al[2][4];
            #pragma unroll
            for (int mt = 0; mt < 2; mt++) {
                ldsm4(ah[mt], &sAh[wm + mt * 16 + a_row][k0 + a_col]);
                ldsm4(al[mt], &sAl[wm + mt * 16 + a_row][k0 + a_col]);
            }
            unsigned int bh[2][4], bl[2][4];
            #pragma unroll
            for (int nb = 0; nb < 2; nb++) {
                ldsm4(bh[nb], &sWh[wn + nb * 16 + b_row][k0 + b_col]);
                ldsm4(bl[nb], &sWl[wn + nb * 16 + b_row][k0 + b_col]);
            }
            #pragma unroll
            for (int mt = 0; mt < 2; mt++) {
                #pragma unroll
                for (int nt = 0; nt < 4; nt++) {
                    const int nb = nt >> 1, hf = (nt & 1) * 2;
                    mma_bf16(acc[mt][nt], ah[mt], bh[nb][hf], bh[nb][hf + 1]);
                    mma_bf16(acc[mt][nt], ah[mt], bl[nb][hf], bl[nb][hf + 1]);
                    mma_bf16(acc[mt][nt], al[mt], bh[nb][hf], bh[nb][hf + 1]);
                }
            }
        }
        __syncthreads();
        if (++st == 3) st = 0;
    }

    const int cg = lane >> 2;
    const int ct = (lane & 3) * 2;

    if (mode == 3) {
        // transposed store: C treated as [N_total rows][BT], write tile [64][128]
        float (*tp)[TPAD] = (float(*)[TPAD])s_raw;   // 64 x 132 floats, rows 16B-aligned
        #pragma unroll
        for (int mt = 0; mt < 2; mt++) {
            #pragma unroll
            for (int nt = 0; nt < 4; nt++) {
                int r0 = wm + mt * 16 + cg;
                int c0 = wn + nt * 8 + ct;
                tp[c0    ][r0    ] = acc[mt][nt][0];
                tp[c0 + 1][r0    ] = acc[mt][nt][1];
                tp[c0    ][r0 + 8] = acc[mt][nt][2];
                tp[c0 + 1][r0 + 8] = acc[mt][nt][3];
            }
        }
        __syncthreads();
        const int c  = tid >> 2;          // 0..63 output row (h)
        const int cb = (tid & 3) * 4;     // 0,4,8,12
        float* dst = C + (size_t)(bn + c) * BT + bm;
        const float* src = tp[c];
        #pragma unroll
        for (int i = 0; i < 8; i++) {
            int col = cb + i * 16;
            *(float4*)(dst + col) = *(const float4*)(src + col);
        }
        return;
    }

    #pragma unroll
    for (int mt = 0; mt < 2; mt++) {
        #pragma unroll
        for (int nt = 0; nt < 4; nt++) {
            int r0 = bm + wm + mt * 16 + cg;
            int c0 = bn + wn + nt * 8 + ct;
            float* p0 = C + (size_t)r0 * N + c0;
            float* p1 = C + (size_t)(r0 + 8) * N + c0;
            if (mode == 2) {
                atomicAdd(p0,     acc[mt][nt][0]);
                atomicAdd(p0 + 1, acc[mt][nt][1]);
                atomicAdd(p1,     acc[mt][nt][2]);
                atomicAdd(p1 + 1, acc[mt][nt][3]);
            } else {
                float2 v0 = make_float2(acc[mt][nt][0], acc[mt][nt][1]);
                float2 v1 = make_float2(acc[mt][nt][2], acc[mt][nt][3]);
                if (mode == 1) {
                    float2 o0 = *(float2*)p0, o1 = *(float2*)p1;
                    v0.x += o0.x; v0.y += o0.y;
                    v1.x += o1.x; v1.y += o1.y;
                }
                *(float2*)p0 = v0; *(float2*)p1 = v1;
            }
        }
    }
}

// ---------------- merged embed + pos-encoding + weight split + tables ----------------
__global__ void emb_split_kernel(const float* __restrict__ x,
                                 const float* __restrict__ emb_w,
                                 const float* __restrict__ emb_b,
                                 const float* __restrict__ in_w,
                                 const float* __restrict__ out_w,
                                 const float* __restrict__ A_p) {
    if (blockIdx.x < BT) {
        int bt = blockIdx.x;
        int d  = threadIdx.x;
        __shared__ float sx[32];
        if (d < 32) sx[d] = x[bt * 32 + d];
        __syncthreads();
        float acc = emb_b[d];
        const float* w = emb_w + d * 32;
        #pragma unroll
        for (int i = 0; i < 32; i++) acc = fmaf(sx[i], w[i], acc);
        int t = bt & (TT - 1);
        int k2 = d & ~1;
        float div = __expf((float)k2 * (-9.210340371976184f / 256.0f));
        float ang = (float)t * div;
        acc += (d & 1) ? cosf(ang) : sinf(ang);
        g_h[bt * DD + d] = acc;
    } else {
        int i = (blockIdx.x - BT) * 256 + threadIdx.x;
        if (i < NW) {
            split_bf16(in_w[i], g_iwh[i], g_iwl[i]);
        } else if (i < 2 * NW) {
            int j = i - NW;
            split_bf16(out_w[j], g_owh[j], g_owl[j]);
        } else {
            int j = i - 2 * NW;
            if (j < NTAB) {
                float Ap = A_p[j];
                float A = -__expf(Ap);
                float iA = (fabsf(A) < 1e-5f) ? 1.f : (1.f / A);
                g_tab[j] = make_float2(A * 1.4426950408889634f, Ap * iA);
            }
        }
    }
}

// ---------------- LN kernel (warp per row) ----------------
__global__ __launch_bounds__(256) void ln_kernel(
    const float* __restrict__ ng, const float* __restrict__ nb_)
{
    const int lane = threadIdx.x & 31;
    const int row  = blockIdx.x * 8 + (threadIdx.x >> 5);
    const float* p = g_h + (size_t)row * DD + lane * 8;
    float4 a = *(const float4*)p;
    float4 c = *(const float4*)(p + 4);
    float v[8] = {a.x, a.y, a.z, a.w, c.x, c.y, c.z, c.w};
    float s = 0.f;
    #pragma unroll
    for (int j = 0; j < 8; j++) s += v[j];
    #pragma unroll
    for (int o = 16; o; o >>= 1) s += __shfl_xor_sync(0xffffffffu, s, o);
    float mean = s * (1.f / 256.f);
    float vv = 0.f;
    #pragma unroll
    for (int j = 0; j < 8; j++) { float d0 = v[j] - mean; vv += d0 * d0; }
    #pragma unroll
    for (int o = 16; o; o >>= 1) vv += __shfl_xor_sync(0xffffffffu, vv, o);
    float rstd = rsqrtf(vv * (1.f / 256.f) + 1e-5f);
    float4 gg0 = *(const float4*)(ng + lane * 8);
    float4 gg1 = *(const float4*)(ng + lane * 8 + 4);
    float4 bb0 = *(const float4*)(nb_ + lane * 8);
    float4 bb1 = *(const float4*)(nb_ + lane * 8 + 4);
    float gv[8] = {gg0.x, gg0.y, gg0.z, gg0.w, gg1.x, gg1.y, gg1.z, gg1.w};
    float bv[8] = {bb0.x, bb0.y, bb0.z, bb0.w, bb1.x, bb1.y, bb1.z, bb1.w};
    bf16 oh[8], ol[8];
    #pragma unroll
    for (int j = 0; j < 8; j++) {
        float o = (v[j] - mean) * rstd * gv[j] + bv[j];
        split_bf16(o, oh[j], ol[j]);
    }
    uint4 uh, ul;
    uh.x = pk2(oh[0], oh[1]); uh.y = pk2(oh[2], oh[3]);
    uh.z = pk2(oh[4], oh[5]); uh.w = pk2(oh[6], oh[7]);
    ul.x = pk2(ol[0], ol[1]); ul.y = pk2(ol[2], ol[3]);
    ul.z = pk2(ol[4], ol[5]); ul.w = pk2(ol[6], ol[7]);
    *(uint4*)(g_lnh + (size_t)row * DD + lane * 8) = uh;
    *(uint4*)(g_lnl + (size_t)row * DD + lane * 8) = ul;
}

// ---------------- gemm1: 512 blocks, transposed output [h][bt] ----------------
__global__ __launch_bounds__(256, 2) void kernel_g1(
    const bf16* __restrict__ iwh, const bf16* __restrict__ iwl)
{
    extern __shared__ __align__(16) char s_dyn[];
    const int t = blockIdx.x;
    gemm_tile_pipe(s_dyn, g_lnh, g_lnl, iwh, iwl, g_v, HH, DD, DD, 0,
                   3, (t >> 3) * 128, (t & 7) * 64);
}

// ---------------- gemm2: split-K x2, 512 blocks ----------------
__global__ __launch_bounds__(256, 2) void kernel_b(
    const bf16* __restrict__ owh, const bf16* __restrict__ owl)
{
    extern __shared__ __align__(16) char s_dyn[];
    const int t    = blockIdx.x;
    const int tile = t >> 1;
    const int half = t & 1;
    gemm_tile_pipe(s_dyn, g_yh, g_yl, owh, owl, g_h, DD, HH, HH / 2, half * (HH / 2),
                   2, (tile >> 2) * 128, (tile & 3) * 64);
}

// ---------------- kernel MID: conv + dt + scan (64-reg class, 4 blk/SM) ----------------
#define MID_SMEM 32768
__global__ __launch_bounds__(256, 4) void kernel_mid(
    const float* __restrict__ cw,
    const float* __restrict__ Dpw,
    const float2* __restrict__ tab,
    const float* __restrict__ w1,  const float* __restrict__ b1,
    const float* __restrict__ w2,  const float* __restrict__ b2)
{
    __shared__ __align__(16) char s_raw[MID_SMEM];
    const int bid = blockIdx.x;
    const int nbk = gridDim.x;
    const int tid = threadIdx.x;
    const int lane = tid & 31;
    const int warp = tid >> 5;

    // ---- conv(k=3)+silu streaming: g_v[h][bt] -> g_vcT[h][bt] ----
    {
        for (int i4 = bid * 256 + tid; i4 < BTH / 4; i4 += nbk * 256) {
            int idx = i4 * 4;
            int t = idx & (TT - 1);
            int h = idx >> 13;
            float4 v = *(const float4*)(g_v + idx);
            float lm = (t > 0) ? g_v[idx - 1] : 0.f;
            float rp = (t < TT - 4) ? g_v[idx + 4] : 0.f;
            float w0 = cw[h * 3 + 0], w1v = cw[h * 3 + 1], w2v = cw[h * 3 + 2];
            float4 r;
            r.x = silu_f(fmaf(w0, lm,  fmaf(w1v, v.x, w2v * v.y)));
            r.y = silu_f(fmaf(w0, v.x, fmaf(w1v, v.y, w2v * v.z)));
            r.z = silu_f(fmaf(w0, v.y, fmaf(w1v, v.z, w2v * v.w)));
            r.w = silu_f(fmaf(w0, v.z, fmaf(w1v, v.w, w2v * rp)));
            *(float4*)(g_vcT + idx) = r;
        }
    }
    grid_barrier();

    // ---- dt1 + dt2 fused -> g_dtT[h][bt] (512 tasks of 16 bt) ----
    {
        float (*red)[16][9] = (float(*)[16][9])(s_raw);
        float (*dtrs)[9]    = (float(*)[9])(s_raw + 8640);
        const int btl = tid & 15;
        const int q   = tid >> 4;
        for (int task = bid; task < BT / 16; task += nbk) {
            const int bt0 = task * 16;
            float acc[RR];
            #pragma unroll
            for (int r = 0; r < RR; r++) acc[r] = 0.f;
            const int hbase = q * 32;
            #pragma unroll 4
            for (int hh = 0; hh < 32; hh++) {
                int h = hbase + hh;
                float v = g_vcT[(size_t)h * BT + bt0 + btl];
                #pragma unroll
                for (int r = 0; r < RR; r++) acc[r] = fmaf(v, w1[r * HH + h], acc[r]);
            }
            if (q > 0) {
                #pragma unroll
                for (int r = 0; r < RR; r++) red[q - 1][btl][r] = acc[r];
            }
            __syncthreads();
            if (q == 0) {
                #pragma unroll
                for (int r = 0; r < RR; r++) {
                    float s = acc[r] + b1[r];
                    #pragma unroll
                    for (int g = 0; g < 15; g++) s += red[g][btl][r];
                    dtrs[btl][r] = fmaxf(s, 0.f);
                }
            }
            __syncthreads();
            #pragma unroll 4
            for (int hh = q; hh < HH; hh += 16) {
                float wreg[RR];
                #pragma unroll
                for (int r = 0; r < RR; r++) wreg[r] = w2[hh * RR + r];
                float a2 = b2[hh];
                #pragma unroll
                for (int r = 0; r < RR; r++) a2 = fmaf(dtrs[btl][r], wreg[r], a2);
                float sp = (a2 > 15.f) ? a2 : log1pf(__expf(a2));
                g_dtT[(size_t)hh * BT + bt0 + btl] = sp;
            }
            __syncthreads();
        }
    }
    grid_barrier();

    // ---- scan pass 1: chunk summaries (P, z_end) in z-space, CK=64 ----
    {
        float2* scr = (float2*)g_v;
        const int u = lane >> 1;
        const int p = lane & 1;
        for (int wt = bid * 8 + warp; wt < BB * 32 * NCK; wt += nbk * 8) {
            const int b  = wt / (32 * NCK);
            const int hb = (wt / NCK) & 31;
            const int ck = wt & (NCK - 1);
            const int h  = hb * 16 + u;
            const int ch = b * HH + h;
            float A2[8];
            const float2* tp = tab + h * NN + p * 8;
            #pragma unroll
            for (int j = 0; j < 8; j += 2) {
                float4 tv = *(const float4*)(tp + j);
                A2[j] = tv.x; A2[j + 1] = tv.z;
            }
            const float* xr = g_vcT + (size_t)h * BT + b * TT + ck * CK;
            const float* dr = g_dtT + (size_t)h * BT + b * TT + ck * CK;
            float z[8];
            #pragma unroll
            for (int j = 0; j < 8; j++) z[j] = 0.f;
            float sdt = 0.f;
            float4 xv = *(const float4*)xr;
            float4 dv = *(const float4*)dr;
            #pragma unroll 4
            for (int t4 = 0; t4 < CK; t4 += 4) {
                float4 xn, dn;
                if (t4 < CK - 4) {
                    xn = *(const float4*)(xr + t4 + 4);
                    dn = *(const float4*)(dr + t4 + 4);
                }
                #pragma unroll
                for (int k = 0; k < 4; k++) {
                    float x   = ((const float*)&xv)[k];
                    float dtv = ((const float*)&dv)[k];
                    float c = dtv * x;
                    sdt += dtv;
                    #pragma unroll
                    for (int j = 0; j < 8; j++) {
                        float dA = ex2f(A2[j] * dtv);
                        z[j] = fmaf(dA, z[j] + c, -c);
                    }
                }
                xv = xn; dv = dn;
            }
            float2* out = scr + ((size_t)ch * NCK + ck) * 16 + p * 8;
            #pragma unroll
            for (int j = 0; j < 8; j++)
                out[j] = make_float2(ex2f(A2[j] * sdt), z[j]);
        }
    }
    grid_barrier();

    // ---- scan pass 2: serial carry per (ch, n), NCK steps ----
    {
        float2* scr = (float2*)g_v;
        for (int i = bid * 256 + tid; i < CH * NN; i += nbk * 256) {
            float2* base = scr + ((size_t)(i >> 4) * NCK) * 16 + (i & 15);
            float c = 0.f;
            #pragma unroll
            for (int j = 0; j < NCK; j++) {
                float2 s = base[(size_t)j * 16];
                base[(size_t)j * 16].x = c;
                c = fmaf(s.x, c, s.y);
            }
        }
    }
    grid_barrier();

    // ---- scan pass 3: re-scan with carry init (z-space), emit y (CK=64) ----
    {
        float2* scr = (float2*)g_v;
        bf16 (*s_yh)[16] = (bf16(*)[16])(s_raw + warp * 4096);
        bf16 (*s_yl)[16] = (bf16(*)[16])(s_raw + warp * 4096 + 2048);
        const int u = lane >> 1;
        const int p = lane & 1;
        for (int wt = bid * 8 + warp; wt < BB * 32 * NCK; wt += nbk * 8) {
            const int b  = wt / (32 * NCK);
            const int hb = (wt / NCK) & 31;
            const int ck = wt & (NCK - 1);
            const int h  = hb * 16 + u;
            const int ch = b * HH + h;
            float A2[8], qv[8];
            const float2* tp = tab + h * NN + p * 8;
            #pragma unroll
            for (int j = 0; j < 8; j += 2) {
                float4 tv = *(const float4*)(tp + j);
                A2[j] = tv.x; qv[j] = tv.y;
                A2[j + 1] = tv.z; qv[j + 1] = tv.w;
            }
            float Dp = Dpw[h];
            const float* xr = g_vcT + (size_t)h * BT + b * TT + ck * CK;
            const float* dr = g_dtT + (size_t)h * BT + b * TT + ck * CK;
            const float2* cin = scr + ((size_t)ch * NCK + ck) * 16 + p * 8;
            float z[8];
            #pragma unroll
            for (int j = 0; j < 8; j++) z[j] = cin[j].x;
            float4 xv = *(const float4*)xr;
            float4 dv = *(const float4*)dr;
            #pragma unroll 4
            for (int t4 = 0; t4 < CK; t4 += 4) {
                float4 xn, dn;
                if (t4 < CK - 4) {
                    xn = *(const float4*)(xr + t4 + 4);
                    dn = *(const float4*)(dr + t4 + 4);
                }
                #pragma unroll
                for (int k = 0; k < 4; k++) {
                    float x   = ((const float*)&xv)[k];
                    float dtv = ((const float*)&dv)[k];
                    float c = dtv * x;
                    float part = 0.f;
                    #pragma unroll
                    for (int j = 0; j < 8; j++) {
                        float dA = ex2f(A2[j] * dtv);
                        z[j] = fmaf(dA, z[j] + c, -c);
                        part = fmaf(qv[j], z[j], part);
                    }
                    part += __shfl_xor_sync(0xffffffffu, part, 1);
                    if (p == 0) {
                        float y = fmaf(Dp, x, part);
                        bf16 hh_, ll_;
                        split_bf16(y, hh_, ll_);
                        s_yh[t4 + k][u] = hh_;
                        s_yl[t4 + k][u] = ll_;
                    }
                }
                xv = xn; dv = dn;
            }
            __syncwarp();
            {
                size_t rb0 = (size_t)(b * TT + ck * CK + lane) * HH + hb * 16;
                size_t rb1 = (size_t)(b * TT + ck * CK + lane + 32) * HH + hb * 16;
                uint4* sh0 = (uint4*)&s_yh[lane][0];
                uint4* sl0 = (uint4*)&s_yl[lane][0];
                uint4* sh1 = (uint4*)&s_yh[lane + 32][0];
                uint4* sl1 = (uint4*)&s_yl[lane + 32][0];
                *(uint4*)(g_yh + rb0)     = sh0[0];
                *(uint4*)(g_yh + rb0 + 8) = sh0[1];
                *(uint4*)(g_yl + rb0)     = sl0[0];
                *(uint4*)(g_yl + rb0 + 8) = sl0[1];
                *(uint4*)(g_yh + rb1)     = sh1[0];
                *(uint4*)(g_yh + rb1 + 8) = sh1[1];
                *(uint4*)(g_yl + rb1)     = sl1[0];
                *(uint4*)(g_yl + rb1 + 8) = sl1[1];
            }
            __syncwarp();
        }
    }
}

// ---------------- final LN (last token) + head1(silu) + head2 ----------------
__global__ void final_kernel(const float* __restrict__ fg,
                             const float* __restrict__ fb,
                             const float* __restrict__ w1,
                             const float* __restrict__ b1,
                             const float* __restrict__ w2,
                             const float* __restrict__ b2,
                             float* __restrict__ out) {
    int b = blockIdx.x;
    int tid = threadIdx.x;
    __shared__ float red1[8], red2[8];
    __shared__ float s_ln[DD];
    __shared__ float s_h1[DD];
    const float* row = g_h + (size_t)(b * TT + (TT - 1)) * DD;
    float v = row[tid];
    float s = v;
    #pragma unroll
    for (int o = 16; o; o >>= 1) s += __shfl_xor_sync(0xffffffffu, s, o);
    if ((tid & 31) == 0) red1[tid >> 5] = s;
    __syncthreads();
    float mean = 0.f;
    #pragma unroll
    for (int i = 0; i < 8; i++) mean += red1[i];
    mean *= (1.f / 256.f);
    float c = v - mean;
    float cc = c * c;
    #pragma unroll
    for (int o = 16; o; o >>= 1) cc += __shfl_xor_sync(0xffffffffu, cc, o);
    if ((tid & 31) == 0) red2[tid >> 5] = cc;
    __syncthreads();
    float var = 0.f;
    #pragma unroll
    for (int i = 0; i < 8; i++) var += red2[i];
    var *= (1.f / 256.f);
    s_ln[tid] = c * rsqrtf(var + 1e-5f) * fg[tid] + fb[tid];
    __syncthreads();
    float acc = b1[tid];
    const float* w1r = w1 + tid * DD;
    #pragma unroll 8
    for (int k = 0; k < DD; k++) acc = fmaf(s_ln[k], w1r[k], acc);
    s_h1[tid] = silu_f(acc);
    __syncthreads();
    if (tid < 96) {
        float a2 = b2[tid];
        const float* w2r = w2 + tid * DD;
        #pragma unroll 8
        for (int k = 0; k < DD; k++) a2 = fmaf(s_h1[k], w2r[k], a2);
        out[b * 96 + tid] = a2;
    }
}

// ---------------- launcher: 18 graph nodes ----------------
extern "C" void kernel_launch(void* const* d_in, const int* in_sizes, int n_in,
                              void* d_out, int out_size) {
    const float* x      = (const float*)d_in[0];
    const float* emb_w  = (const float*)d_in[1];
    const float* emb_b  = (const float*)d_in[2];
    const float* norm_g = (const float*)d_in[3];
    const float* norm_b = (const float*)d_in[4];
    const float* in_w   = (const float*)d_in[5];
    const float* conv_w = (const float*)d_in[6];
    const float* A_p    = (const float*)d_in[7];
    const float* D_p    = (const float*)d_in[8];
    const float* dt1_w  = (const float*)d_in[9];
    const float* dt1_b  = (const float*)d_in[10];
    const float* dt2_w  = (const float*)d_in[11];
    const float* dt2_b  = (const float*)d_in[12];
    const float* out_w  = (const float*)d_in[13];
    const float* fin_g  = (const float*)d_in[14];
    const float* fin_b  = (const float*)d_in[15];
    const float* h1_w   = (const float*)d_in[16];
    const float* h1_b   = (const float*)d_in[17];
    const float* h2_w   = (const float*)d_in[18];
    const float* h2_b   = (const float*)d_in[19];
    float* out = (float*)d_out;

    bf16 *piwh, *piwl, *powh, *powl;
    float2* ptab;
    cudaGetSymbolAddress((void**)&piwh, g_iwh);
    cudaGetSymbolAddress((void**)&piwl, g_iwl);
    cudaGetSymbolAddress((void**)&powh, g_owh);
    cudaGetSymbolAddress((void**)&powl, g_owl);
    cudaGetSymbolAddress((void**)&ptab, g_tab);

    cudaFuncSetAttribute(kernel_g1, cudaFuncAttributeMaxDynamicSharedMemorySize,
                         GEMM_SMEM_DYN);
    cudaFuncSetAttribute(kernel_b, cudaFuncAttributeMaxDynamicSharedMemorySize,
                         GEMM_SMEM_DYN);

    emb_split_kernel<<<BT + (2 * NW + NTAB) / 256, 256>>>(
        x, emb_w, emb_b, in_w, out_w, A_p);

    for (int l = 0; l < LL; l++) {
        ln_kernel<<<BT / 8, 256>>>(norm_g + l * DD, norm_b + l * DD);

        kernel_g1<<<512, 256, GEMM_SMEM_DYN>>>(
            piwh + (size_t)l * HH * DD, piwl + (size_t)l * HH * DD);

        kernel_mid<<<GRID_MID, 256>>>(
            conv_w + (size_t)l * HH * 3,
            D_p + l * HH,
            ptab + (size_t)l * HH * NN,
            dt1_w + (size_t)l * RR * HH, dt1_b + l * RR,
            dt2_w + (size_t)l * HH * RR, dt2_b + l * HH);

        kernel_b<<<512, 256, GEMM_SMEM_DYN>>>(
            powh + (size_t)l * DD * HH, powl + (size_t)l * DD * HH);
    }

    final_kernel<<<BB, 256>>>(fin_g, fin_b, h1_w, h1_b, h2_w, h2_b, out);
}